// round 7
// baseline (speedup 1.0000x reference)
#include <cuda_runtime.h>
#include <cuda_bf16.h>
#include <math.h>
#include <stdint.h>

#define BATCH 2
#define SEQ   2048
#define HID   1024
#define NH    16
#define HD    64
#define MTOT  (BATCH*SEQ)
#define OUT_ELEMS   (MTOT*HID)
#define W_ELEMS     (BATCH*NH*SEQ*SEQ)
#define LOG2E 1.44269504088896340736f

/* ---- fp8 split scales (per tensor class, all powers of 2) ----
   inputs  (sigma ~1):    fp8 hi x4,   fp8 lo x2048,  bf16 hi x128
   weights (sigma ~2^-5): fp8 hi x128, fp8 lo x65536, bf16 hi x2048
   Q out:                 fp8 hi x4,   lo x2048,      bf16 x128
   K out:                 fp8 hi x4,   lo x2048,      bf16 x64
   O out  (sigma <=1):    fp8 hi x8,   lo x4096,      bf16 x256
   GEMM proj  S = 2^2*2^7*2^9 = 2^18 ; outproj S = 2^3*2^7*2^9 = 2^19
   attention QK S = 2^2*2^2*2^9 = 2^13                                */
#define INV_S_PROJ 3.814697265625e-06f   /* 2^-18 */
#define INV_S_OPRJ 1.9073486328125e-06f  /* 2^-19 */

/* ---------------- scratch (no allocations allowed) ---------------- */
__device__ float g_cos[SEQ*(HD/2)];
__device__ float g_sin[SEQ*(HD/2)];

/* attention operands (B,H,S,*) */
__device__ __nv_bfloat16 g_Qh[BATCH*NH*SEQ*HD];    /* qh * 128 */
__device__ uint8_t       g_Q8[BATCH*NH*SEQ*HD*2];  /* [qh*4 | ql*2048] */
__device__ __nv_bfloat16 g_Kh[BATCH*NH*SEQ*HD];    /* kh * 64 */
__device__ uint8_t       g_K8[BATCH*NH*SEQ*HD*2];  /* [kl*2048 | kh*4] */
__device__ __nv_bfloat16 g_Vh[BATCH*NH*SEQ*HD];
__device__ __nv_bfloat16 g_Vl[BATCH*NH*SEQ*HD];

/* GEMM operands: bf16 hi [rows x 1024] + fp8 [rows x 2048] */
__device__ __nv_bfloat16 a_qh[MTOT*1024];
__device__ uint8_t       a_q8[MTOT*2048];
__device__ __nv_bfloat16 a_kh[MTOT*1024];
__device__ uint8_t       a_k8[MTOT*2048];
__device__ __nv_bfloat16 a_vh[MTOT*1024];
__device__ uint8_t       a_v8[MTOT*2048];
__device__ __nv_bfloat16 a_oh[MTOT*1024];
__device__ uint8_t       a_o8[MTOT*2048];
__device__ __nv_bfloat16 w_qh[HID*1024];
__device__ uint8_t       w_q8[HID*2048];
__device__ __nv_bfloat16 w_kh[HID*1024];
__device__ uint8_t       w_k8[HID*2048];
__device__ __nv_bfloat16 w_vh[HID*1024];
__device__ uint8_t       w_v8[HID*2048];
__device__ __nv_bfloat16 w_oh[HID*1024];
__device__ uint8_t       w_o8[HID*2048];

/* ---------------- helpers ---------------- */
__device__ __forceinline__ uint32_t smem_u32(const void* p) {
    uint32_t a;
    asm("{ .reg .u64 t; cvta.to.shared.u64 t, %1; cvt.u32.u64 %0, t; }"
        : "=r"(a) : "l"(p));
    return a;
}
__device__ __forceinline__ void cp16(uint32_t s, const void* g) {
    asm volatile("cp.async.cg.shared.global [%0], [%1], 16;"
                 :: "r"(s), "l"(g));
}
#define CP_COMMIT() asm volatile("cp.async.commit_group;" ::: "memory")
#define CP_WAIT(N)  asm volatile("cp.async.wait_group %0;" :: "n"(N) : "memory")

__device__ __forceinline__ void ldsm4(uint32_t& r0, uint32_t& r1,
                                      uint32_t& r2, uint32_t& r3, uint32_t addr)
{
    asm volatile("ldmatrix.sync.aligned.m8n8.x4.shared.b16 {%0,%1,%2,%3}, [%4];"
                 : "=r"(r0), "=r"(r1), "=r"(r2), "=r"(r3) : "r"(addr));
}
__device__ __forceinline__ void ldsm4t(uint32_t& r0, uint32_t& r1,
                                       uint32_t& r2, uint32_t& r3, uint32_t addr)
{
    asm volatile("ldmatrix.sync.aligned.m8n8.x4.trans.shared.b16 {%0,%1,%2,%3}, [%4];"
                 : "=r"(r0), "=r"(r1), "=r"(r2), "=r"(r3) : "r"(addr));
}
__device__ __forceinline__ void mma_bf16(float* d, const uint32_t* a,
                                         uint32_t b0, uint32_t b1)
{
    asm volatile(
        "mma.sync.aligned.m16n8k16.row.col.f32.bf16.bf16.f32 "
        "{%0,%1,%2,%3}, {%4,%5,%6,%7}, {%8,%9}, {%0,%1,%2,%3};"
        : "+f"(d[0]), "+f"(d[1]), "+f"(d[2]), "+f"(d[3])
        : "r"(a[0]), "r"(a[1]), "r"(a[2]), "r"(a[3]), "r"(b0), "r"(b1));
}
__device__ __forceinline__ void mma_fp8(float* d, const uint32_t* a,
                                        uint32_t b0, uint32_t b1)
{
    asm volatile(
        "mma.sync.aligned.m16n8k32.row.col.f32.e4m3.e4m3.f32 "
        "{%0,%1,%2,%3}, {%4,%5,%6,%7}, {%8,%9}, {%0,%1,%2,%3};"
        : "+f"(d[0]), "+f"(d[1]), "+f"(d[2]), "+f"(d[3])
        : "r"(a[0]), "r"(a[1]), "r"(a[2]), "r"(a[3]), "r"(b0), "r"(b1));
}
__device__ __forceinline__ float ex2(float x) {
    float y;
    asm("ex2.approx.ftz.f32 %0, %1;" : "=f"(y) : "f"(x));
    return y;
}
__device__ __forceinline__ uint32_t pack_bf2(float x, float y) {
    __nv_bfloat162 t = __floats2bfloat162_rn(x, y);
    return *(uint32_t*)&t;
}
/* pack two f32 -> e4m3x2 (lo = first arg) */
__device__ __forceinline__ uint16_t cvt_e4m3x2(float lo, float hi) {
    uint16_t r;
    asm("cvt.rn.satfinite.e4m3x2.f32 %0, %1, %2;" : "=h"(r) : "f"(hi), "f"(lo));
    return r;
}

/* ---------------- RoPE tables ---------------- */
__global__ void rope_table_kernel() {
    int idx = blockIdx.x * blockDim.x + threadIdx.x;
    if (idx >= SEQ * (HD/2)) return;
    int s = idx >> 5;
    int j = idx & 31;
    double inv = exp(-((double)(2*j) / (double)HD) * log(10000.0));
    double ang = (double)s * inv;
    g_cos[idx] = (float)cos(ang);
    g_sin[idx] = (float)sin(ang);
}

/* -------- fp32 -> scaled bf16-hi + fp8 split kernels -------------- */
/* A-side (inputs, sigma~1): bf16 = hi*128, fp8 row [hi*4 | lo*2048]  */
__global__ void __launch_bounds__(256)
split_a_kernel(const float* __restrict__ src,
               __nv_bfloat16* __restrict__ dsth,
               uint8_t* __restrict__ dst8, int n2)
{
    int idx = blockIdx.x * blockDim.x + threadIdx.x;
    if (idx >= n2) return;
    int row = idx >> 9, kp = (idx & 511) * 2;
    float2 x = ((const float2*)src)[idx];
    __nv_bfloat16 h0 = __float2bfloat16(x.x);
    __nv_bfloat16 h1 = __float2bfloat16(x.y);
    float h0f = __bfloat162float(h0), h1f = __bfloat162float(h1);
    ((__nv_bfloat162*)dsth)[idx] = __floats2bfloat162_rn(h0f*128.f, h1f*128.f);
    float l0 = x.x - h0f, l1 = x.y - h1f;
    size_t b8 = (size_t)row * 2048 + kp;
    *(uint16_t*)(dst8 + b8)        = cvt_e4m3x2(h0f*4.f,   h1f*4.f);
    *(uint16_t*)(dst8 + b8 + 1024) = cvt_e4m3x2(l0*2048.f, l1*2048.f);
}
/* B-side (weights, sigma~2^-5): bf16 = hi*2048, fp8 [lo*65536 | hi*128] */
__global__ void __launch_bounds__(256)
split_b_kernel(const float* __restrict__ src,
               __nv_bfloat16* __restrict__ dsth,
               uint8_t* __restrict__ dst8, int n2)
{
    int idx = blockIdx.x * blockDim.x + threadIdx.x;
    if (idx >= n2) return;
    int row = idx >> 9, kp = (idx & 511) * 2;
    float2 x = ((const float2*)src)[idx];
    __nv_bfloat16 h0 = __float2bfloat16(x.x);
    __nv_bfloat16 h1 = __float2bfloat16(x.y);
    float h0f = __bfloat162float(h0), h1f = __bfloat162float(h1);
    ((__nv_bfloat162*)dsth)[idx] = __floats2bfloat162_rn(h0f*2048.f, h1f*2048.f);
    float l0 = x.x - h0f, l1 = x.y - h1f;
    size_t b8 = (size_t)row * 2048 + kp;
    *(uint16_t*)(dst8 + b8)        = cvt_e4m3x2(l0*65536.f, l1*65536.f);
    *(uint16_t*)(dst8 + b8 + 1024) = cvt_e4m3x2(h0f*128.f,  h1f*128.f);
}

/* ================= GEMM: bf16 main + fp8 corrections =================
   acc accumulates at scale S; epilogue: c = acc*invS + bias.
   mode 0: RoPE, Q-style out;  mode 3: RoPE, K-style out;
   mode 1: V out (bf16 hi+lo); mode 2: fp32 row-major out.            */
#define GSTG 40960

__global__ void __launch_bounds__(256, 2)
gemm_mma(const __nv_bfloat16* __restrict__ Ah, const uint8_t* __restrict__ A8,
         const __nv_bfloat16* __restrict__ Bh, const uint8_t* __restrict__ B8,
         const float* __restrict__ bias, float invS,
         float* __restrict__ dst,
         __nv_bfloat16* __restrict__ dhi,
         __nv_bfloat16* __restrict__ dlo,
         uint8_t* __restrict__ d8, int mode)
{
    extern __shared__ __align__(16) char gsm[];

    const int tid = threadIdx.x;
    const int wid = tid >> 5, l = tid & 31;
    const int warp_m = wid >> 1, warp_n = wid & 1;
    const int m0 = blockIdx.y * 128;
    const int n0 = blockIdx.x * 128;
    const uint32_t sb = smem_u32(gsm);

    const uint4* gAh = (const uint4*)(Ah + (size_t)m0 * 1024);
    const uint4* gA8 = (const uint4*)(A8 + (size_t)m0 * 2048);
    const uint4* gBh = (const uint4*)(Bh + (size_t)n0 * 1024);
    const uint4* gB8 = (const uint4*)(B8 + (size_t)n0 * 2048);

    float acc[2][8][4];
#pragma unroll
    for (int i = 0; i < 2; i++)
#pragma unroll
        for (int j = 0; j < 8; j++)
#pragma unroll
            for (int p = 0; p < 4; p++) acc[i][j][p] = 0.f;

    uint32_t a_off[2], b_off[4];
#pragma unroll
    for (int mt = 0; mt < 2; mt++)
        a_off[mt] = (warp_m*32 + mt*16 + (l & 15))*80 + (l >> 4)*16;
#pragma unroll
    for (int nt = 0; nt < 4; nt++) {
        int row = warp_n*64 + nt*16 + (l & 7) + ((l >> 4) & 1) * 8;
        b_off[nt] = 20480 + row*80 + ((l >> 3) & 1)*16;
    }

    auto load_stage = [&](int stg, int it) {
        uint32_t base = sb + stg*GSTG;
#pragma unroll
        for (int u = 0; u < 2; u++) {
            int f = u*256 + tid;
            int r = f >> 2, c = f & 3;
            cp16(base +         r*80 + c*16, gAh + (size_t)r*128 + it*4 + c);
            cp16(base + 10240 + r*80 + c*16, gA8 + (size_t)r*128 + (c>>1)*64 + it*2 + (c&1));
            cp16(base + 20480 + r*80 + c*16, gBh + (size_t)r*128 + it*4 + c);
            cp16(base + 30720 + r*80 + c*16, gB8 + (size_t)r*128 + (c>>1)*64 + it*2 + (c&1));
        }
    };

    load_stage(0, 0);
    CP_COMMIT();

    for (int it = 0; it < 32; it++) {
        int cur = it & 1;
        if (it + 1 < 32) {
            load_stage(cur ^ 1, it + 1);
            CP_COMMIT();
            CP_WAIT(1);
        } else {
            CP_WAIT(0);
        }
        __syncthreads();

        uint32_t stgb = sb + cur*GSTG;
#pragma unroll
        for (int ks = 0; ks < 2; ks++) {
            uint32_t a[2][4], b[4][4];
#pragma unroll
            for (int mt = 0; mt < 2; mt++)
                ldsm4(a[mt][0], a[mt][1], a[mt][2], a[mt][3],
                      stgb + a_off[mt] + ks*32);
#pragma unroll
            for (int nt = 0; nt < 4; nt++)
                ldsm4(b[nt][0], b[nt][1], b[nt][2], b[nt][3],
                      stgb + b_off[nt] + ks*32);
#pragma unroll
            for (int mt = 0; mt < 2; mt++)
#pragma unroll
                for (int nt = 0; nt < 4; nt++) {
                    mma_bf16(acc[mt][nt*2],   a[mt], b[nt][0], b[nt][1]);
                    mma_bf16(acc[mt][nt*2+1], a[mt], b[nt][2], b[nt][3]);
                }
        }
#pragma unroll
        for (int c8 = 0; c8 < 2; c8++) {
            uint32_t a[2][4], b[4][4];
#pragma unroll
            for (int mt = 0; mt < 2; mt++)
                ldsm4(a[mt][0], a[mt][1], a[mt][2], a[mt][3],
                      stgb + 10240 + a_off[mt] + c8*32);
#pragma unroll
            for (int nt = 0; nt < 4; nt++)
                ldsm4(b[nt][0], b[nt][1], b[nt][2], b[nt][3],
                      stgb + 10240 + b_off[nt] + c8*32);
#pragma unroll
            for (int mt = 0; mt < 2; mt++)
#pragma unroll
                for (int nt = 0; nt < 4; nt++) {
                    mma_fp8(acc[mt][nt*2],   a[mt], b[nt][0], b[nt][1]);
                    mma_fp8(acc[mt][nt*2+1], a[mt], b[nt][2], b[nt][3]);
                }
        }
        __syncthreads();
    }

    /* ---------------- epilogue ---------------- */
    const int g = l >> 2, q = l & 3;
#pragma unroll
    for (int mt = 0; mt < 2; mt++) {
        int mrow0 = m0 + warp_m*32 + mt*16 + g;
#pragma unroll
        for (int nt2 = 0; nt2 < 8; nt2++) {
            int ncol = n0 + warp_n*64 + nt2*8 + q*2;
            float b0 = bias[ncol], b1 = bias[ncol+1];
            float c0 = fmaf(acc[mt][nt2][0], invS, b0);
            float c1 = fmaf(acc[mt][nt2][1], invS, b1);
            float c2 = fmaf(acc[mt][nt2][2], invS, b0);
            float c3 = fmaf(acc[mt][nt2][3], invS, b1);

            if (mode == 2) {
                *(float2*)(dst + (size_t)mrow0    *HID + ncol) = make_float2(c0, c1);
                *(float2*)(dst + (size_t)(mrow0+8)*HID + ncol) = make_float2(c2, c3);
            } else {
                int h = ncol >> 6, d = ncol & 63;
                int bb0 = mrow0 >> 11, ss0 = mrow0 & 2047;
                int mrow1 = mrow0 + 8;
                int bb1 = mrow1 >> 11, ss1 = mrow1 & 2047;
                if (mode != 1) {   /* RoPE for Q and K */
                    float cs0 = g_cos[ss0*32 + (d>>1)], sn0 = g_sin[ss0*32 + (d>>1)];
                    float cs1 = g_cos[ss1*32 + (d>>1)], sn1 = g_sin[ss1*32 + (d>>1)];
                    float t0 = c0*cs0 - c1*sn0, t1 = c0*sn0 + c1*cs0;
                    float t2 = c2*cs1 - c3*sn1, t3 = c2*sn1 + c3*cs1;
                    c0 = t0; c1 = t1; c2 = t2; c3 = t3;
                }
                size_t r0i = ((size_t)(bb0*NH + h)*SEQ + ss0);
                size_t r1i = ((size_t)(bb1*NH + h)*SEQ + ss1);
                __nv_bfloat16 h0 = __float2bfloat16(c0);
                __nv_bfloat16 h1 = __float2bfloat16(c1);
                __nv_bfloat16 h2 = __float2bfloat16(c2);
                __nv_bfloat16 h3 = __float2bfloat16(c3);
                float h0f = __bfloat162float(h0), h1f = __bfloat162float(h1);
                float h2f = __bfloat162float(h2), h3f = __bfloat162float(h3);
                float l0 = c0 - h0f, l1 = c1 - h1f;
                float l2 = c2 - h2f, l3 = c3 - h3f;
                if (mode == 1) {   /* V: unscaled bf16 hi + lo */
                    *(__nv_bfloat162*)(dhi + (r0i<<6) + d) = __halves2bfloat162(h0, h1);
                    *(__nv_bfloat162*)(dhi + (r1i<<6) + d) = __halves2bfloat162(h2, h3);
                    *(__nv_bfloat162*)(dlo + (r0i<<6) + d) =
                        __floats2bfloat162_rn(l0, l1);
                    *(__nv_bfloat162*)(dlo + (r1i<<6) + d) =
                        __floats2bfloat162_rn(l2, l3);
                } else if (mode == 0) {  /* Q: bf16 x128, fp8 [h*4 | l*2048] */
                    *(__nv_bfloat162*)(dhi + (r0i<<6) + d) =
                        __floats2bfloat162_rn(h0f*128.f, h1f*128.f);
                    *(__nv_bfloat162*)(dhi + (r1i<<6) + d) =
                        __floats2bfloat162_rn(h2f*128.f, h3f*128.f);
                    *(uint16_t*)(d8 + (r0i<<7) + d)      = cvt_e4m3x2(h0f*4.f, h1f*4.f);
                    *(uint16_t*)(d8 + (r0i<<7) + 64 + d) = cvt_e4m3x2(l0*2048.f, l1*2048.f);
                    *(uint16_t*)(d8 + (r1i<<7) + d)      = cvt_e4m3x2(h2f*4.f, h3f*4.f);
                    *(uint16_t*)(d8 + (r1i<<7) + 64 + d) = cvt_e4m3x2(l2*2048.f, l3*2048.f);
                } else {                 /* K: bf16 x64, fp8 [l*2048 | h*4] */
                    *(__nv_bfloat162*)(dhi + (r0i<<6) + d) =
                        __floats2bfloat162_rn(h0f*64.f, h1f*64.f);
                    *(__nv_bfloat162*)(dhi + (r1i<<6) + d) =
                        __floats2bfloat162_rn(h2f*64.f, h3f*64.f);
                    *(uint16_t*)(d8 + (r0i<<7) + d)      = cvt_e4m3x2(l0*2048.f, l1*2048.f);
                    *(uint16_t*)(d8 + (r0i<<7) + 64 + d) = cvt_e4m3x2(h0f*4.f, h1f*4.f);
                    *(uint16_t*)(d8 + (r1i<<7) + d)      = cvt_e4m3x2(l2*2048.f, l3*2048.f);
                    *(uint16_t*)(d8 + (r1i<<7) + 64 + d) = cvt_e4m3x2(h2f*4.f, h3f*4.f);
                }
            }
        }
    }
}

/* ================= attention =================
   QK at scale 2^13 (bf16 Qx128*Kx64 + fp8 cross); softmax constant
   folds invS. PV = 3x bf16 split (unscaled V).                       */
#define QSZ   36864
#define ASTG  36864
#define ASMEM (QSZ + 2*ASTG)

__global__ void __launch_bounds__(256, 2)
attn_mma(float* __restrict__ wout, int write_w)
{
    extern __shared__ __align__(16) char dsm[];
    const int tid = threadIdx.x;
    const int w = tid >> 5, l = tid & 31;
    const int g = l >> 2, q = l & 3;
    const int qt = (gridDim.x - 1) - blockIdx.x;
    const int h = blockIdx.y, b = blockIdx.z;
    const int q0 = qt * 128;
    const size_t basebh = (size_t)(b*NH + h) * SEQ;
    const uint32_t sb = smem_u32(dsm);

    /* Q loads */
    {
        const uint4* gh = (const uint4*)(g_Qh + (basebh + q0) * HD);
        const uint4* g8 = (const uint4*)(g_Q8 + (basebh + q0) * 128);
#pragma unroll
        for (int u = 0; u < 4; u++) {
            int f = u*256 + tid;
            int r = f >> 3, c = f & 7;
            cp16(sb + r*144 + c*16,         gh + r*8 + c);
            cp16(sb + 18432 + r*144 + c*16, g8 + r*8 + c);
        }
        CP_COMMIT();
    }

    const uint32_t aQh = sb + (w*16 + (l & 15))*144 + (l >> 4)*16;
    const uint32_t aQ8 = aQh + 18432;
    uint32_t bk_off[4];
    {
        int krow = (l & 7) + ((l >> 4) & 1) * 8;
        int kcb  = ((l >> 3) & 1) * 16;
#pragma unroll
        for (int nt = 0; nt < 4; nt++)
            bk_off[nt] = (nt*16 + krow)*144 + kcb;
    }
    const uint32_t av_off = 18432 + (l & 15)*144 + (l >> 4)*16;

    /* softmax scale with QK descale folded: 0.125 * log2e * 2^-13 */
    const float CE2 = 0.125f * LOG2E / 8192.0f;
    const int nkt = 2*qt + 2;
    const int rw0 = q0 + w*16;
    const int r0 = rw0 + g, r1 = r0 + 8;

    auto loadK = [&](int stg, int kb) {
        uint32_t base = sb + QSZ + stg*ASTG;
        const uint4* gkh = (const uint4*)(g_Kh + (basebh + kb*64) * HD);
        const uint4* gk8 = (const uint4*)(g_K8 + (basebh + kb*64) * 128);
#pragma unroll
        for (int u = 0; u < 2; u++) {
            int f = u*256 + tid;
            int r = f >> 3, c = f & 7;
            cp16(base + r*144 + c*16,        gkh + r*8 + c);
            cp16(base + 9216 + r*144 + c*16, gk8 + r*8 + c);
        }
    };
    auto loadKV = [&](int stg, int kb) {
        uint32_t base = sb + QSZ + stg*ASTG;
        const uint4* gkh = (const uint4*)(g_Kh + (basebh + kb*64) * HD);
        const uint4* gk8 = (const uint4*)(g_K8 + (basebh + kb*64) * 128);
        const uint4* gvh = (const uint4*)(g_Vh + (basebh + kb*64) * HD);
        const uint4* gvl = (const uint4*)(g_Vl + (basebh + kb*64) * HD);
#pragma unroll
        for (int u = 0; u < 2; u++) {
            int f = u*256 + tid;
            int r = f >> 3, c = f & 7;
            cp16(base + r*144 + c*16,         gkh + r*8 + c);
            cp16(base + 9216  + r*144 + c*16, gk8 + r*8 + c);
            cp16(base + 18432 + r*144 + c*16, gvh + r*8 + c);
            cp16(base + 27648 + r*144 + c*16, gvl + r*8 + c);
        }
    };

    auto qk_tile = [&](uint32_t kbase, float acc[8][4]) {
#pragma unroll
        for (int nt = 0; nt < 8; nt++)
#pragma unroll
            for (int p = 0; p < 4; p++) acc[nt][p] = 0.f;
#pragma unroll
        for (int ks = 0; ks < 4; ks++) {
            uint32_t ah[4];
            ldsm4(ah[0], ah[1], ah[2], ah[3], aQh + ks*32);
#pragma unroll
            for (int np = 0; np < 4; np++) {
                uint32_t kh[4];
                ldsm4(kh[0], kh[1], kh[2], kh[3], kbase + bk_off[np] + ks*32);
                mma_bf16(acc[np*2],   ah, kh[0], kh[1]);
                mma_bf16(acc[np*2+1], ah, kh[2], kh[3]);
            }
        }
#pragma unroll
        for (int c8 = 0; c8 < 4; c8++) {
            uint32_t a8[4];
            ldsm4(a8[0], a8[1], a8[2], a8[3], aQ8 + c8*32);
#pragma unroll
            for (int np = 0; np < 4; np++) {
                uint32_t k8[4];
                ldsm4(k8[0], k8[1], k8[2], k8[3],
                      kbase + 9216 + bk_off[np] + c8*32);
                mma_fp8(acc[np*2],   a8, k8[0], k8[1]);
                mma_fp8(acc[np*2+1], a8, k8[2], k8[3]);
            }
        }
    };

    float m2[2] = {-1e30f, -1e30f};
    float l2[2] = {0.f, 0.f};

    /* ---------------- PASS 1 ---------------- */
    loadK(0, 0);
    CP_COMMIT();

    for (int kb = 0; kb < nkt; kb++) {
        int cur = kb & 1;
        if (kb + 1 < nkt) {
            loadK(cur ^ 1, kb + 1);
            CP_COMMIT();
            CP_WAIT(1);
        } else {
            CP_WAIT(0);
        }
        __syncthreads();

        float acc[8][4];
        qk_tile(sb + QSZ + cur*ASTG, acc);
        __syncthreads();

        const bool needmask = (kb*64 + 63) > rw0;
#pragma unroll
        for (int nt = 0; nt < 8; nt++) {
            int k0c = kb*64 + nt*8 + q*2;
            acc[nt][0] = (!needmask || k0c   <= r0) ? acc[nt][0]*CE2 : -1e30f;
            acc[nt][1] = (!needmask || k0c+1 <= r0) ? acc[nt][1]*CE2 : -1e30f;
            acc[nt][2] = (!needmask || k0c   <= r1) ? acc[nt][2]*CE2 : -1e30f;
            acc[nt][3] = (!needmask || k0c+1 <= r1) ? acc[nt][3]*CE2 : -1e30f;
        }
        float tm0 = -1e30f, tm1 = -1e30f;
#pragma unroll
        for (int nt = 0; nt < 8; nt++) {
            tm0 = fmaxf(tm0, fmaxf(acc[nt][0], acc[nt][1]));
            tm1 = fmaxf(tm1, fmaxf(acc[nt][2], acc[nt][3]));
        }
        tm0 = fmaxf(tm0, __shfl_xor_sync(0xffffffffu, tm0, 1));
        tm0 = fmaxf(tm0, __shfl_xor_sync(0xffffffffu, tm0, 2));
        tm1 = fmaxf(tm1, __shfl_xor_sync(0xffffffffu, tm1, 1));
        tm1 = fmaxf(tm1, __shfl_xor_sync(0xffffffffu, tm1, 2));
        float mn0 = fmaxf(m2[0], tm0), mn1 = fmaxf(m2[1], tm1);
        float s0 = 0.f, s1 = 0.f;
#pragma unroll
        for (int nt = 0; nt < 8; nt++) {
            s0 += ex2(acc[nt][0] - mn0) + ex2(acc[nt][1] - mn0);
            s1 += ex2(acc[nt][2] - mn1) + ex2(acc[nt][3] - mn1);
        }
        s0 += __shfl_xor_sync(0xffffffffu, s0, 1);
        s0 += __shfl_xor_sync(0xffffffffu, s0, 2);
        s1 += __shfl_xor_sync(0xffffffffu, s1, 1);
        s1 += __shfl_xor_sync(0xffffffffu, s1, 2);
        l2[0] = l2[0] * ex2(m2[0] - mn0) + s0;  m2[0] = mn0;
        l2[1] = l2[1] * ex2(m2[1] - mn1) + s1;  m2[1] = mn1;
    }

    const float invl0 = 1.f / l2[0];
    const float invl1 = 1.f / l2[1];

    float o[8][4];
#pragma unroll
    for (int nd = 0; nd < 8; nd++)
#pragma unroll
        for (int p = 0; p < 4; p++) o[nd][p] = 0.f;

    /* ---------------- PASS 2 ---------------- */
    loadKV(0, 0);
    CP_COMMIT();

    for (int kb = 0; kb < nkt; kb++) {
        int cur = kb & 1;
        if (kb + 1 < nkt) {
            loadKV(cur ^ 1, kb + 1);
            CP_COMMIT();
            CP_WAIT(1);
        } else {
            CP_WAIT(0);
        }
        __syncthreads();

        uint32_t kbase = sb + QSZ + cur*ASTG;
        float acc[8][4];
        qk_tile(kbase, acc);

        const bool needmask = (kb*64 + 63) > rw0;
#pragma unroll
        for (int nt = 0; nt < 8; nt++) {
            int k0c = kb*64 + nt*8 + q*2;
            float w0 = (!needmask || k0c   <= r0)
                       ? ex2(acc[nt][0]*CE2 - m2[0]) * invl0 : 0.f;
            float w1 = (!needmask || k0c+1 <= r0)
                       ? ex2(acc[nt][1]*CE2 - m2[0]) * invl0 : 0.f;
            float w2 = (!needmask || k0c   <= r1)
                       ? ex2(acc[nt][2]*CE2 - m2[1]) * invl1 : 0.f;
            float w3 = (!needmask || k0c+1 <= r1)
                       ? ex2(acc[nt][3]*CE2 - m2[1]) * invl1 : 0.f;
            acc[nt][0] = w0; acc[nt][1] = w1; acc[nt][2] = w2; acc[nt][3] = w3;
            if (write_w) {
                __stcs((float2*)(wout + (basebh + r0)*SEQ + k0c), make_float2(w0, w1));
                __stcs((float2*)(wout + (basebh + r1)*SEQ + k0c), make_float2(w2, w3));
            }
        }

        /* PV: 3x bf16 split, W frags straight from acc */
#pragma unroll
        for (int t = 0; t < 4; t++) {
            uint32_t awh[4], awl[4];
            {
                float c0 = acc[2*t][0],   c1 = acc[2*t][1];
                float c2 = acc[2*t][2],   c3 = acc[2*t][3];
                float d0 = acc[2*t+1][0], d1 = acc[2*t+1][1];
                float d2 = acc[2*t+1][2], d3 = acc[2*t+1][3];
                awh[0] = pack_bf2(c0, c1);
                awh[1] = pack_bf2(c2, c3);
                awh[2] = pack_bf2(d0, d1);
                awh[3] = pack_bf2(d2, d3);
                __nv_bfloat162* ph;
                ph = (__nv_bfloat162*)&awh[0];
                awl[0] = pack_bf2(c0 - __bfloat162float(ph->x),
                                  c1 - __bfloat162float(ph->y));
                ph = (__nv_bfloat162*)&awh[1];
                awl[1] = pack_bf2(c2 - __bfloat162float(ph->x),
                                  c3 - __bfloat162float(ph->y));
                ph = (__nv_bfloat162*)&awh[2];
                awl[2] = pack_bf2(d0 - __bfloat162float(ph->x),
                                  d1 - __bfloat162float(ph->y));
                ph = (__nv_bfloat162*)&awh[3];
                awl[3] = pack_bf2(d2 - __bfloat162float(ph->x),
                                  d3 - __bfloat162float(ph->y));
            }
#pragma unroll
            for (int nd = 0; nd < 4; nd++) {
                uint32_t vh[4], vl[4];
                ldsm4t(vh[0], vh[1], vh[2], vh[3],
                       kbase + av_off + t*2304 + nd*32);
                ldsm4t(vl[0], vl[1], vl[2], vl[3],
                       kbase + av_off + 9216 + t*2304 + nd*32);
                mma_bf16(o[nd*2],   awh, vh[0], vh[1]);
                mma_bf16(o[nd*2+1], awh, vh[2], vh[3]);
                mma_bf16(o[nd*2],   awl, vh[0], vh[1]);
                mma_bf16(o[nd*2+1], awl, vh[2], vh[3]);
                mma_bf16(o[nd*2],   awh, vl[0], vl[1]);
                mma_bf16(o[nd*2+1], awh, vl[2], vl[3]);
            }
        }
        __syncthreads();
    }

    /* zero-fill masked region */
    if (write_w) {
        int kend = q0 + 128;
        int rem = SEQ - kend;
        if (rem > 0) {
            float4 z4 = make_float4(0.f, 0.f, 0.f, 0.f);
            for (int r = tid >> 5; r < 128; r += 8) {
                float* rowp = wout + (basebh + q0 + r)*SEQ + kend;
                for (int cc = (tid & 31)*4; cc < rem; cc += 128)
                    __stcs((float4*)(rowp + cc), z4);
            }
        }
    }

    /* write O as out-proj A-operand: bf16 x256, fp8 [h*8 | l*4096] */
    {
        size_t mg0 = (size_t)b*SEQ + q0 + w*16 + g;
        size_t mg1 = mg0 + 8;
#pragma unroll
        for (int nd = 0; nd < 8; nd++) {
            int col = h*64 + nd*8 + q*2;
            float c0 = o[nd][0], c1 = o[nd][1];
            float c2 = o[nd][2], c3 = o[nd][3];
            __nv_bfloat16 h0 = __float2bfloat16(c0);
            __nv_bfloat16 h1 = __float2bfloat16(c1);
            __nv_bfloat16 h2 = __float2bfloat16(c2);
            __nv_bfloat16 h3 = __float2bfloat16(c3);
            float h0f = __bfloat162float(h0), h1f = __bfloat162float(h1);
            float h2f = __bfloat162float(h2), h3f = __bfloat162float(h3);
            *(__nv_bfloat162*)(a_oh + mg0*1024 + col) =
                __floats2bfloat162_rn(h0f*256.f, h1f*256.f);
            *(__nv_bfloat162*)(a_oh + mg1*1024 + col) =
                __floats2bfloat162_rn(h2f*256.f, h3f*256.f);
            *(uint16_t*)(a_o8 + mg0*2048 + col)        = cvt_e4m3x2(h0f*8.f, h1f*8.f);
            *(uint16_t*)(a_o8 + mg0*2048 + 1024 + col) = cvt_e4m3x2((c0-h0f)*4096.f, (c1-h1f)*4096.f);
            *(uint16_t*)(a_o8 + mg1*2048 + col)        = cvt_e4m3x2(h2f*8.f, h3f*8.f);
            *(uint16_t*)(a_o8 + mg1*2048 + 1024 + col) = cvt_e4m3x2((c2-h2f)*4096.f, (c3-h3f)*4096.f);
        }
    }
}

/* ---------------- launcher ---------------- */
extern "C" void kernel_launch(void* const* d_in, const int* in_sizes, int n_in,
                              void* d_out, int out_size)
{
    const float* q  = (const float*)d_in[0];
    const float* k  = (const float*)d_in[1];
    const float* v  = (const float*)d_in[2];
    const float* Wq = (const float*)d_in[3];
    const float* bq = (const float*)d_in[4];
    const float* Wk = (const float*)d_in[5];
    const float* bk = (const float*)d_in[6];
    const float* Wv = (const float*)d_in[7];
    const float* bv = (const float*)d_in[8];
    const float* Wo = (const float*)d_in[9];
    const float* bo = (const float*)d_in[10];

    float* out  = (float*)d_out;
    int write_w = (out_size >= OUT_ELEMS + W_ELEMS) ? 1 : 0;
    float* wout = out + OUT_ELEMS;

    __nv_bfloat16 *p_aqh, *p_akh, *p_avh, *p_aoh, *p_wqh, *p_wkh, *p_wvh, *p_woh;
    uint8_t *p_aq8, *p_ak8, *p_av8, *p_ao8, *p_wq8, *p_wk8, *p_wv8, *p_wo8;
    __nv_bfloat16 *p_qh, *p_kh, *p_vh, *p_vl;
    uint8_t *p_q8, *p_k8;
    cudaGetSymbolAddress((void**)&p_aqh, a_qh);
    cudaGetSymbolAddress((void**)&p_akh, a_kh);
    cudaGetSymbolAddress((void**)&p_avh, a_vh);
    cudaGetSymbolAddress((void**)&p_aoh, a_oh);
    cudaGetSymbolAddress((void**)&p_aq8, a_q8);
    cudaGetSymbolAddress((void**)&p_ak8, a_k8);
    cudaGetSymbolAddress((void**)&p_av8, a_v8);
    cudaGetSymbolAddress((void**)&p_ao8, a_o8);
    cudaGetSymbolAddress((void**)&p_wqh, w_qh);
    cudaGetSymbolAddress((void**)&p_wkh, w_kh);
    cudaGetSymbolAddress((void**)&p_wvh, w_vh);
    cudaGetSymbolAddress((void**)&p_woh, w_oh);
    cudaGetSymbolAddress((void**)&p_wq8, w_q8);
    cudaGetSymbolAddress((void**)&p_wk8, w_k8);
    cudaGetSymbolAddress((void**)&p_wv8, w_v8);
    cudaGetSymbolAddress((void**)&p_wo8, w_o8);
    cudaGetSymbolAddress((void**)&p_qh, g_Qh);
    cudaGetSymbolAddress((void**)&p_kh, g_Kh);
    cudaGetSymbolAddress((void**)&p_vh, g_Vh);
    cudaGetSymbolAddress((void**)&p_vl, g_Vl);
    cudaGetSymbolAddress((void**)&p_q8, g_Q8);
    cudaGetSymbolAddress((void**)&p_k8, g_K8);

    rope_table_kernel<<<(SEQ*32 + 255)/256, 256>>>();

    const int nIn2 = MTOT * HID / 2;
    const int nW2  = HID * HID / 2;
    split_a_kernel<<<(nIn2+255)/256, 256>>>(q, p_aqh, p_aq8, nIn2);
    split_a_kernel<<<(nIn2+255)/256, 256>>>(k, p_akh, p_ak8, nIn2);
    split_a_kernel<<<(nIn2+255)/256, 256>>>(v, p_avh, p_av8, nIn2);
    split_b_kernel<<<(nW2+255)/256, 256>>>(Wq, p_wqh, p_wq8, nW2);
    split_b_kernel<<<(nW2+255)/256, 256>>>(Wk, p_wkh, p_wk8, nW2);
    split_b_kernel<<<(nW2+255)/256, 256>>>(Wv, p_wvh, p_wv8, nW2);
    split_b_kernel<<<(nW2+255)/256, 256>>>(Wo, p_woh, p_wo8, nW2);

    cudaFuncSetAttribute(gemm_mma,
                         cudaFuncAttributeMaxDynamicSharedMemorySize, 2*GSTG);
    cudaFuncSetAttribute(attn_mma,
                         cudaFuncAttributeMaxDynamicSharedMemorySize, ASMEM);

    dim3 ggrid(HID/128, MTOT/128);   /* (8, 32) */
    gemm_mma<<<ggrid, 256, 2*GSTG>>>(p_aqh, p_aq8, p_wqh, p_wq8, bq, INV_S_PROJ,
                                     nullptr, p_qh, nullptr, p_q8, 0);
    gemm_mma<<<ggrid, 256, 2*GSTG>>>(p_akh, p_ak8, p_wkh, p_wk8, bk, INV_S_PROJ,
                                     nullptr, p_kh, nullptr, p_k8, 3);
    gemm_mma<<<ggrid, 256, 2*GSTG>>>(p_avh, p_av8, p_wvh, p_wv8, bv, INV_S_PROJ,
                                     nullptr, p_vh, p_vl, nullptr, 1);

    attn_mma<<<dim3(SEQ/128, NH, BATCH), 256, ASMEM>>>(wout, write_w);

    gemm_mma<<<ggrid, 256, 2*GSTG>>>(p_aoh, p_ao8, p_woh, p_wo8, bo, INV_S_OPRJ,
                                     out, nullptr, nullptr, nullptr, 2);
}

// round 8
// speedup vs baseline: 1.1414x; 1.1414x over previous
#include <cuda_runtime.h>
#include <cuda_bf16.h>
#include <cuda_fp16.h>
#include <math.h>
#include <stdint.h>

#define BATCH 2
#define SEQ   2048
#define HID   1024
#define NH    16
#define HD    64
#define MTOT  (BATCH*SEQ)
#define OUT_ELEMS   (MTOT*HID)
#define W_ELEMS     (BATCH*NH*SEQ*SEQ)
#define KS3   3072               /* split-K: [hi | lo | hi] x 1024 */
#define LOG2E 1.44269504088896340736f

/* ---------------- scratch (no allocations allowed) ---------------- */
__device__ float g_cos[SEQ*(HD/2)];
__device__ float g_sin[SEQ*(HD/2)];

__device__ __nv_bfloat16 g_Qh[BATCH*NH*SEQ*HD];
__device__ __nv_bfloat16 g_Ql[BATCH*NH*SEQ*HD];
__device__ __nv_bfloat16 g_Kh[BATCH*NH*SEQ*HD];
__device__ __nv_bfloat16 g_Kl[BATCH*NH*SEQ*HD];
__device__ __half        g_Vh[BATCH*NH*SEQ*HD];
__device__ __half        g_Vl[BATCH*NH*SEQ*HD];

/* unnormalized exp cache (f16) + per-(row,tile) running max */
__device__ __half g_E[(size_t)BATCH*NH*SEQ*SEQ];
__device__ float  g_M[(size_t)BATCH*NH*SEQ*(SEQ/64)];

__device__ __nv_bfloat16 s_q [MTOT*KS3];
__device__ __nv_bfloat16 s_k [MTOT*KS3];
__device__ __nv_bfloat16 s_v [MTOT*KS3];
__device__ __nv_bfloat16 s_at[MTOT*KS3];
__device__ __nv_bfloat16 s_wq[HID*KS3];
__device__ __nv_bfloat16 s_wk[HID*KS3];
__device__ __nv_bfloat16 s_wv[HID*KS3];
__device__ __nv_bfloat16 s_wo[HID*KS3];

/* ---------------- helpers ---------------- */
__device__ __forceinline__ uint32_t smem_u32(const void* p) {
    uint32_t a;
    asm("{ .reg .u64 t; cvta.to.shared.u64 t, %1; cvt.u32.u64 %0, t; }"
        : "=r"(a) : "l"(p));
    return a;
}
__device__ __forceinline__ void cp16(uint32_t s, const void* g) {
    asm volatile("cp.async.cg.shared.global [%0], [%1], 16;"
                 :: "r"(s), "l"(g));
}
#define CP_COMMIT() asm volatile("cp.async.commit_group;" ::: "memory")
#define CP_WAIT(N)  asm volatile("cp.async.wait_group %0;" :: "n"(N) : "memory")

__device__ __forceinline__ void ldsm4(uint32_t& r0, uint32_t& r1,
                                      uint32_t& r2, uint32_t& r3, uint32_t addr)
{
    asm volatile("ldmatrix.sync.aligned.m8n8.x4.shared.b16 {%0,%1,%2,%3}, [%4];"
                 : "=r"(r0), "=r"(r1), "=r"(r2), "=r"(r3) : "r"(addr));
}
__device__ __forceinline__ void ldsm4t(uint32_t& r0, uint32_t& r1,
                                       uint32_t& r2, uint32_t& r3, uint32_t addr)
{
    asm volatile("ldmatrix.sync.aligned.m8n8.x4.trans.shared.b16 {%0,%1,%2,%3}, [%4];"
                 : "=r"(r0), "=r"(r1), "=r"(r2), "=r"(r3) : "r"(addr));
}
__device__ __forceinline__ void mma_bf16(float* d, const uint32_t* a,
                                         uint32_t b0, uint32_t b1)
{
    asm volatile(
        "mma.sync.aligned.m16n8k16.row.col.f32.bf16.bf16.f32 "
        "{%0,%1,%2,%3}, {%4,%5,%6,%7}, {%8,%9}, {%0,%1,%2,%3};"
        : "+f"(d[0]), "+f"(d[1]), "+f"(d[2]), "+f"(d[3])
        : "r"(a[0]), "r"(a[1]), "r"(a[2]), "r"(a[3]), "r"(b0), "r"(b1));
}
__device__ __forceinline__ void mma_f16(float* d, const uint32_t* a,
                                        uint32_t b0, uint32_t b1)
{
    asm volatile(
        "mma.sync.aligned.m16n8k16.row.col.f32.f16.f16.f32 "
        "{%0,%1,%2,%3}, {%4,%5,%6,%7}, {%8,%9}, {%0,%1,%2,%3};"
        : "+f"(d[0]), "+f"(d[1]), "+f"(d[2]), "+f"(d[3])
        : "r"(a[0]), "r"(a[1]), "r"(a[2]), "r"(a[3]), "r"(b0), "r"(b1));
}
__device__ __forceinline__ float ex2(float x) {
    float y;
    asm("ex2.approx.ftz.f32 %0, %1;" : "=f"(y) : "f"(x));
    return y;
}
__device__ __forceinline__ uint32_t pack_h2(float x, float y) {
    __half2 t = __floats2half2_rn(x, y);
    return *(uint32_t*)&t;
}

/* ---------------- RoPE tables ---------------- */
__global__ void rope_table_kernel() {
    int idx = blockIdx.x * blockDim.x + threadIdx.x;
    if (idx >= SEQ * (HD/2)) return;
    int s = idx >> 5;
    int j = idx & 31;
    double inv = exp(-((double)(2*j) / (double)HD) * log(10000.0));
    double ang = (double)s * inv;
    g_cos[idx] = (float)cos(ang);
    g_sin[idx] = (float)sin(ang);
}

/* -------- fp32 -> bf16 splits (R5 format) -------- */
__global__ void __launch_bounds__(256)
split_a_kernel(const float* __restrict__ src, __nv_bfloat16* __restrict__ dst, int n)
{
    int idx = blockIdx.x * blockDim.x + threadIdx.x;
    if (idx >= n) return;
    float x = src[idx];
    int row = idx >> 10, kk = idx & 1023;
    int blk = kk >> 5,  j  = kk & 31;
    __nv_bfloat16 hi = __float2bfloat16(x);
    __nv_bfloat16 lo = __float2bfloat16(x - __bfloat162float(hi));
    size_t base = (size_t)row * KS3 + blk*96 + j;
    dst[base]      = hi;
    dst[base + 32] = lo;
    dst[base + 64] = hi;
}
__global__ void __launch_bounds__(256)
split_b_kernel(const float* __restrict__ src, __nv_bfloat16* __restrict__ dst, int n)
{
    int idx = blockIdx.x * blockDim.x + threadIdx.x;
    if (idx >= n) return;
    float x = src[idx];
    int row = idx >> 10, kk = idx & 1023;
    int blk = kk >> 5,  j  = kk & 31;
    __nv_bfloat16 hi = __float2bfloat16(x);
    __nv_bfloat16 lo = __float2bfloat16(x - __bfloat162float(hi));
    size_t base = (size_t)row * KS3 + blk*96 + j;
    dst[base]      = hi;
    dst[base + 32] = hi;
    dst[base + 64] = lo;
}

/* ================= pipelined mma.sync GEMM (R5) =================
   mode 0: +bias, RoPE, bf16 hi/lo out (B,H,S,D)   [Q and K]
   mode 1: +bias,       f16  hi/lo out (B,H,S,D)   [V]
   mode 2: +bias,       fp32 row-major out                        */
#define GSTG 36864

__global__ void __launch_bounds__(256, 2)
gemm_mma(const __nv_bfloat16* __restrict__ A,
         const __nv_bfloat16* __restrict__ B,
         const float* __restrict__ bias,
         float* __restrict__ dst,
         void* __restrict__ dhi_v,
         void* __restrict__ dlo_v, int mode)
{
    extern __shared__ __align__(16) char gsm[];

    const int tid = threadIdx.x;
    const int wid = tid >> 5, l = tid & 31;
    const int warp_m = wid >> 1, warp_n = wid & 1;
    const int m0 = blockIdx.y * 128;
    const int n0 = blockIdx.x * 128;
    const uint32_t sb = smem_u32(gsm);

    const uint4* gA = (const uint4*)(A + (size_t)m0 * KS3);
    const uint4* gB = (const uint4*)(B + (size_t)n0 * KS3);

    float acc[2][8][4];
#pragma unroll
    for (int i = 0; i < 2; i++)
#pragma unroll
        for (int j = 0; j < 8; j++)
#pragma unroll
            for (int p = 0; p < 4; p++) acc[i][j][p] = 0.f;

    uint32_t a_off[2], b_off[4];
#pragma unroll
    for (int mt = 0; mt < 2; mt++)
        a_off[mt] = (warp_m*32 + mt*16 + (l & 15))*144 + (l >> 4)*16;
#pragma unroll
    for (int nt = 0; nt < 4; nt++) {
        int row = warp_n*64 + nt*16 + (l & 7) + ((l >> 4) & 1) * 8;
        b_off[nt] = 18432 + row*144 + ((l >> 3) & 1)*16;
    }

    auto load_stage = [&](int stg, int it) {
        uint32_t base = sb + stg*GSTG;
#pragma unroll
        for (int u = 0; u < 4; u++) {
            int f = u*256 + tid;
            int r = f >> 3, c = f & 7;
            cp16(base + r*144 + c*16,         gA + (size_t)r*(KS3/8) + it*8 + c);
            cp16(base + 18432 + r*144 + c*16, gB + (size_t)r*(KS3/8) + it*8 + c);
        }
    };

    load_stage(0, 0);
    CP_COMMIT();

    for (int it = 0; it < KS3/64; it++) {
        int cur = it & 1;
        if (it + 1 < KS3/64) {
            load_stage(cur ^ 1, it + 1);
            CP_COMMIT();
            CP_WAIT(1);
        } else {
            CP_WAIT(0);
        }
        __syncthreads();

        uint32_t stgb = sb + cur*GSTG;
#pragma unroll
        for (int ks = 0; ks < 4; ks++) {
            uint32_t a[2][4], b[4][4];
#pragma unroll
            for (int mt = 0; mt < 2; mt++)
                ldsm4(a[mt][0], a[mt][1], a[mt][2], a[mt][3],
                      stgb + a_off[mt] + ks*32);
#pragma unroll
            for (int nt = 0; nt < 4; nt++)
                ldsm4(b[nt][0], b[nt][1], b[nt][2], b[nt][3],
                      stgb + b_off[nt] + ks*32);
#pragma unroll
            for (int mt = 0; mt < 2; mt++)
#pragma unroll
                for (int nt = 0; nt < 4; nt++) {
                    mma_bf16(acc[mt][nt*2],   a[mt], b[nt][0], b[nt][1]);
                    mma_bf16(acc[mt][nt*2+1], a[mt], b[nt][2], b[nt][3]);
                }
        }
        __syncthreads();
    }

    /* ---------------- epilogue ---------------- */
    const int g = l >> 2, q = l & 3;
#pragma unroll
    for (int mt = 0; mt < 2; mt++) {
        int mrow0 = m0 + warp_m*32 + mt*16 + g;
#pragma unroll
        for (int nt2 = 0; nt2 < 8; nt2++) {
            int ncol = n0 + warp_n*64 + nt2*8 + q*2;
            float b0 = bias[ncol], b1 = bias[ncol+1];
            float c0 = acc[mt][nt2][0] + b0;
            float c1 = acc[mt][nt2][1] + b1;
            float c2 = acc[mt][nt2][2] + b0;
            float c3 = acc[mt][nt2][3] + b1;

            if (mode == 2) {
                *(float2*)(dst + (size_t)mrow0    *HID + ncol) = make_float2(c0, c1);
                *(float2*)(dst + (size_t)(mrow0+8)*HID + ncol) = make_float2(c2, c3);
            } else {
                int h = ncol >> 6, d = ncol & 63;
                int bb0 = mrow0 >> 11, ss0 = mrow0 & 2047;
                int mrow1 = mrow0 + 8;
                int bb1 = mrow1 >> 11, ss1 = mrow1 & 2047;
                if (mode == 0) {
                    float cs0 = g_cos[ss0*32 + (d>>1)], sn0 = g_sin[ss0*32 + (d>>1)];
                    float cs1 = g_cos[ss1*32 + (d>>1)], sn1 = g_sin[ss1*32 + (d>>1)];
                    float t0 = c0*cs0 - c1*sn0, t1 = c0*sn0 + c1*cs0;
                    float t2 = c2*cs1 - c3*sn1, t3 = c2*sn1 + c3*cs1;
                    c0 = t0; c1 = t1; c2 = t2; c3 = t3;
                }
                size_t a0 = (((size_t)(bb0*NH + h)*SEQ + ss0) << 6) + d;
                size_t a1 = (((size_t)(bb1*NH + h)*SEQ + ss1) << 6) + d;
                if (mode == 1) {   /* V: f16 hi + lo */
                    __half* dhi = (__half*)dhi_v;
                    __half* dlo = (__half*)dlo_v;
                    __half h0 = __float2half_rn(c0);
                    __half h1 = __float2half_rn(c1);
                    __half h2 = __float2half_rn(c2);
                    __half h3 = __float2half_rn(c3);
                    *(__half2*)(dhi + a0) = __halves2half2(h0, h1);
                    *(__half2*)(dhi + a1) = __halves2half2(h2, h3);
                    *(__half2*)(dlo + a0) = __floats2half2_rn(
                        c0 - __half2float(h0), c1 - __half2float(h1));
                    *(__half2*)(dlo + a1) = __floats2half2_rn(
                        c2 - __half2float(h2), c3 - __half2float(h3));
                } else {           /* Q/K: bf16 hi + lo */
                    __nv_bfloat16* dhi = (__nv_bfloat16*)dhi_v;
                    __nv_bfloat16* dlo = (__nv_bfloat16*)dlo_v;
                    __nv_bfloat16 h0 = __float2bfloat16(c0);
                    __nv_bfloat16 h1 = __float2bfloat16(c1);
                    __nv_bfloat16 h2 = __float2bfloat16(c2);
                    __nv_bfloat16 h3 = __float2bfloat16(c3);
                    *(__nv_bfloat162*)(dhi + a0) = __halves2bfloat162(h0, h1);
                    *(__nv_bfloat162*)(dhi + a1) = __halves2bfloat162(h2, h3);
                    *(__nv_bfloat162*)(dlo + a0) = __floats2bfloat162_rn(
                        c0 - __bfloat162float(h0), c1 - __bfloat162float(h1));
                    *(__nv_bfloat162*)(dlo + a1) = __floats2bfloat162_rn(
                        c2 - __bfloat162float(h2), c3 - __bfloat162float(h3));
                }
            }
        }
    }
}

/* ================= single-pass flash attention + e-cache =========
   Phase 1 (per k-tile): QK 3-term bf16 -> s; online m/l; e=exp2(s-m)
   stored f16 to g_E (+ m per row,tile to g_M); O rescaled, O += e@V
   (V f16 hi/lo, e exact f16 -> 2 mma). Phase 2: re-read e, scale by
   exp2(m_tile - m_fin)*invl, write fp32 weights. O scaled by invl,
   written in split-A format for out-proj.                           */
#define QSZ   36864
#define ASTG  36864
#define ASMEM (QSZ + 2*ASTG + 1024)

__global__ void __launch_bounds__(256, 2)
attn_mma(float* __restrict__ wout, int write_w)
{
    extern __shared__ __align__(16) char dsm[];
    float2* rowfac = (float2*)(dsm + QSZ + 2*ASTG);   /* [128] */

    const int tid = threadIdx.x;
    const int w = tid >> 5, l = tid & 31;
    const int g = l >> 2, q = l & 3;
    const int qt = (gridDim.x - 1) - blockIdx.x;      /* heavy first */
    const int h = blockIdx.y, b = blockIdx.z;
    const int q0 = qt * 128;
    const size_t basebh = (size_t)(b*NH + h) * SEQ;
    const uint32_t sb = smem_u32(dsm);

    /* Q loads */
    {
        const uint4* gh = (const uint4*)(g_Qh + (basebh + q0) * HD);
        const uint4* gl = (const uint4*)(g_Ql + (basebh + q0) * HD);
#pragma unroll
        for (int u = 0; u < 4; u++) {
            int f = u*256 + tid;
            int r = f >> 3, c = f & 7;
            cp16(sb + r*144 + c*16,         gh + r*8 + c);
            cp16(sb + 18432 + r*144 + c*16, gl + r*8 + c);
        }
        CP_COMMIT();
    }

    const uint32_t aQh = sb + (w*16 + (l & 15))*144 + (l >> 4)*16;
    const uint32_t aQl = aQh + 18432;
    uint32_t bk_off[4];
    {
        int krow = (l & 7) + ((l >> 4) & 1) * 8;
        int kcb  = ((l >> 3) & 1) * 16;
#pragma unroll
        for (int nt = 0; nt < 4; nt++)
            bk_off[nt] = (nt*16 + krow)*144 + kcb;
    }
    const uint32_t av_off = 18432 + (l & 15)*144 + (l >> 4)*16;

    const float CE = 0.125f * LOG2E;
    const int nkt = 2*qt + 2;
    const int rw0 = q0 + w*16;
    const int r0 = rw0 + g, r1 = r0 + 8;

    auto loadKV = [&](int stg, int kb) {
        uint32_t base = sb + QSZ + stg*ASTG;
        const uint4* gkh = (const uint4*)(g_Kh + (basebh + kb*64) * HD);
        const uint4* gkl = (const uint4*)(g_Kl + (basebh + kb*64) * HD);
        const uint4* gvh = (const uint4*)(g_Vh + (basebh + kb*64) * HD);
        const uint4* gvl = (const uint4*)(g_Vl + (basebh + kb*64) * HD);
#pragma unroll
        for (int u = 0; u < 2; u++) {
            int f = u*256 + tid;
            int r = f >> 3, c = f & 7;
            cp16(base + r*144 + c*16,         gkh + r*8 + c);
            cp16(base + 9216  + r*144 + c*16, gkl + r*8 + c);
            cp16(base + 18432 + r*144 + c*16, gvh + r*8 + c);
            cp16(base + 27648 + r*144 + c*16, gvl + r*8 + c);
        }
    };

    float m2[2] = {-1e30f, -1e30f};
    float l2[2] = {0.f, 0.f};
    float o[8][4];
#pragma unroll
    for (int nd = 0; nd < 8; nd++)
#pragma unroll
        for (int p = 0; p < 4; p++) o[nd][p] = 0.f;

    loadKV(0, 0);
    CP_COMMIT();

    for (int kb = 0; kb < nkt; kb++) {
        int cur = kb & 1;
        if (kb + 1 < nkt) {
            loadKV(cur ^ 1, kb + 1);
            CP_COMMIT();
            CP_WAIT(1);
        } else {
            CP_WAIT(0);
        }
        __syncthreads();

        uint32_t kbase = sb + QSZ + cur*ASTG;

        /* QK: 3-term bf16 split */
        float acc[8][4];
#pragma unroll
        for (int nt = 0; nt < 8; nt++)
#pragma unroll
            for (int p = 0; p < 4; p++) acc[nt][p] = 0.f;
#pragma unroll
        for (int ks = 0; ks < 4; ks++) {
            uint32_t ah[4], al[4];
            ldsm4(ah[0], ah[1], ah[2], ah[3], aQh + ks*32);
            ldsm4(al[0], al[1], al[2], al[3], aQl + ks*32);
#pragma unroll
            for (int np = 0; np < 4; np++) {
                uint32_t kh[4], kl[4];
                ldsm4(kh[0], kh[1], kh[2], kh[3], kbase + bk_off[np] + ks*32);
                ldsm4(kl[0], kl[1], kl[2], kl[3], kbase + 9216 + bk_off[np] + ks*32);
                mma_bf16(acc[np*2],   ah, kh[0], kh[1]);
                mma_bf16(acc[np*2+1], ah, kh[2], kh[3]);
                mma_bf16(acc[np*2],   al, kh[0], kh[1]);
                mma_bf16(acc[np*2+1], al, kh[2], kh[3]);
                mma_bf16(acc[np*2],   ah, kl[0], kl[1]);
                mma_bf16(acc[np*2+1], ah, kl[2], kl[3]);
            }
        }

        /* mask + scale to log2 domain */
        const bool needmask = (kb*64 + 63) > rw0;
#pragma unroll
        for (int nt = 0; nt < 8; nt++) {
            int k0c = kb*64 + nt*8 + q*2;
            acc[nt][0] = (!needmask || k0c   <= r0) ? acc[nt][0]*CE : -1e30f;
            acc[nt][1] = (!needmask || k0c+1 <= r0) ? acc[nt][1]*CE : -1e30f;
            acc[nt][2] = (!needmask || k0c   <= r1) ? acc[nt][2]*CE : -1e30f;
            acc[nt][3] = (!needmask || k0c+1 <= r1) ? acc[nt][3]*CE : -1e30f;
        }

        /* online max */
        float tm0 = -1e30f, tm1 = -1e30f;
#pragma unroll
        for (int nt = 0; nt < 8; nt++) {
            tm0 = fmaxf(tm0, fmaxf(acc[nt][0], acc[nt][1]));
            tm1 = fmaxf(tm1, fmaxf(acc[nt][2], acc[nt][3]));
        }
        tm0 = fmaxf(tm0, __shfl_xor_sync(0xffffffffu, tm0, 1));
        tm0 = fmaxf(tm0, __shfl_xor_sync(0xffffffffu, tm0, 2));
        tm1 = fmaxf(tm1, __shfl_xor_sync(0xffffffffu, tm1, 1));
        tm1 = fmaxf(tm1, __shfl_xor_sync(0xffffffffu, tm1, 2));
        float mn0 = fmaxf(m2[0], tm0), mn1 = fmaxf(m2[1], tm1);
        float cf0 = ex2(m2[0] - mn0), cf1 = ex2(m2[1] - mn1);

        /* e = exp2(s - m); pack f16, store to gmem, row sums */
        uint32_t ew0[8], ew1[8];
        float s0 = 0.f, s1 = 0.f;
#pragma unroll
        for (int nt = 0; nt < 8; nt++) {
            float e0 = ex2(acc[nt][0] - mn0);
            float e1 = ex2(acc[nt][1] - mn0);
            float e2 = ex2(acc[nt][2] - mn1);
            float e3 = ex2(acc[nt][3] - mn1);
            s0 += e0 + e1;  s1 += e2 + e3;
            ew0[nt] = pack_h2(e0, e1);
            ew1[nt] = pack_h2(e2, e3);
            int k0c = kb*64 + nt*8 + q*2;
            __stcs((uint32_t*)((__half*)g_E + (basebh + r0)*SEQ + k0c), ew0[nt]);
            __stcs((uint32_t*)((__half*)g_E + (basebh + r1)*SEQ + k0c), ew1[nt]);
        }
        s0 += __shfl_xor_sync(0xffffffffu, s0, 1);
        s0 += __shfl_xor_sync(0xffffffffu, s0, 2);
        s1 += __shfl_xor_sync(0xffffffffu, s1, 1);
        s1 += __shfl_xor_sync(0xffffffffu, s1, 2);
        l2[0] = l2[0]*cf0 + s0;  m2[0] = mn0;
        l2[1] = l2[1]*cf1 + s1;  m2[1] = mn1;

        if (q == 0) {
            g_M[(basebh + r0)*32 + kb] = mn0;
            g_M[(basebh + r1)*32 + kb] = mn1;
        }

        /* rescale O */
#pragma unroll
        for (int nd = 0; nd < 8; nd++) {
            o[nd][0] *= cf0; o[nd][1] *= cf0;
            o[nd][2] *= cf1; o[nd][3] *= cf1;
        }

        /* PV: e (exact f16) x V f16 hi/lo, 2 mma per (t,nd) pair */
#pragma unroll
        for (int t = 0; t < 4; t++) {
            uint32_t aw[4] = {ew0[2*t], ew1[2*t], ew0[2*t+1], ew1[2*t+1]};
#pragma unroll
            for (int nd = 0; nd < 4; nd++) {
                uint32_t vh[4], vl[4];
                ldsm4t(vh[0], vh[1], vh[2], vh[3],
                       kbase + av_off + t*2304 + nd*32);
                ldsm4t(vl[0], vl[1], vl[2], vl[3],
                       kbase + av_off + 9216 + t*2304 + nd*32);
                mma_f16(o[nd*2],   aw, vh[0], vh[1]);
                mma_f16(o[nd*2+1], aw, vh[2], vh[3]);
                mma_f16(o[nd*2],   aw, vl[0], vl[1]);
                mma_f16(o[nd*2+1], aw, vl[2], vl[3]);
            }
        }
        __syncthreads();
    }

    const float invl0 = 1.f / l2[0];
    const float invl1 = 1.f / l2[1];
    if (q == 0) {
        rowfac[w*16 + g]     = make_float2(m2[0], invl0);
        rowfac[w*16 + g + 8] = make_float2(m2[1], invl1);
    }

    /* write O in split-A format for out-proj */
    {
        size_t mg0 = (size_t)b*SEQ + q0 + w*16 + g;
        size_t mg1 = mg0 + 8;
#pragma unroll
        for (int nd = 0; nd < 8; nd++) {
            int col = h*64 + nd*8 + q*2;
            int blk = col >> 5, j = col & 31;
            size_t b0 = mg0*KS3 + blk*96 + j;
            size_t b1 = mg1*KS3 + blk*96 + j;
            float c0 = o[nd][0]*invl0, c1 = o[nd][1]*invl0;
            float c2 = o[nd][2]*invl1, c3 = o[nd][3]*invl1;
            __nv_bfloat16 h0 = __float2bfloat16(c0);
            __nv_bfloat16 h1 = __float2bfloat16(c1);
            __nv_bfloat16 h2 = __float2bfloat16(c2);
            __nv_bfloat16 h3 = __float2bfloat16(c3);
            __nv_bfloat162 hi0 = __halves2bfloat162(h0, h1);
            __nv_bfloat162 hi1 = __halves2bfloat162(h2, h3);
            __nv_bfloat162 lo0 = __floats2bfloat162_rn(
                c0 - __bfloat162float(h0), c1 - __bfloat162float(h1));
            __nv_bfloat162 lo1 = __floats2bfloat162_rn(
                c2 - __bfloat162float(h2), c3 - __bfloat162float(h3));
            *(__nv_bfloat162*)(s_at + b0)      = hi0;
            *(__nv_bfloat162*)(s_at + b0 + 32) = lo0;
            *(__nv_bfloat162*)(s_at + b0 + 64) = hi0;
            *(__nv_bfloat162*)(s_at + b1)      = hi1;
            *(__nv_bfloat162*)(s_at + b1 + 32) = lo1;
            *(__nv_bfloat162*)(s_at + b1 + 64) = hi1;
        }
    }
    __syncthreads();

    /* ---------------- phase 2: normalize weights ---------------- */
    if (write_w) {
        const int per_row = nkt * 8;            /* uint4 (8 f16) per row */
        const int total = 128 * per_row;
        for (int f = tid; f < total; f += 256) {
            int r = f / per_row;
            int j = f - r * per_row;
            int kb = j >> 3;
            int cc = (j & 7) * 8;
            float2 rf = rowfac[r];
            float mt = g_M[(basebh + q0 + r)*32 + kb];
            float sc = ex2(mt - rf.x) * rf.y;
            size_t eoff = (basebh + q0 + r)*SEQ + kb*64 + cc;
            uint4 ev = *(const uint4*)((const __half*)g_E + eoff);
            __half2 p0 = *(__half2*)&ev.x;
            __half2 p1 = *(__half2*)&ev.y;
            __half2 p2 = *(__half2*)&ev.z;
            __half2 p3 = *(__half2*)&ev.w;
            float4 w0 = make_float4(__half2float(p0.x)*sc, __half2float(p0.y)*sc,
                                    __half2float(p1.x)*sc, __half2float(p1.y)*sc);
            float4 w1 = make_float4(__half2float(p2.x)*sc, __half2float(p2.y)*sc,
                                    __half2float(p3.x)*sc, __half2float(p3.y)*sc);
            __stcs((float4*)(wout + eoff), w0);
            __stcs((float4*)(wout + eoff + 4), w1);
        }

        /* zero-fill masked (upper-triangle) region */
        int kend = q0 + 128;
        int rem = SEQ - kend;
        if (rem > 0) {
            float4 z4 = make_float4(0.f, 0.f, 0.f, 0.f);
            for (int r = tid >> 5; r < 128; r += 8) {
                float* rowp = wout + (basebh + q0 + r)*SEQ + kend;
                for (int cc = (tid & 31)*4; cc < rem; cc += 128)
                    __stcs((float4*)(rowp + cc), z4);
            }
        }
    }
}

/* ---------------- launcher ---------------- */
extern "C" void kernel_launch(void* const* d_in, const int* in_sizes, int n_in,
                              void* d_out, int out_size)
{
    const float* q  = (const float*)d_in[0];
    const float* k  = (const float*)d_in[1];
    const float* v  = (const float*)d_in[2];
    const float* Wq = (const float*)d_in[3];
    const float* bq = (const float*)d_in[4];
    const float* Wk = (const float*)d_in[5];
    const float* bk = (const float*)d_in[6];
    const float* Wv = (const float*)d_in[7];
    const float* bv = (const float*)d_in[8];
    const float* Wo = (const float*)d_in[9];
    const float* bo = (const float*)d_in[10];

    float* out  = (float*)d_out;
    int write_w = (out_size >= OUT_ELEMS + W_ELEMS) ? 1 : 0;
    float* wout = out + OUT_ELEMS;

    __nv_bfloat16 *p_sq, *p_sk, *p_sv, *p_swq, *p_swk, *p_swv, *p_swo, *p_sat;
    __nv_bfloat16 *p_qh, *p_ql, *p_kh, *p_kl;
    __half *p_vh, *p_vl;
    cudaGetSymbolAddress((void**)&p_sq,  s_q);
    cudaGetSymbolAddress((void**)&p_sk,  s_k);
    cudaGetSymbolAddress((void**)&p_sv,  s_v);
    cudaGetSymbolAddress((void**)&p_swq, s_wq);
    cudaGetSymbolAddress((void**)&p_swk, s_wk);
    cudaGetSymbolAddress((void**)&p_swv, s_wv);
    cudaGetSymbolAddress((void**)&p_swo, s_wo);
    cudaGetSymbolAddress((void**)&p_sat, s_at);
    cudaGetSymbolAddress((void**)&p_qh, g_Qh);
    cudaGetSymbolAddress((void**)&p_ql, g_Ql);
    cudaGetSymbolAddress((void**)&p_kh, g_Kh);
    cudaGetSymbolAddress((void**)&p_kl, g_Kl);
    cudaGetSymbolAddress((void**)&p_vh, g_Vh);
    cudaGetSymbolAddress((void**)&p_vl, g_Vl);

    rope_table_kernel<<<(SEQ*32 + 255)/256, 256>>>();

    const int nIn = MTOT * HID;
    const int nW  = HID * HID;
    split_a_kernel<<<(nIn+255)/256, 256>>>(q,  p_sq,  nIn);
    split_a_kernel<<<(nIn+255)/256, 256>>>(k,  p_sk,  nIn);
    split_a_kernel<<<(nIn+255)/256, 256>>>(v,  p_sv,  nIn);
    split_b_kernel<<<(nW +255)/256, 256>>>(Wq, p_swq, nW);
    split_b_kernel<<<(nW +255)/256, 256>>>(Wk, p_swk, nW);
    split_b_kernel<<<(nW +255)/256, 256>>>(Wv, p_swv, nW);
    split_b_kernel<<<(nW +255)/256, 256>>>(Wo, p_swo, nW);

    cudaFuncSetAttribute(gemm_mma,
                         cudaFuncAttributeMaxDynamicSharedMemorySize, 2*GSTG);
    cudaFuncSetAttribute(attn_mma,
                         cudaFuncAttributeMaxDynamicSharedMemorySize, ASMEM);

    dim3 ggrid(HID/128, MTOT/128);   /* (8, 32) */
    gemm_mma<<<ggrid, 256, 2*GSTG>>>(p_sq, p_swq, bq, nullptr, p_qh, p_ql, 0);
    gemm_mma<<<ggrid, 256, 2*GSTG>>>(p_sk, p_swk, bk, nullptr, p_kh, p_kl, 0);
    gemm_mma<<<ggrid, 256, 2*GSTG>>>(p_sv, p_swv, bv, nullptr, p_vh, p_vl, 1);

    attn_mma<<<dim3(SEQ/128, NH, BATCH), 256, ASMEM>>>(wout, write_w);

    gemm_mma<<<ggrid, 256, 2*GSTG>>>(p_sat, p_swo, bo, out, nullptr, nullptr, 2);
}

// round 9
// speedup vs baseline: 1.2627x; 1.1063x over previous
#include <cuda_runtime.h>
#include <cuda_bf16.h>
#include <cuda_fp16.h>
#include <math.h>
#include <stdint.h>

#define BATCH 2
#define SEQ   2048
#define HID   1024
#define NH    16
#define HD    64
#define MTOT  (BATCH*SEQ)
#define OUT_ELEMS   (MTOT*HID)
#define W_ELEMS     (BATCH*NH*SEQ*SEQ)
#define KS3   3072               /* split-K: [hi | lo | hi] x 1024 */
#define LOG2E 1.44269504088896340736f

/* ---------------- scratch (no allocations allowed) ---------------- */
__device__ float g_cos[SEQ*(HD/2)];
__device__ float g_sin[SEQ*(HD/2)];

__device__ __nv_bfloat16 g_Qh[BATCH*NH*SEQ*HD];
__device__ __nv_bfloat16 g_Ql[BATCH*NH*SEQ*HD];
__device__ __nv_bfloat16 g_Kh[BATCH*NH*SEQ*HD];
__device__ __nv_bfloat16 g_Kl[BATCH*NH*SEQ*HD];
__device__ __half        g_Vh[BATCH*NH*SEQ*HD];
__device__ __half        g_Vl[BATCH*NH*SEQ*HD];

__device__ __nv_bfloat16 s_q [MTOT*KS3];
__device__ __nv_bfloat16 s_k [MTOT*KS3];
__device__ __nv_bfloat16 s_v [MTOT*KS3];
__device__ __nv_bfloat16 s_at[MTOT*KS3];
__device__ __nv_bfloat16 s_wq[HID*KS3];
__device__ __nv_bfloat16 s_wk[HID*KS3];
__device__ __nv_bfloat16 s_wv[HID*KS3];
__device__ __nv_bfloat16 s_wo[HID*KS3];

/* ---------------- helpers ---------------- */
__device__ __forceinline__ uint32_t smem_u32(const void* p) {
    uint32_t a;
    asm("{ .reg .u64 t; cvta.to.shared.u64 t, %1; cvt.u32.u64 %0, t; }"
        : "=r"(a) : "l"(p));
    return a;
}
__device__ __forceinline__ void cp16(uint32_t s, const void* g) {
    asm volatile("cp.async.cg.shared.global [%0], [%1], 16;"
                 :: "r"(s), "l"(g));
}
#define CP_COMMIT() asm volatile("cp.async.commit_group;" ::: "memory")
#define CP_WAIT(N)  asm volatile("cp.async.wait_group %0;" :: "n"(N) : "memory")

__device__ __forceinline__ void ldsm4(uint32_t& r0, uint32_t& r1,
                                      uint32_t& r2, uint32_t& r3, uint32_t addr)
{
    asm volatile("ldmatrix.sync.aligned.m8n8.x4.shared.b16 {%0,%1,%2,%3}, [%4];"
                 : "=r"(r0), "=r"(r1), "=r"(r2), "=r"(r3) : "r"(addr));
}
__device__ __forceinline__ void ldsm4t(uint32_t& r0, uint32_t& r1,
                                       uint32_t& r2, uint32_t& r3, uint32_t addr)
{
    asm volatile("ldmatrix.sync.aligned.m8n8.x4.trans.shared.b16 {%0,%1,%2,%3}, [%4];"
                 : "=r"(r0), "=r"(r1), "=r"(r2), "=r"(r3) : "r"(addr));
}
__device__ __forceinline__ void mma_bf16(float* d, const uint32_t* a,
                                         uint32_t b0, uint32_t b1)
{
    asm volatile(
        "mma.sync.aligned.m16n8k16.row.col.f32.bf16.bf16.f32 "
        "{%0,%1,%2,%3}, {%4,%5,%6,%7}, {%8,%9}, {%0,%1,%2,%3};"
        : "+f"(d[0]), "+f"(d[1]), "+f"(d[2]), "+f"(d[3])
        : "r"(a[0]), "r"(a[1]), "r"(a[2]), "r"(a[3]), "r"(b0), "r"(b1));
}
__device__ __forceinline__ void mma_f16(float* d, const uint32_t* a,
                                        uint32_t b0, uint32_t b1)
{
    asm volatile(
        "mma.sync.aligned.m16n8k16.row.col.f32.f16.f16.f32 "
        "{%0,%1,%2,%3}, {%4,%5,%6,%7}, {%8,%9}, {%0,%1,%2,%3};"
        : "+f"(d[0]), "+f"(d[1]), "+f"(d[2]), "+f"(d[3])
        : "r"(a[0]), "r"(a[1]), "r"(a[2]), "r"(a[3]), "r"(b0), "r"(b1));
}
__device__ __forceinline__ float ex2(float x) {
    float y;
    asm("ex2.approx.ftz.f32 %0, %1;" : "=f"(y) : "f"(x));
    return y;
}
__device__ __forceinline__ uint32_t pack_h2(float x, float y) {
    __half2 t = __floats2half2_rn(x, y);
    return *(uint32_t*)&t;
}

/* ---------------- RoPE tables ---------------- */
__global__ void rope_table_kernel() {
    int idx = blockIdx.x * blockDim.x + threadIdx.x;
    if (idx >= SEQ * (HD/2)) return;
    int s = idx >> 5;
    int j = idx & 31;
    double inv = exp(-((double)(2*j) / (double)HD) * log(10000.0));
    double ang = (double)s * inv;
    g_cos[idx] = (float)cos(ang);
    g_sin[idx] = (float)sin(ang);
}

/* -------- merged fp32 -> bf16 split (all 7 tensors, 1 launch) ----- */
__global__ void __launch_bounds__(256)
split_all(const float* __restrict__ q, const float* __restrict__ k,
          const float* __restrict__ v, const float* __restrict__ Wq,
          const float* __restrict__ Wk, const float* __restrict__ Wv,
          const float* __restrict__ Wo)
{
    int bid = blockIdx.x;
    const float* src;
    __nv_bfloat16* dst;
    int idx, isA;
    if (bid < 49152) {                 /* inputs: 3 x 16384 blocks */
        int t = bid >> 14;             /* /16384 */
        src = (t == 0) ? q : (t == 1) ? k : v;
        dst = (t == 0) ? s_q : (t == 1) ? s_k : s_v;
        idx = ((bid & 16383) << 8) + threadIdx.x;
        isA = 1;
    } else {                           /* weights: 4 x 4096 blocks */
        int r = bid - 49152;
        int t = r >> 12;               /* /4096 */
        src = (t == 0) ? Wq : (t == 1) ? Wk : (t == 2) ? Wv : Wo;
        dst = (t == 0) ? s_wq : (t == 1) ? s_wk : (t == 2) ? s_wv : s_wo;
        idx = ((r & 4095) << 8) + threadIdx.x;
        isA = 0;
    }
    float x = src[idx];
    int row = idx >> 10, kk = idx & 1023;
    int blk = kk >> 5,  j  = kk & 31;
    __nv_bfloat16 hi = __float2bfloat16(x);
    __nv_bfloat16 lo = __float2bfloat16(x - __bfloat162float(hi));
    size_t base = (size_t)row * KS3 + blk*96 + j;
    dst[base]      = hi;
    dst[base + 32] = isA ? lo : hi;
    dst[base + 64] = isA ? hi : lo;
}

/* ================= GEMM mainloop core (R5) ================= */
#define GSTG 36864

__device__ __forceinline__ void gemm_core(
    const __nv_bfloat16* __restrict__ A, const __nv_bfloat16* __restrict__ B,
    char* gsm, int tid, int warp_m, int warp_n, int l,
    int m0, int n0, float acc[2][8][4])
{
    const uint32_t sb = smem_u32(gsm);
    const uint4* gA = (const uint4*)(A + (size_t)m0 * KS3);
    const uint4* gB = (const uint4*)(B + (size_t)n0 * KS3);

    uint32_t a_off[2], b_off[4];
#pragma unroll
    for (int mt = 0; mt < 2; mt++)
        a_off[mt] = (warp_m*32 + mt*16 + (l & 15))*144 + (l >> 4)*16;
#pragma unroll
    for (int nt = 0; nt < 4; nt++) {
        int row = warp_n*64 + nt*16 + (l & 7) + ((l >> 4) & 1) * 8;
        b_off[nt] = 18432 + row*144 + ((l >> 3) & 1)*16;
    }

    auto load_stage = [&](int stg, int it) {
        uint32_t base = sb + stg*GSTG;
#pragma unroll
        for (int u = 0; u < 4; u++) {
            int f = u*256 + tid;
            int r = f >> 3, c = f & 7;
            cp16(base + r*144 + c*16,         gA + (size_t)r*(KS3/8) + it*8 + c);
            cp16(base + 18432 + r*144 + c*16, gB + (size_t)r*(KS3/8) + it*8 + c);
        }
    };

    load_stage(0, 0);
    CP_COMMIT();

    for (int it = 0; it < KS3/64; it++) {
        int cur = it & 1;
        if (it + 1 < KS3/64) {
            load_stage(cur ^ 1, it + 1);
            CP_COMMIT();
            CP_WAIT(1);
        } else {
            CP_WAIT(0);
        }
        __syncthreads();

        uint32_t stgb = sb + cur*GSTG;
#pragma unroll
        for (int ks = 0; ks < 4; ks++) {
            uint32_t a[2][4], b[4][4];
#pragma unroll
            for (int mt = 0; mt < 2; mt++)
                ldsm4(a[mt][0], a[mt][1], a[mt][2], a[mt][3],
                      stgb + a_off[mt] + ks*32);
#pragma unroll
            for (int nt = 0; nt < 4; nt++)
                ldsm4(b[nt][0], b[nt][1], b[nt][2], b[nt][3],
                      stgb + b_off[nt] + ks*32);
#pragma unroll
            for (int mt = 0; mt < 2; mt++)
#pragma unroll
                for (int nt = 0; nt < 4; nt++) {
                    mma_bf16(acc[mt][nt*2],   a[mt], b[nt][0], b[nt][1]);
                    mma_bf16(acc[mt][nt*2+1], a[mt], b[nt][2], b[nt][3]);
                }
        }
        __syncthreads();
    }
}

/* ---- merged QKV projection GEMM: z = 0 (Q), 1 (K), 2 (V) ---- */
__global__ void __launch_bounds__(256, 2)
gemm_qkv(const float* __restrict__ bq, const float* __restrict__ bk,
         const float* __restrict__ bv)
{
    extern __shared__ __align__(16) char gsm[];

    const int tid = threadIdx.x;
    const int wid = tid >> 5, l = tid & 31;
    const int warp_m = wid >> 1, warp_n = wid & 1;
    const int m0 = blockIdx.y * 128;
    const int n0 = blockIdx.x * 128;
    const int z = blockIdx.z;

    const __nv_bfloat16* A = (z == 0) ? s_q  : (z == 1) ? s_k  : s_v;
    const __nv_bfloat16* B = (z == 0) ? s_wq : (z == 1) ? s_wk : s_wv;
    const float* bias      = (z == 0) ? bq   : (z == 1) ? bk   : bv;

    float acc[2][8][4];
#pragma unroll
    for (int i = 0; i < 2; i++)
#pragma unroll
        for (int j = 0; j < 8; j++)
#pragma unroll
            for (int p = 0; p < 4; p++) acc[i][j][p] = 0.f;

    gemm_core(A, B, gsm, tid, warp_m, warp_n, l, m0, n0, acc);

    const int g = l >> 2, q = l & 3;
#pragma unroll
    for (int mt = 0; mt < 2; mt++) {
        int mrow0 = m0 + warp_m*32 + mt*16 + g;
#pragma unroll
        for (int nt2 = 0; nt2 < 8; nt2++) {
            int ncol = n0 + warp_n*64 + nt2*8 + q*2;
            float b0 = bias[ncol], b1 = bias[ncol+1];
            float c0 = acc[mt][nt2][0] + b0;
            float c1 = acc[mt][nt2][1] + b1;
            float c2 = acc[mt][nt2][2] + b0;
            float c3 = acc[mt][nt2][3] + b1;

            int h = ncol >> 6, d = ncol & 63;
            int bb0 = mrow0 >> 11, ss0 = mrow0 & 2047;
            int mrow1 = mrow0 + 8;
            int bb1 = mrow1 >> 11, ss1 = mrow1 & 2047;
            if (z < 2) {       /* RoPE for Q and K */
                float cs0 = g_cos[ss0*32 + (d>>1)], sn0 = g_sin[ss0*32 + (d>>1)];
                float cs1 = g_cos[ss1*32 + (d>>1)], sn1 = g_sin[ss1*32 + (d>>1)];
                float t0 = c0*cs0 - c1*sn0, t1 = c0*sn0 + c1*cs0;
                float t2 = c2*cs1 - c3*sn1, t3 = c2*sn1 + c3*cs1;
                c0 = t0; c1 = t1; c2 = t2; c3 = t3;
            }
            size_t a0 = (((size_t)(bb0*NH + h)*SEQ + ss0) << 6) + d;
            size_t a1 = (((size_t)(bb1*NH + h)*SEQ + ss1) << 6) + d;
            if (z == 2) {      /* V: f16 hi + lo */
                __half h0 = __float2half_rn(c0);
                __half h1 = __float2half_rn(c1);
                __half h2 = __float2half_rn(c2);
                __half h3 = __float2half_rn(c3);
                *(__half2*)(g_Vh + a0) = __halves2half2(h0, h1);
                *(__half2*)(g_Vh + a1) = __halves2half2(h2, h3);
                *(__half2*)(g_Vl + a0) = __floats2half2_rn(
                    c0 - __half2float(h0), c1 - __half2float(h1));
                *(__half2*)(g_Vl + a1) = __floats2half2_rn(
                    c2 - __half2float(h2), c3 - __half2float(h3));
            } else {
                __nv_bfloat16* dhi = (z == 0) ? g_Qh : g_Kh;
                __nv_bfloat16* dlo = (z == 0) ? g_Ql : g_Kl;
                __nv_bfloat16 h0 = __float2bfloat16(c0);
                __nv_bfloat16 h1 = __float2bfloat16(c1);
                __nv_bfloat16 h2 = __float2bfloat16(c2);
                __nv_bfloat16 h3 = __float2bfloat16(c3);
                *(__nv_bfloat162*)(dhi + a0) = __halves2bfloat162(h0, h1);
                *(__nv_bfloat162*)(dhi + a1) = __halves2bfloat162(h2, h3);
                *(__nv_bfloat162*)(dlo + a0) = __floats2bfloat162_rn(
                    c0 - __bfloat162float(h0), c1 - __bfloat162float(h1));
                *(__nv_bfloat162*)(dlo + a1) = __floats2bfloat162_rn(
                    c2 - __bfloat162float(h2), c3 - __bfloat162float(h3));
            }
        }
    }
}

/* ---- output projection GEMM ---- */
__global__ void __launch_bounds__(256, 2)
gemm_out(const float* __restrict__ bo, float* __restrict__ dst)
{
    extern __shared__ __align__(16) char gsm[];

    const int tid = threadIdx.x;
    const int wid = tid >> 5, l = tid & 31;
    const int warp_m = wid >> 1, warp_n = wid & 1;
    const int m0 = blockIdx.y * 128;
    const int n0 = blockIdx.x * 128;

    float acc[2][8][4];
#pragma unroll
    for (int i = 0; i < 2; i++)
#pragma unroll
        for (int j = 0; j < 8; j++)
#pragma unroll
            for (int p = 0; p < 4; p++) acc[i][j][p] = 0.f;

    gemm_core(s_at, s_wo, gsm, tid, warp_m, warp_n, l, m0, n0, acc);

    const int g = l >> 2, q = l & 3;
#pragma unroll
    for (int mt = 0; mt < 2; mt++) {
        int mrow0 = m0 + warp_m*32 + mt*16 + g;
#pragma unroll
        for (int nt2 = 0; nt2 < 8; nt2++) {
            int ncol = n0 + warp_n*64 + nt2*8 + q*2;
            float b0 = bo[ncol], b1 = bo[ncol+1];
            *(float2*)(dst + (size_t)mrow0    *HID + ncol) =
                make_float2(acc[mt][nt2][0] + b0, acc[mt][nt2][1] + b1);
            *(float2*)(dst + (size_t)(mrow0+8)*HID + ncol) =
                make_float2(acc[mt][nt2][2] + b0, acc[mt][nt2][3] + b1);
        }
    }
}

/* ================= two-pass attention (R5) + f16 PV =================
   Pass 1: QK 3-term bf16 -> online row max/sum (registers only).
   Pass 2: QK recompute, w = exp2(s*c - m)/l -> fp32 gmem write;
           PV: w exact-f16 x V f16 hi/lo (2 mma).                     */
#define QSZ   36864
#define ASTG  36864
#define ASMEM (QSZ + 2*ASTG)

__global__ void __launch_bounds__(256, 2)
attn_mma(float* __restrict__ wout, int write_w)
{
    extern __shared__ __align__(16) char dsm[];
    const int tid = threadIdx.x;
    const int w = tid >> 5, l = tid & 31;
    const int g = l >> 2, q = l & 3;
    const int qt = (gridDim.x - 1) - blockIdx.x;    /* heavy tiles first */
    const int h = blockIdx.y, b = blockIdx.z;
    const int q0 = qt * 128;
    const size_t basebh = (size_t)(b*NH + h) * SEQ;
    const uint32_t sb = smem_u32(dsm);

    /* Q loads */
    {
        const uint4* gh = (const uint4*)(g_Qh + (basebh + q0) * HD);
        const uint4* gl = (const uint4*)(g_Ql + (basebh + q0) * HD);
#pragma unroll
        for (int u = 0; u < 4; u++) {
            int f = u*256 + tid;
            int r = f >> 3, c = f & 7;
            cp16(sb + r*144 + c*16,         gh + r*8 + c);
            cp16(sb + 18432 + r*144 + c*16, gl + r*8 + c);
        }
        CP_COMMIT();
    }

    const uint32_t aQh = sb + (w*16 + (l & 15))*144 + (l >> 4)*16;
    const uint32_t aQl = aQh + 18432;
    uint32_t bk_off[4];
    {
        int krow = (l & 7) + ((l >> 4) & 1) * 8;
        int kcb  = ((l >> 3) & 1) * 16;
#pragma unroll
        for (int nt = 0; nt < 4; nt++)
            bk_off[nt] = (nt*16 + krow)*144 + kcb;
    }
    const uint32_t av_off = 18432 + (l & 15)*144 + (l >> 4)*16;

    const float CE = 0.125f * LOG2E;
    const int nkt = 2*qt + 2;
    const int rw0 = q0 + w*16;
    const int r0 = rw0 + g, r1 = r0 + 8;

    auto loadK = [&](int stg, int kb) {
        uint32_t base = sb + QSZ + stg*ASTG;
        const uint4* gkh = (const uint4*)(g_Kh + (basebh + kb*64) * HD);
        const uint4* gkl = (const uint4*)(g_Kl + (basebh + kb*64) * HD);
#pragma unroll
        for (int u = 0; u < 2; u++) {
            int f = u*256 + tid;
            int r = f >> 3, c = f & 7;
            cp16(base + r*144 + c*16,        gkh + r*8 + c);
            cp16(base + 9216 + r*144 + c*16, gkl + r*8 + c);
        }
    };
    auto loadKV = [&](int stg, int kb) {
        uint32_t base = sb + QSZ + stg*ASTG;
        const uint4* gkh = (const uint4*)(g_Kh + (basebh + kb*64) * HD);
        const uint4* gkl = (const uint4*)(g_Kl + (basebh + kb*64) * HD);
        const uint4* gvh = (const uint4*)(g_Vh + (basebh + kb*64) * HD);
        const uint4* gvl = (const uint4*)(g_Vl + (basebh + kb*64) * HD);
#pragma unroll
        for (int u = 0; u < 2; u++) {
            int f = u*256 + tid;
            int r = f >> 3, c = f & 7;
            cp16(base + r*144 + c*16,         gkh + r*8 + c);
            cp16(base + 9216  + r*144 + c*16, gkl + r*8 + c);
            cp16(base + 18432 + r*144 + c*16, gvh + r*8 + c);
            cp16(base + 27648 + r*144 + c*16, gvl + r*8 + c);
        }
    };

    /* QK: 3-term bf16 split */
    auto qk_tile = [&](uint32_t kbase, float acc[8][4]) {
#pragma unroll
        for (int nt = 0; nt < 8; nt++)
#pragma unroll
            for (int p = 0; p < 4; p++) acc[nt][p] = 0.f;
#pragma unroll
        for (int ks = 0; ks < 4; ks++) {
            uint32_t ah[4], al[4];
            ldsm4(ah[0], ah[1], ah[2], ah[3], aQh + ks*32);
            ldsm4(al[0], al[1], al[2], al[3], aQl + ks*32);
#pragma unroll
            for (int np = 0; np < 4; np++) {
                uint32_t kh[4], kl[4];
                ldsm4(kh[0], kh[1], kh[2], kh[3], kbase + bk_off[np] + ks*32);
                ldsm4(kl[0], kl[1], kl[2], kl[3], kbase + 9216 + bk_off[np] + ks*32);
                mma_bf16(acc[np*2],   ah, kh[0], kh[1]);
                mma_bf16(acc[np*2+1], ah, kh[2], kh[3]);
                mma_bf16(acc[np*2],   al, kh[0], kh[1]);
                mma_bf16(acc[np*2+1], al, kh[2], kh[3]);
                mma_bf16(acc[np*2],   ah, kl[0], kl[1]);
                mma_bf16(acc[np*2+1], ah, kl[2], kl[3]);
            }
        }
    };

    float m2[2] = {-1e30f, -1e30f};
    float l2[2] = {0.f, 0.f};

    /* ---------------- PASS 1: row max & sum ---------------- */
    loadK(0, 0);
    CP_COMMIT();

    for (int kb = 0; kb < nkt; kb++) {
        int cur = kb & 1;
        if (kb + 1 < nkt) {
            loadK(cur ^ 1, kb + 1);
            CP_COMMIT();
            CP_WAIT(1);
        } else {
            CP_WAIT(0);
        }
        __syncthreads();

        float acc[8][4];
        qk_tile(sb + QSZ + cur*ASTG, acc);
        __syncthreads();

        const bool needmask = (kb*64 + 63) > rw0;
#pragma unroll
        for (int nt = 0; nt < 8; nt++) {
            int k0c = kb*64 + nt*8 + q*2;
            acc[nt][0] = (!needmask || k0c   <= r0) ? acc[nt][0]*CE : -1e30f;
            acc[nt][1] = (!needmask || k0c+1 <= r0) ? acc[nt][1]*CE : -1e30f;
            acc[nt][2] = (!needmask || k0c   <= r1) ? acc[nt][2]*CE : -1e30f;
            acc[nt][3] = (!needmask || k0c+1 <= r1) ? acc[nt][3]*CE : -1e30f;
        }
        float tm0 = -1e30f, tm1 = -1e30f;
#pragma unroll
        for (int nt = 0; nt < 8; nt++) {
            tm0 = fmaxf(tm0, fmaxf(acc[nt][0], acc[nt][1]));
            tm1 = fmaxf(tm1, fmaxf(acc[nt][2], acc[nt][3]));
        }
        tm0 = fmaxf(tm0, __shfl_xor_sync(0xffffffffu, tm0, 1));
        tm0 = fmaxf(tm0, __shfl_xor_sync(0xffffffffu, tm0, 2));
        tm1 = fmaxf(tm1, __shfl_xor_sync(0xffffffffu, tm1, 1));
        tm1 = fmaxf(tm1, __shfl_xor_sync(0xffffffffu, tm1, 2));
        float mn0 = fmaxf(m2[0], tm0), mn1 = fmaxf(m2[1], tm1);
        float s0 = 0.f, s1 = 0.f;
#pragma unroll
        for (int nt = 0; nt < 8; nt++) {
            s0 += ex2(acc[nt][0] - mn0) + ex2(acc[nt][1] - mn0);
            s1 += ex2(acc[nt][2] - mn1) + ex2(acc[nt][3] - mn1);
        }
        s0 += __shfl_xor_sync(0xffffffffu, s0, 1);
        s0 += __shfl_xor_sync(0xffffffffu, s0, 2);
        s1 += __shfl_xor_sync(0xffffffffu, s1, 1);
        s1 += __shfl_xor_sync(0xffffffffu, s1, 2);
        l2[0] = l2[0] * ex2(m2[0] - mn0) + s0;  m2[0] = mn0;
        l2[1] = l2[1] * ex2(m2[1] - mn1) + s1;  m2[1] = mn1;
    }

    const float invl0 = 1.f / l2[0];
    const float invl1 = 1.f / l2[1];

    float o[8][4];
#pragma unroll
    for (int nd = 0; nd < 8; nd++)
#pragma unroll
        for (int p = 0; p < 4; p++) o[nd][p] = 0.f;

    /* ---------------- PASS 2: weights + O ---------------- */
    loadKV(0, 0);
    CP_COMMIT();

    for (int kb = 0; kb < nkt; kb++) {
        int cur = kb & 1;
        if (kb + 1 < nkt) {
            loadKV(cur ^ 1, kb + 1);
            CP_COMMIT();
            CP_WAIT(1);
        } else {
            CP_WAIT(0);
        }
        __syncthreads();

        uint32_t kbase = sb + QSZ + cur*ASTG;
        float acc[8][4];
        qk_tile(kbase, acc);

        const bool needmask = (kb*64 + 63) > rw0;
        uint32_t ew0[8], ew1[8];
#pragma unroll
        for (int nt = 0; nt < 8; nt++) {
            int k0c = kb*64 + nt*8 + q*2;
            float w0 = (!needmask || k0c   <= r0)
                       ? ex2(acc[nt][0]*CE - m2[0]) * invl0 : 0.f;
            float w1 = (!needmask || k0c+1 <= r0)
                       ? ex2(acc[nt][1]*CE - m2[0]) * invl0 : 0.f;
            float w2 = (!needmask || k0c   <= r1)
                       ? ex2(acc[nt][2]*CE - m2[1]) * invl1 : 0.f;
            float w3 = (!needmask || k0c+1 <= r1)
                       ? ex2(acc[nt][3]*CE - m2[1]) * invl1 : 0.f;
            ew0[nt] = pack_h2(w0, w1);
            ew1[nt] = pack_h2(w2, w3);
            if (write_w) {
                __stcs((float2*)(wout + (basebh + r0)*SEQ + k0c), make_float2(w0, w1));
                __stcs((float2*)(wout + (basebh + r1)*SEQ + k0c), make_float2(w2, w3));
            }
        }

        /* PV: w exact-f16 x V f16 hi/lo (2 mma per pair) */
#pragma unroll
        for (int t = 0; t < 4; t++) {
            uint32_t aw[4] = {ew0[2*t], ew1[2*t], ew0[2*t+1], ew1[2*t+1]};
#pragma unroll
            for (int nd = 0; nd < 4; nd++) {
                uint32_t vh[4], vl[4];
                ldsm4t(vh[0], vh[1], vh[2], vh[3],
                       kbase + av_off + t*2304 + nd*32);
                ldsm4t(vl[0], vl[1], vl[2], vl[3],
                       kbase + av_off + 9216 + t*2304 + nd*32);
                mma_f16(o[nd*2],   aw, vh[0], vh[1]);
                mma_f16(o[nd*2+1], aw, vh[2], vh[3]);
                mma_f16(o[nd*2],   aw, vl[0], vl[1]);
                mma_f16(o[nd*2+1], aw, vl[2], vl[3]);
            }
        }
        __syncthreads();
    }

    /* zero-fill masked (upper-triangle) region */
    if (write_w) {
        int kend = q0 + 128;
        int rem = SEQ - kend;
        if (rem > 0) {
            float4 z4 = make_float4(0.f, 0.f, 0.f, 0.f);
            for (int r = tid >> 5; r < 128; r += 8) {
                float* rowp = wout + (basebh + q0 + r)*SEQ + kend;
                for (int cc = (tid & 31)*4; cc < rem; cc += 128)
                    __stcs((float4*)(rowp + cc), z4);
            }
        }
    }

    /* write O in split-A format for the out-projection */
    {
        size_t mg0 = (size_t)b*SEQ + q0 + w*16 + g;
        size_t mg1 = mg0 + 8;
#pragma unroll
        for (int nd = 0; nd < 8; nd++) {
            int col = h*64 + nd*8 + q*2;
            int blk = col >> 5, j = col & 31;
            size_t b0 = mg0*KS3 + blk*96 + j;
            size_t b1 = mg1*KS3 + blk*96 + j;
            float c0 = o[nd][0], c1 = o[nd][1];
            float c2 = o[nd][2], c3 = o[nd][3];
            __nv_bfloat16 h0 = __float2bfloat16(c0);
            __nv_bfloat16 h1 = __float2bfloat16(c1);
            __nv_bfloat16 h2 = __float2bfloat16(c2);
            __nv_bfloat16 h3 = __float2bfloat16(c3);
            __nv_bfloat162 hi0 = __halves2bfloat162(h0, h1);
            __nv_bfloat162 hi1 = __halves2bfloat162(h2, h3);
            __nv_bfloat162 lo0 = __floats2bfloat162_rn(
                c0 - __bfloat162float(h0), c1 - __bfloat162float(h1));
            __nv_bfloat162 lo1 = __floats2bfloat162_rn(
                c2 - __bfloat162float(h2), c3 - __bfloat162float(h3));
            *(__nv_bfloat162*)(s_at + b0)      = hi0;
            *(__nv_bfloat162*)(s_at + b0 + 32) = lo0;
            *(__nv_bfloat162*)(s_at + b0 + 64) = hi0;
            *(__nv_bfloat162*)(s_at + b1)      = hi1;
            *(__nv_bfloat162*)(s_at + b1 + 32) = lo1;
            *(__nv_bfloat162*)(s_at + b1 + 64) = hi1;
        }
    }
}

/* ---------------- launcher ---------------- */
extern "C" void kernel_launch(void* const* d_in, const int* in_sizes, int n_in,
                              void* d_out, int out_size)
{
    const float* q  = (const float*)d_in[0];
    const float* k  = (const float*)d_in[1];
    const float* v  = (const float*)d_in[2];
    const float* bq = (const float*)d_in[4];
    const float* bk = (const float*)d_in[6];
    const float* bv = (const float*)d_in[8];
    const float* Wq = (const float*)d_in[3];
    const float* Wk = (const float*)d_in[5];
    const float* Wv = (const float*)d_in[7];
    const float* Wo = (const float*)d_in[9];
    const float* bo = (const float*)d_in[10];

    float* out  = (float*)d_out;
    int write_w = (out_size >= OUT_ELEMS + W_ELEMS) ? 1 : 0;
    float* wout = out + OUT_ELEMS;

    rope_table_kernel<<<(SEQ*32 + 255)/256, 256>>>();

    split_all<<<65536, 256>>>(q, k, v, Wq, Wk, Wv, Wo);

    cudaFuncSetAttribute(gemm_qkv,
                         cudaFuncAttributeMaxDynamicSharedMemorySize, 2*GSTG);
    cudaFuncSetAttribute(gemm_out,
                         cudaFuncAttributeMaxDynamicSharedMemorySize, 2*GSTG);
    cudaFuncSetAttribute(attn_mma,
                         cudaFuncAttributeMaxDynamicSharedMemorySize, ASMEM);

    gemm_qkv<<<dim3(HID/128, MTOT/128, 3), 256, 2*GSTG>>>(bq, bk, bv);

    attn_mma<<<dim3(SEQ/128, NH, BATCH), 256, ASMEM>>>(wout, write_w);

    gemm_out<<<dim3(HID/128, MTOT/128), 256, 2*GSTG>>>(bo, out);
}

// round 10
// speedup vs baseline: 1.3500x; 1.0692x over previous
#include <cuda_runtime.h>
#include <cuda_bf16.h>
#include <cuda_fp16.h>
#include <math.h>
#include <stdint.h>

#define BATCH 2
#define SEQ   2048
#define HID   1024
#define NH    16
#define HD    64
#define MTOT  (BATCH*SEQ)
#define OUT_ELEMS   (MTOT*HID)
#define W_ELEMS     (BATCH*NH*SEQ*SEQ)
#define KS3   3072               /* split-K: [hi | lo | hi] x 1024 */
#define LOG2E 1.44269504088896340736f

/* ---------------- scratch (no allocations allowed) ---------------- */
__device__ float g_cos[SEQ*(HD/2)];
__device__ float g_sin[SEQ*(HD/2)];

__device__ __nv_bfloat16 g_Qh[BATCH*NH*SEQ*HD];
__device__ __nv_bfloat16 g_Ql[BATCH*NH*SEQ*HD];
__device__ __nv_bfloat16 g_Kh[BATCH*NH*SEQ*HD];
__device__ __nv_bfloat16 g_Kl[BATCH*NH*SEQ*HD];
__device__ __half        g_Vh[BATCH*NH*SEQ*HD];
__device__ __half        g_Vl[BATCH*NH*SEQ*HD];

__device__ __nv_bfloat16 s_q [MTOT*KS3];
__device__ __nv_bfloat16 s_k [MTOT*KS3];
__device__ __nv_bfloat16 s_v [MTOT*KS3];
__device__ __nv_bfloat16 s_at[MTOT*KS3];
__device__ __nv_bfloat16 s_wq[HID*KS3];
__device__ __nv_bfloat16 s_wk[HID*KS3];
__device__ __nv_bfloat16 s_wv[HID*KS3];
__device__ __nv_bfloat16 s_wo[HID*KS3];

/* ---------------- helpers ---------------- */
__device__ __forceinline__ uint32_t smem_u32(const void* p) {
    uint32_t a;
    asm("{ .reg .u64 t; cvta.to.shared.u64 t, %1; cvt.u32.u64 %0, t; }"
        : "=r"(a) : "l"(p));
    return a;
}
__device__ __forceinline__ void cp16(uint32_t s, const void* g) {
    asm volatile("cp.async.cg.shared.global [%0], [%1], 16;"
                 :: "r"(s), "l"(g));
}
#define CP_COMMIT() asm volatile("cp.async.commit_group;" ::: "memory")
#define CP_WAIT(N)  asm volatile("cp.async.wait_group %0;" :: "n"(N) : "memory")

__device__ __forceinline__ void ldsm4(uint32_t& r0, uint32_t& r1,
                                      uint32_t& r2, uint32_t& r3, uint32_t addr)
{
    asm volatile("ldmatrix.sync.aligned.m8n8.x4.shared.b16 {%0,%1,%2,%3}, [%4];"
                 : "=r"(r0), "=r"(r1), "=r"(r2), "=r"(r3) : "r"(addr));
}
__device__ __forceinline__ void ldsm4t(uint32_t& r0, uint32_t& r1,
                                       uint32_t& r2, uint32_t& r3, uint32_t addr)
{
    asm volatile("ldmatrix.sync.aligned.m8n8.x4.trans.shared.b16 {%0,%1,%2,%3}, [%4];"
                 : "=r"(r0), "=r"(r1), "=r"(r2), "=r"(r3) : "r"(addr));
}
__device__ __forceinline__ void mma_bf16(float* d, const uint32_t* a,
                                         uint32_t b0, uint32_t b1)
{
    asm volatile(
        "mma.sync.aligned.m16n8k16.row.col.f32.bf16.bf16.f32 "
        "{%0,%1,%2,%3}, {%4,%5,%6,%7}, {%8,%9}, {%0,%1,%2,%3};"
        : "+f"(d[0]), "+f"(d[1]), "+f"(d[2]), "+f"(d[3])
        : "r"(a[0]), "r"(a[1]), "r"(a[2]), "r"(a[3]), "r"(b0), "r"(b1));
}
__device__ __forceinline__ void mma_f16(float* d, const uint32_t* a,
                                        uint32_t b0, uint32_t b1)
{
    asm volatile(
        "mma.sync.aligned.m16n8k16.row.col.f32.f16.f16.f32 "
        "{%0,%1,%2,%3}, {%4,%5,%6,%7}, {%8,%9}, {%0,%1,%2,%3};"
        : "+f"(d[0]), "+f"(d[1]), "+f"(d[2]), "+f"(d[3])
        : "r"(a[0]), "r"(a[1]), "r"(a[2]), "r"(a[3]), "r"(b0), "r"(b1));
}
__device__ __forceinline__ float ex2(float x) {
    float y;
    asm("ex2.approx.ftz.f32 %0, %1;" : "=f"(y) : "f"(x));
    return y;
}
__device__ __forceinline__ uint32_t pack_h2(float x, float y) {
    __half2 t = __floats2half2_rn(x, y);
    return *(uint32_t*)&t;
}

/* ---------------- RoPE tables ---------------- */
__global__ void rope_table_kernel() {
    int idx = blockIdx.x * blockDim.x + threadIdx.x;
    if (idx >= SEQ * (HD/2)) return;
    int s = idx >> 5;
    int j = idx & 31;
    double inv = exp(-((double)(2*j) / (double)HD) * log(10000.0));
    double ang = (double)s * inv;
    g_cos[idx] = (float)cos(ang);
    g_sin[idx] = (float)sin(ang);
}

/* -------- merged fp32 -> bf16 split (all 7 tensors, 1 launch) ----- */
__global__ void __launch_bounds__(256)
split_all(const float* __restrict__ q, const float* __restrict__ k,
          const float* __restrict__ v, const float* __restrict__ Wq,
          const float* __restrict__ Wk, const float* __restrict__ Wv,
          const float* __restrict__ Wo)
{
    int bid = blockIdx.x;
    const float* src;
    __nv_bfloat16* dst;
    int idx, isA;
    if (bid < 49152) {                 /* inputs: 3 x 16384 blocks */
        int t = bid >> 14;
        src = (t == 0) ? q : (t == 1) ? k : v;
        dst = (t == 0) ? s_q : (t == 1) ? s_k : s_v;
        idx = ((bid & 16383) << 8) + threadIdx.x;
        isA = 1;
    } else {                           /* weights: 4 x 4096 blocks */
        int r = bid - 49152;
        int t = r >> 12;
        src = (t == 0) ? Wq : (t == 1) ? Wk : (t == 2) ? Wv : Wo;
        dst = (t == 0) ? s_wq : (t == 1) ? s_wk : (t == 2) ? s_wv : s_wo;
        idx = ((r & 4095) << 8) + threadIdx.x;
        isA = 0;
    }
    float x = src[idx];
    int row = idx >> 10, kk = idx & 1023;
    int blk = kk >> 5,  j  = kk & 31;
    __nv_bfloat16 hi = __float2bfloat16(x);
    __nv_bfloat16 lo = __float2bfloat16(x - __bfloat162float(hi));
    size_t base = (size_t)row * KS3 + blk*96 + j;
    dst[base]      = hi;
    dst[base + 32] = isA ? lo : hi;
    dst[base + 64] = isA ? hi : lo;
}

/* ================= GEMM mainloop core ================= */
#define GSTG 36864

__device__ __forceinline__ void gemm_core(
    const __nv_bfloat16* __restrict__ A, const __nv_bfloat16* __restrict__ B,
    char* gsm, int tid, int warp_m, int warp_n, int l,
    int m0, int n0, float acc[2][8][4])
{
    const uint32_t sb = smem_u32(gsm);
    const uint4* gA = (const uint4*)(A + (size_t)m0 * KS3);
    const uint4* gB = (const uint4*)(B + (size_t)n0 * KS3);

    uint32_t a_off[2], b_off[4];
#pragma unroll
    for (int mt = 0; mt < 2; mt++)
        a_off[mt] = (warp_m*32 + mt*16 + (l & 15))*144 + (l >> 4)*16;
#pragma unroll
    for (int nt = 0; nt < 4; nt++) {
        int row = warp_n*64 + nt*16 + (l & 7) + ((l >> 4) & 1) * 8;
        b_off[nt] = 18432 + row*144 + ((l >> 3) & 1)*16;
    }

    auto load_stage = [&](int stg, int it) {
        uint32_t base = sb + stg*GSTG;
#pragma unroll
        for (int u = 0; u < 4; u++) {
            int f = u*256 + tid;
            int r = f >> 3, c = f & 7;
            cp16(base + r*144 + c*16,         gA + (size_t)r*(KS3/8) + it*8 + c);
            cp16(base + 18432 + r*144 + c*16, gB + (size_t)r*(KS3/8) + it*8 + c);
        }
    };

    load_stage(0, 0);
    CP_COMMIT();

    for (int it = 0; it < KS3/64; it++) {
        int cur = it & 1;
        if (it + 1 < KS3/64) {
            load_stage(cur ^ 1, it + 1);
            CP_COMMIT();
            CP_WAIT(1);
        } else {
            CP_WAIT(0);
        }
        __syncthreads();

        uint32_t stgb = sb + cur*GSTG;
#pragma unroll
        for (int ks = 0; ks < 4; ks++) {
            uint32_t a[2][4], b[4][4];
#pragma unroll
            for (int mt = 0; mt < 2; mt++)
                ldsm4(a[mt][0], a[mt][1], a[mt][2], a[mt][3],
                      stgb + a_off[mt] + ks*32);
#pragma unroll
            for (int nt = 0; nt < 4; nt++)
                ldsm4(b[nt][0], b[nt][1], b[nt][2], b[nt][3],
                      stgb + b_off[nt] + ks*32);
#pragma unroll
            for (int mt = 0; mt < 2; mt++)
#pragma unroll
                for (int nt = 0; nt < 4; nt++) {
                    mma_bf16(acc[mt][nt*2],   a[mt], b[nt][0], b[nt][1]);
                    mma_bf16(acc[mt][nt*2+1], a[mt], b[nt][2], b[nt][3]);
                }
        }
        __syncthreads();
    }
}

/* ---- merged QKV projection GEMM: z = 0 (Q), 1 (K), 2 (V) ---- */
__global__ void __launch_bounds__(256, 2)
gemm_qkv(const float* __restrict__ bq, const float* __restrict__ bk,
         const float* __restrict__ bv)
{
    extern __shared__ __align__(16) char gsm[];

    const int tid = threadIdx.x;
    const int wid = tid >> 5, l = tid & 31;
    const int warp_m = wid >> 1, warp_n = wid & 1;
    const int m0 = blockIdx.y * 128;
    const int n0 = blockIdx.x * 128;
    const int z = blockIdx.z;

    const __nv_bfloat16* A = (z == 0) ? s_q  : (z == 1) ? s_k  : s_v;
    const __nv_bfloat16* B = (z == 0) ? s_wq : (z == 1) ? s_wk : s_wv;
    const float* bias      = (z == 0) ? bq   : (z == 1) ? bk   : bv;

    float acc[2][8][4];
#pragma unroll
    for (int i = 0; i < 2; i++)
#pragma unroll
        for (int j = 0; j < 8; j++)
#pragma unroll
            for (int p = 0; p < 4; p++) acc[i][j][p] = 0.f;

    gemm_core(A, B, gsm, tid, warp_m, warp_n, l, m0, n0, acc);

    const int g = l >> 2, q = l & 3;
#pragma unroll
    for (int mt = 0; mt < 2; mt++) {
        int mrow0 = m0 + warp_m*32 + mt*16 + g;
#pragma unroll
        for (int nt2 = 0; nt2 < 8; nt2++) {
            int ncol = n0 + warp_n*64 + nt2*8 + q*2;
            float b0 = bias[ncol], b1 = bias[ncol+1];
            float c0 = acc[mt][nt2][0] + b0;
            float c1 = acc[mt][nt2][1] + b1;
            float c2 = acc[mt][nt2][2] + b0;
            float c3 = acc[mt][nt2][3] + b1;

            int h = ncol >> 6, d = ncol & 63;
            int bb0 = mrow0 >> 11, ss0 = mrow0 & 2047;
            int mrow1 = mrow0 + 8;
            int bb1 = mrow1 >> 11, ss1 = mrow1 & 2047;
            if (z < 2) {
                float cs0 = g_cos[ss0*32 + (d>>1)], sn0 = g_sin[ss0*32 + (d>>1)];
                float cs1 = g_cos[ss1*32 + (d>>1)], sn1 = g_sin[ss1*32 + (d>>1)];
                float t0 = c0*cs0 - c1*sn0, t1 = c0*sn0 + c1*cs0;
                float t2 = c2*cs1 - c3*sn1, t3 = c2*sn1 + c3*cs1;
                c0 = t0; c1 = t1; c2 = t2; c3 = t3;
            }
            size_t a0 = (((size_t)(bb0*NH + h)*SEQ + ss0) << 6) + d;
            size_t a1 = (((size_t)(bb1*NH + h)*SEQ + ss1) << 6) + d;
            if (z == 2) {
                __half h0 = __float2half_rn(c0);
                __half h1 = __float2half_rn(c1);
                __half h2 = __float2half_rn(c2);
                __half h3 = __float2half_rn(c3);
                *(__half2*)(g_Vh + a0) = __halves2half2(h0, h1);
                *(__half2*)(g_Vh + a1) = __halves2half2(h2, h3);
                *(__half2*)(g_Vl + a0) = __floats2half2_rn(
                    c0 - __half2float(h0), c1 - __half2float(h1));
                *(__half2*)(g_Vl + a1) = __floats2half2_rn(
                    c2 - __half2float(h2), c3 - __half2float(h3));
            } else {
                __nv_bfloat16* dhi = (z == 0) ? g_Qh : g_Kh;
                __nv_bfloat16* dlo = (z == 0) ? g_Ql : g_Kl;
                __nv_bfloat16 h0 = __float2bfloat16(c0);
                __nv_bfloat16 h1 = __float2bfloat16(c1);
                __nv_bfloat16 h2 = __float2bfloat16(c2);
                __nv_bfloat16 h3 = __float2bfloat16(c3);
                *(__nv_bfloat162*)(dhi + a0) = __halves2bfloat162(h0, h1);
                *(__nv_bfloat162*)(dhi + a1) = __halves2bfloat162(h2, h3);
                *(__nv_bfloat162*)(dlo + a0) = __floats2bfloat162_rn(
                    c0 - __bfloat162float(h0), c1 - __bfloat162float(h1));
                *(__nv_bfloat162*)(dlo + a1) = __floats2bfloat162_rn(
                    c2 - __bfloat162float(h2), c3 - __bfloat162float(h3));
            }
        }
    }
}

/* ---- output projection GEMM ---- */
__global__ void __launch_bounds__(256, 2)
gemm_out(const float* __restrict__ bo, float* __restrict__ dst)
{
    extern __shared__ __align__(16) char gsm[];

    const int tid = threadIdx.x;
    const int wid = tid >> 5, l = tid & 31;
    const int warp_m = wid >> 1, warp_n = wid & 1;
    const int m0 = blockIdx.y * 128;
    const int n0 = blockIdx.x * 128;

    float acc[2][8][4];
#pragma unroll
    for (int i = 0; i < 2; i++)
#pragma unroll
        for (int j = 0; j < 8; j++)
#pragma unroll
            for (int p = 0; p < 4; p++) acc[i][j][p] = 0.f;

    gemm_core(s_at, s_wo, gsm, tid, warp_m, warp_n, l, m0, n0, acc);

    const int g = l >> 2, q = l & 3;
#pragma unroll
    for (int mt = 0; mt < 2; mt++) {
        int mrow0 = m0 + warp_m*32 + mt*16 + g;
#pragma unroll
        for (int nt2 = 0; nt2 < 8; nt2++) {
            int ncol = n0 + warp_n*64 + nt2*8 + q*2;
            float b0 = bo[ncol], b1 = bo[ncol+1];
            *(float2*)(dst + (size_t)mrow0    *HID + ncol) =
                make_float2(acc[mt][nt2][0] + b0, acc[mt][nt2][1] + b1);
            *(float2*)(dst + (size_t)(mrow0+8)*HID + ncol) =
                make_float2(acc[mt][nt2][2] + b0, acc[mt][nt2][3] + b1);
        }
    }
}

/* ================= two-pass attention, causal-paired =================
   Grid (8, NH, BATCH) = 256 CTAs, one balanced wave. CTA bx handles
   q-tiles (15 - bx) and (bx): combined k-tile count = 34, constant.   */
#define QSZ   36864
#define ASTG  36864
#define ASMEM (QSZ + 2*ASTG)

__global__ void __launch_bounds__(256, 2)
attn_mma(float* __restrict__ wout, int write_w)
{
    extern __shared__ __align__(16) char dsm[];
    const int tid = threadIdx.x;
    const int w = tid >> 5, l = tid & 31;
    const int g = l >> 2, q = l & 3;
    const int h = blockIdx.y, b = blockIdx.z;
    const size_t basebh = (size_t)(b*NH + h) * SEQ;
    const uint32_t sb = smem_u32(dsm);
    const float CE = 0.125f * LOG2E;

    uint32_t bk_off[4];
    {
        int krow = (l & 7) + ((l >> 4) & 1) * 8;
        int kcb  = ((l >> 3) & 1) * 16;
#pragma unroll
        for (int nt = 0; nt < 4; nt++)
            bk_off[nt] = (nt*16 + krow)*144 + kcb;
    }
    const uint32_t aQh = sb + (w*16 + (l & 15))*144 + (l >> 4)*16;
    const uint32_t aQl = aQh + 18432;
    const uint32_t av_off = 18432 + (l & 15)*144 + (l >> 4)*16;

    auto loadK = [&](int stg, int kb) {
        uint32_t base = sb + QSZ + stg*ASTG;
        const uint4* gkh = (const uint4*)(g_Kh + (basebh + kb*64) * HD);
        const uint4* gkl = (const uint4*)(g_Kl + (basebh + kb*64) * HD);
#pragma unroll
        for (int u = 0; u < 2; u++) {
            int f = u*256 + tid;
            int r = f >> 3, c = f & 7;
            cp16(base + r*144 + c*16,        gkh + r*8 + c);
            cp16(base + 9216 + r*144 + c*16, gkl + r*8 + c);
        }
    };
    auto loadKV = [&](int stg, int kb) {
        uint32_t base = sb + QSZ + stg*ASTG;
        const uint4* gkh = (const uint4*)(g_Kh + (basebh + kb*64) * HD);
        const uint4* gkl = (const uint4*)(g_Kl + (basebh + kb*64) * HD);
        const uint4* gvh = (const uint4*)(g_Vh + (basebh + kb*64) * HD);
        const uint4* gvl = (const uint4*)(g_Vl + (basebh + kb*64) * HD);
#pragma unroll
        for (int u = 0; u < 2; u++) {
            int f = u*256 + tid;
            int r = f >> 3, c = f & 7;
            cp16(base + r*144 + c*16,         gkh + r*8 + c);
            cp16(base + 9216  + r*144 + c*16, gkl + r*8 + c);
            cp16(base + 18432 + r*144 + c*16, gvh + r*8 + c);
            cp16(base + 27648 + r*144 + c*16, gvl + r*8 + c);
        }
    };

    /* QK: 3-term bf16 split */
    auto qk_tile = [&](uint32_t kbase, float acc[8][4]) {
#pragma unroll
        for (int nt = 0; nt < 8; nt++)
#pragma unroll
            for (int p = 0; p < 4; p++) acc[nt][p] = 0.f;
#pragma unroll
        for (int ks = 0; ks < 4; ks++) {
            uint32_t ah[4], al[4];
            ldsm4(ah[0], ah[1], ah[2], ah[3], aQh + ks*32);
            ldsm4(al[0], al[1], al[2], al[3], aQl + ks*32);
#pragma unroll
            for (int np = 0; np < 4; np++) {
                uint32_t kh[4], kl[4];
                ldsm4(kh[0], kh[1], kh[2], kh[3], kbase + bk_off[np] + ks*32);
                ldsm4(kl[0], kl[1], kl[2], kl[3], kbase + 9216 + bk_off[np] + ks*32);
                mma_bf16(acc[np*2],   ah, kh[0], kh[1]);
                mma_bf16(acc[np*2+1], ah, kh[2], kh[3]);
                mma_bf16(acc[np*2],   al, kh[0], kh[1]);
                mma_bf16(acc[np*2+1], al, kh[2], kh[3]);
                mma_bf16(acc[np*2],   ah, kl[0], kl[1]);
                mma_bf16(acc[np*2+1], ah, kl[2], kl[3]);
            }
        }
    };

    for (int half = 0; half < 2; half++) {
        const int qt = half ? blockIdx.x : (15 - blockIdx.x);
        const int q0 = qt * 128;
        const int nkt = 2*qt + 2;
        const int rw0 = q0 + w*16;
        const int r0 = rw0 + g, r1 = r0 + 8;

        /* Q loads */
        {
            const uint4* gh = (const uint4*)(g_Qh + (basebh + q0) * HD);
            const uint4* gl = (const uint4*)(g_Ql + (basebh + q0) * HD);
#pragma unroll
            for (int u = 0; u < 4; u++) {
                int f = u*256 + tid;
                int r = f >> 3, c = f & 7;
                cp16(sb + r*144 + c*16,         gh + r*8 + c);
                cp16(sb + 18432 + r*144 + c*16, gl + r*8 + c);
            }
            CP_COMMIT();
        }

        float m2[2] = {-1e30f, -1e30f};
        float l2[2] = {0.f, 0.f};

        /* ---------------- PASS 1: row max & sum ---------------- */
        loadK(0, 0);
        CP_COMMIT();

        for (int kb = 0; kb < nkt; kb++) {
            int cur = kb & 1;
            if (kb + 1 < nkt) {
                loadK(cur ^ 1, kb + 1);
                CP_COMMIT();
                CP_WAIT(1);
            } else {
                CP_WAIT(0);
            }
            __syncthreads();

            float acc[8][4];
            qk_tile(sb + QSZ + cur*ASTG, acc);
            __syncthreads();

            const bool needmask = (kb*64 + 63) > rw0;
#pragma unroll
            for (int nt = 0; nt < 8; nt++) {
                int k0c = kb*64 + nt*8 + q*2;
                acc[nt][0] = (!needmask || k0c   <= r0) ? acc[nt][0]*CE : -1e30f;
                acc[nt][1] = (!needmask || k0c+1 <= r0) ? acc[nt][1]*CE : -1e30f;
                acc[nt][2] = (!needmask || k0c   <= r1) ? acc[nt][2]*CE : -1e30f;
                acc[nt][3] = (!needmask || k0c+1 <= r1) ? acc[nt][3]*CE : -1e30f;
            }
            float tm0 = -1e30f, tm1 = -1e30f;
#pragma unroll
            for (int nt = 0; nt < 8; nt++) {
                tm0 = fmaxf(tm0, fmaxf(acc[nt][0], acc[nt][1]));
                tm1 = fmaxf(tm1, fmaxf(acc[nt][2], acc[nt][3]));
            }
            tm0 = fmaxf(tm0, __shfl_xor_sync(0xffffffffu, tm0, 1));
            tm0 = fmaxf(tm0, __shfl_xor_sync(0xffffffffu, tm0, 2));
            tm1 = fmaxf(tm1, __shfl_xor_sync(0xffffffffu, tm1, 1));
            tm1 = fmaxf(tm1, __shfl_xor_sync(0xffffffffu, tm1, 2));
            float mn0 = fmaxf(m2[0], tm0), mn1 = fmaxf(m2[1], tm1);
            float s0 = 0.f, s1 = 0.f;
#pragma unroll
            for (int nt = 0; nt < 8; nt++) {
                s0 += ex2(acc[nt][0] - mn0) + ex2(acc[nt][1] - mn0);
                s1 += ex2(acc[nt][2] - mn1) + ex2(acc[nt][3] - mn1);
            }
            s0 += __shfl_xor_sync(0xffffffffu, s0, 1);
            s0 += __shfl_xor_sync(0xffffffffu, s0, 2);
            s1 += __shfl_xor_sync(0xffffffffu, s1, 1);
            s1 += __shfl_xor_sync(0xffffffffu, s1, 2);
            l2[0] = l2[0] * ex2(m2[0] - mn0) + s0;  m2[0] = mn0;
            l2[1] = l2[1] * ex2(m2[1] - mn1) + s1;  m2[1] = mn1;
        }

        const float invl0 = 1.f / l2[0];
        const float invl1 = 1.f / l2[1];

        float o[8][4];
#pragma unroll
        for (int nd = 0; nd < 8; nd++)
#pragma unroll
            for (int p = 0; p < 4; p++) o[nd][p] = 0.f;

        /* ---------------- PASS 2: weights + O ---------------- */
        loadKV(0, 0);
        CP_COMMIT();

        for (int kb = 0; kb < nkt; kb++) {
            int cur = kb & 1;
            if (kb + 1 < nkt) {
                loadKV(cur ^ 1, kb + 1);
                CP_COMMIT();
                CP_WAIT(1);
            } else {
                CP_WAIT(0);
            }
            __syncthreads();

            uint32_t kbase = sb + QSZ + cur*ASTG;
            float acc[8][4];
            qk_tile(kbase, acc);

            const bool needmask = (kb*64 + 63) > rw0;
            uint32_t ew0[8], ew1[8];
#pragma unroll
            for (int nt = 0; nt < 8; nt++) {
                int k0c = kb*64 + nt*8 + q*2;
                float w0 = (!needmask || k0c   <= r0)
                           ? ex2(acc[nt][0]*CE - m2[0]) * invl0 : 0.f;
                float w1 = (!needmask || k0c+1 <= r0)
                           ? ex2(acc[nt][1]*CE - m2[0]) * invl0 : 0.f;
                float w2 = (!needmask || k0c   <= r1)
                           ? ex2(acc[nt][2]*CE - m2[1]) * invl1 : 0.f;
                float w3 = (!needmask || k0c+1 <= r1)
                           ? ex2(acc[nt][3]*CE - m2[1]) * invl1 : 0.f;
                ew0[nt] = pack_h2(w0, w1);
                ew1[nt] = pack_h2(w2, w3);
                if (write_w) {
                    __stcs((float2*)(wout + (basebh + r0)*SEQ + k0c),
                           make_float2(w0, w1));
                    __stcs((float2*)(wout + (basebh + r1)*SEQ + k0c),
                           make_float2(w2, w3));
                }
            }

            /* PV: w exact-f16 x V f16 hi/lo */
#pragma unroll
            for (int t = 0; t < 4; t++) {
                uint32_t aw[4] = {ew0[2*t], ew1[2*t], ew0[2*t+1], ew1[2*t+1]};
#pragma unroll
                for (int nd = 0; nd < 4; nd++) {
                    uint32_t vh[4], vl[4];
                    ldsm4t(vh[0], vh[1], vh[2], vh[3],
                           kbase + av_off + t*2304 + nd*32);
                    ldsm4t(vl[0], vl[1], vl[2], vl[3],
                           kbase + av_off + 9216 + t*2304 + nd*32);
                    mma_f16(o[nd*2],   aw, vh[0], vh[1]);
                    mma_f16(o[nd*2+1], aw, vh[2], vh[3]);
                    mma_f16(o[nd*2],   aw, vl[0], vl[1]);
                    mma_f16(o[nd*2+1], aw, vl[2], vl[3]);
                }
            }
            __syncthreads();
        }

        /* zero-fill masked (upper-triangle) region */
        if (write_w) {
            int kend = q0 + 128;
            int rem = SEQ - kend;
            if (rem > 0) {
                float4 z4 = make_float4(0.f, 0.f, 0.f, 0.f);
                for (int r = tid >> 5; r < 128; r += 8) {
                    float* rowp = wout + (basebh + q0 + r)*SEQ + kend;
                    for (int cc = (tid & 31)*4; cc < rem; cc += 128)
                        __stcs((float4*)(rowp + cc), z4);
                }
            }
        }

        /* write O in split-A format for the out-projection */
        {
            size_t mg0 = (size_t)b*SEQ + q0 + w*16 + g;
            size_t mg1 = mg0 + 8;
#pragma unroll
            for (int nd = 0; nd < 8; nd++) {
                int col = h*64 + nd*8 + q*2;
                int blk = col >> 5, j = col & 31;
                size_t b0 = mg0*KS3 + blk*96 + j;
                size_t b1 = mg1*KS3 + blk*96 + j;
                float c0 = o[nd][0], c1 = o[nd][1];
                float c2 = o[nd][2], c3 = o[nd][3];
                __nv_bfloat16 h0 = __float2bfloat16(c0);
                __nv_bfloat16 h1 = __float2bfloat16(c1);
                __nv_bfloat16 h2 = __float2bfloat16(c2);
                __nv_bfloat16 h3 = __float2bfloat16(c3);
                __nv_bfloat162 hi0 = __halves2bfloat162(h0, h1);
                __nv_bfloat162 hi1 = __halves2bfloat162(h2, h3);
                __nv_bfloat162 lo0 = __floats2bfloat162_rn(
                    c0 - __bfloat162float(h0), c1 - __bfloat162float(h1));
                __nv_bfloat162 lo1 = __floats2bfloat162_rn(
                    c2 - __bfloat162float(h2), c3 - __bfloat162float(h3));
                *(__nv_bfloat162*)(s_at + b0)      = hi0;
                *(__nv_bfloat162*)(s_at + b0 + 32) = lo0;
                *(__nv_bfloat162*)(s_at + b0 + 64) = hi0;
                *(__nv_bfloat162*)(s_at + b1)      = hi1;
                *(__nv_bfloat162*)(s_at + b1 + 32) = lo1;
                *(__nv_bfloat162*)(s_at + b1 + 64) = hi1;
            }
        }
        __syncthreads();
    }
}

/* ---------------- launcher ---------------- */
extern "C" void kernel_launch(void* const* d_in, const int* in_sizes, int n_in,
                              void* d_out, int out_size)
{
    const float* q  = (const float*)d_in[0];
    const float* k  = (const float*)d_in[1];
    const float* v  = (const float*)d_in[2];
    const float* Wq = (const float*)d_in[3];
    const float* bq = (const float*)d_in[4];
    const float* Wk = (const float*)d_in[5];
    const float* bk = (const float*)d_in[6];
    const float* Wv = (const float*)d_in[7];
    const float* bv = (const float*)d_in[8];
    const float* Wo = (const float*)d_in[9];
    const float* bo = (const float*)d_in[10];

    float* out  = (float*)d_out;
    int write_w = (out_size >= OUT_ELEMS + W_ELEMS) ? 1 : 0;
    float* wout = out + OUT_ELEMS;

    rope_table_kernel<<<(SEQ*32 + 255)/256, 256>>>();

    split_all<<<65536, 256>>>(q, k, v, Wq, Wk, Wv, Wo);

    cudaFuncSetAttribute(gemm_qkv,
                         cudaFuncAttributeMaxDynamicSharedMemorySize, 2*GSTG);
    cudaFuncSetAttribute(gemm_out,
                         cudaFuncAttributeMaxDynamicSharedMemorySize, 2*GSTG);
    cudaFuncSetAttribute(attn_mma,
                         cudaFuncAttributeMaxDynamicSharedMemorySize, ASMEM);

    gemm_qkv<<<dim3(HID/128, MTOT/128, 3), 256, 2*GSTG>>>(bq, bk, bv);

    attn_mma<<<dim3(8, NH, BATCH), 256, ASMEM>>>(wout, write_w);

    gemm_out<<<dim3(HID/128, MTOT/128), 256, 2*GSTG>>>(bo, out);
}

// round 11
// speedup vs baseline: 1.8607x; 1.3783x over previous
#include <cuda_runtime.h>
#include <cuda_bf16.h>
#include <cuda_fp16.h>
#include <math.h>
#include <stdint.h>

#define BATCH 2
#define SEQ   2048
#define HID   1024
#define NH    16
#define HD    64
#define MTOT  (BATCH*SEQ)
#define OUT_ELEMS   (MTOT*HID)
#define W_ELEMS     (BATCH*NH*SEQ*SEQ)
#define KS2   2048               /* f16 split-K: [hi(32) | lo(32)] x 1024 */
#define LOG2E 1.44269504088896340736f

/* ---------------- scratch (no allocations allowed) ---------------- */
__device__ float g_cos[SEQ*(HD/2)];
__device__ float g_sin[SEQ*(HD/2)];

/* attention operands (B,H,S,D), f16 */
__device__ __half g_Qh[BATCH*NH*SEQ*HD];
__device__ __half g_Ql[BATCH*NH*SEQ*HD];
__device__ __half g_Kh[BATCH*NH*SEQ*HD];
__device__ __half g_Vh[BATCH*NH*SEQ*HD];

/* GEMM operands, f16, rows x 2048. A-format [ah|al], B-format [bh|bh] */
__device__ __half s_q [MTOT*KS2];
__device__ __half s_k [MTOT*KS2];
__device__ __half s_v [MTOT*KS2];
__device__ __half s_at[MTOT*KS2];
__device__ __half s_wq[HID*KS2];
__device__ __half s_wk[HID*KS2];
__device__ __half s_wv[HID*KS2];
__device__ __half s_wo[HID*KS2];

/* ---------------- helpers ---------------- */
__device__ __forceinline__ uint32_t smem_u32(const void* p) {
    uint32_t a;
    asm("{ .reg .u64 t; cvta.to.shared.u64 t, %1; cvt.u32.u64 %0, t; }"
        : "=r"(a) : "l"(p));
    return a;
}
__device__ __forceinline__ void cp16(uint32_t s, const void* g) {
    asm volatile("cp.async.cg.shared.global [%0], [%1], 16;"
                 :: "r"(s), "l"(g));
}
#define CP_COMMIT() asm volatile("cp.async.commit_group;" ::: "memory")
#define CP_WAIT(N)  asm volatile("cp.async.wait_group %0;" :: "n"(N) : "memory")

__device__ __forceinline__ void ldsm4(uint32_t& r0, uint32_t& r1,
                                      uint32_t& r2, uint32_t& r3, uint32_t addr)
{
    asm volatile("ldmatrix.sync.aligned.m8n8.x4.shared.b16 {%0,%1,%2,%3}, [%4];"
                 : "=r"(r0), "=r"(r1), "=r"(r2), "=r"(r3) : "r"(addr));
}
__device__ __forceinline__ void ldsm4t(uint32_t& r0, uint32_t& r1,
                                       uint32_t& r2, uint32_t& r3, uint32_t addr)
{
    asm volatile("ldmatrix.sync.aligned.m8n8.x4.trans.shared.b16 {%0,%1,%2,%3}, [%4];"
                 : "=r"(r0), "=r"(r1), "=r"(r2), "=r"(r3) : "r"(addr));
}
__device__ __forceinline__ void mma_f16(float* d, const uint32_t* a,
                                        uint32_t b0, uint32_t b1)
{
    asm volatile(
        "mma.sync.aligned.m16n8k16.row.col.f32.f16.f16.f32 "
        "{%0,%1,%2,%3}, {%4,%5,%6,%7}, {%8,%9}, {%0,%1,%2,%3};"
        : "+f"(d[0]), "+f"(d[1]), "+f"(d[2]), "+f"(d[3])
        : "r"(a[0]), "r"(a[1]), "r"(a[2]), "r"(a[3]), "r"(b0), "r"(b1));
}
__device__ __forceinline__ float ex2(float x) {
    float y;
    asm("ex2.approx.ftz.f32 %0, %1;" : "=f"(y) : "f"(x));
    return y;
}
__device__ __forceinline__ uint32_t pack_h2(float x, float y) {
    __half2 t = __floats2half2_rn(x, y);
    return *(uint32_t*)&t;
}

/* ---------------- RoPE tables ---------------- */
__global__ void rope_table_kernel() {
    int idx = blockIdx.x * blockDim.x + threadIdx.x;
    if (idx >= SEQ * (HD/2)) return;
    int s = idx >> 5;
    int j = idx & 31;
    double inv = exp(-((double)(2*j) / (double)HD) * log(10000.0));
    double ang = (double)s * inv;
    g_cos[idx] = (float)cos(ang);
    g_sin[idx] = (float)sin(ang);
}

/* -------- merged fp32 -> f16 split (all 7 tensors, 1 launch) ------ */
__global__ void __launch_bounds__(256)
split_all(const float* __restrict__ q, const float* __restrict__ k,
          const float* __restrict__ v, const float* __restrict__ Wq,
          const float* __restrict__ Wk, const float* __restrict__ Wv,
          const float* __restrict__ Wo)
{
    int bid = blockIdx.x;
    const float* src;
    __half* dst;
    int idx, isA;
    if (bid < 49152) {                 /* inputs: 3 x 16384 blocks */
        int t = bid >> 14;
        src = (t == 0) ? q : (t == 1) ? k : v;
        dst = (t == 0) ? s_q : (t == 1) ? s_k : s_v;
        idx = ((bid & 16383) << 8) + threadIdx.x;
        isA = 1;
    } else {                           /* weights: 4 x 4096 blocks */
        int r = bid - 49152;
        int t = r >> 12;
        src = (t == 0) ? Wq : (t == 1) ? Wk : (t == 2) ? Wv : Wo;
        dst = (t == 0) ? s_wq : (t == 1) ? s_wk : (t == 2) ? s_wv : s_wo;
        idx = ((r & 4095) << 8) + threadIdx.x;
        isA = 0;
    }
    float x = src[idx];
    int row = idx >> 10, kk = idx & 1023;
    int blk = kk >> 5,  j  = kk & 31;
    __half hi = __float2half_rn(x);
    size_t base = (size_t)row * KS2 + blk*64 + j;
    dst[base] = hi;
    dst[base + 32] = isA ? __float2half_rn(x - __half2float(hi)) : hi;
}

/* ================= GEMM mainloop core (f16, K=2048) ================= */
#define GSTG 36864

__device__ __forceinline__ void gemm_core(
    const __half* __restrict__ A, const __half* __restrict__ B,
    char* gsm, int tid, int warp_m, int warp_n, int l,
    int m0, int n0, float acc[2][8][4])
{
    const uint32_t sb = smem_u32(gsm);
    const uint4* gA = (const uint4*)(A + (size_t)m0 * KS2);
    const uint4* gB = (const uint4*)(B + (size_t)n0 * KS2);

    uint32_t a_off[2], b_off[4];
#pragma unroll
    for (int mt = 0; mt < 2; mt++)
        a_off[mt] = (warp_m*32 + mt*16 + (l & 15))*144 + (l >> 4)*16;
#pragma unroll
    for (int nt = 0; nt < 4; nt++) {
        int row = warp_n*64 + nt*16 + (l & 7) + ((l >> 4) & 1) * 8;
        b_off[nt] = 18432 + row*144 + ((l >> 3) & 1)*16;
    }

    auto load_stage = [&](int stg, int it) {
        uint32_t base = sb + stg*GSTG;
#pragma unroll
        for (int u = 0; u < 4; u++) {
            int f = u*256 + tid;
            int r = f >> 3, c = f & 7;
            cp16(base + r*144 + c*16,         gA + (size_t)r*(KS2/8) + it*8 + c);
            cp16(base + 18432 + r*144 + c*16, gB + (size_t)r*(KS2/8) + it*8 + c);
        }
    };

    load_stage(0, 0);
    CP_COMMIT();

    for (int it = 0; it < KS2/64; it++) {
        int cur = it & 1;
        if (it + 1 < KS2/64) {
            load_stage(cur ^ 1, it + 1);
            CP_COMMIT();
            CP_WAIT(1);
        } else {
            CP_WAIT(0);
        }
        __syncthreads();

        uint32_t stgb = sb + cur*GSTG;
#pragma unroll
        for (int ks = 0; ks < 4; ks++) {
            uint32_t a[2][4], b[4][4];
#pragma unroll
            for (int mt = 0; mt < 2; mt++)
                ldsm4(a[mt][0], a[mt][1], a[mt][2], a[mt][3],
                      stgb + a_off[mt] + ks*32);
#pragma unroll
            for (int nt = 0; nt < 4; nt++)
                ldsm4(b[nt][0], b[nt][1], b[nt][2], b[nt][3],
                      stgb + b_off[nt] + ks*32);
#pragma unroll
            for (int mt = 0; mt < 2; mt++)
#pragma unroll
                for (int nt = 0; nt < 4; nt++) {
                    mma_f16(acc[mt][nt*2],   a[mt], b[nt][0], b[nt][1]);
                    mma_f16(acc[mt][nt*2+1], a[mt], b[nt][2], b[nt][3]);
                }
        }
        __syncthreads();
    }
}

/* ---- merged QKV projection GEMM: z = 0 (Q), 1 (K), 2 (V) ---- */
__global__ void __launch_bounds__(256, 2)
gemm_qkv(const float* __restrict__ bq, const float* __restrict__ bk,
         const float* __restrict__ bv)
{
    extern __shared__ __align__(16) char gsm[];

    const int tid = threadIdx.x;
    const int wid = tid >> 5, l = tid & 31;
    const int warp_m = wid >> 1, warp_n = wid & 1;
    const int m0 = blockIdx.y * 128;
    const int n0 = blockIdx.x * 128;
    const int z = blockIdx.z;

    const __half* A = (z == 0) ? s_q  : (z == 1) ? s_k  : s_v;
    const __half* B = (z == 0) ? s_wq : (z == 1) ? s_wk : s_wv;
    const float* bias = (z == 0) ? bq : (z == 1) ? bk : bv;

    float acc[2][8][4];
#pragma unroll
    for (int i = 0; i < 2; i++)
#pragma unroll
        for (int j = 0; j < 8; j++)
#pragma unroll
            for (int p = 0; p < 4; p++) acc[i][j][p] = 0.f;

    gemm_core(A, B, gsm, tid, warp_m, warp_n, l, m0, n0, acc);

    const int g = l >> 2, q = l & 3;
#pragma unroll
    for (int mt = 0; mt < 2; mt++) {
        int mrow0 = m0 + warp_m*32 + mt*16 + g;
#pragma unroll
        for (int nt2 = 0; nt2 < 8; nt2++) {
            int ncol = n0 + warp_n*64 + nt2*8 + q*2;
            float b0 = bias[ncol], b1 = bias[ncol+1];
            float c0 = acc[mt][nt2][0] + b0;
            float c1 = acc[mt][nt2][1] + b1;
            float c2 = acc[mt][nt2][2] + b0;
            float c3 = acc[mt][nt2][3] + b1;

            int h = ncol >> 6, d = ncol & 63;
            int bb0 = mrow0 >> 11, ss0 = mrow0 & 2047;
            int mrow1 = mrow0 + 8;
            int bb1 = mrow1 >> 11, ss1 = mrow1 & 2047;
            if (z < 2) {       /* RoPE for Q and K */
                float cs0 = g_cos[ss0*32 + (d>>1)], sn0 = g_sin[ss0*32 + (d>>1)];
                float cs1 = g_cos[ss1*32 + (d>>1)], sn1 = g_sin[ss1*32 + (d>>1)];
                float t0 = c0*cs0 - c1*sn0, t1 = c0*sn0 + c1*cs0;
                float t2 = c2*cs1 - c3*sn1, t3 = c2*sn1 + c3*cs1;
                c0 = t0; c1 = t1; c2 = t2; c3 = t3;
            }
            size_t a0 = (((size_t)(bb0*NH + h)*SEQ + ss0) << 6) + d;
            size_t a1 = (((size_t)(bb1*NH + h)*SEQ + ss1) << 6) + d;
            __half h0 = __float2half_rn(c0);
            __half h1 = __float2half_rn(c1);
            __half h2 = __float2half_rn(c2);
            __half h3 = __float2half_rn(c3);
            if (z == 0) {      /* Q: f16 hi + lo */
                *(__half2*)(g_Qh + a0) = __halves2half2(h0, h1);
                *(__half2*)(g_Qh + a1) = __halves2half2(h2, h3);
                *(__half2*)(g_Ql + a0) = __floats2half2_rn(
                    c0 - __half2float(h0), c1 - __half2float(h1));
                *(__half2*)(g_Ql + a1) = __floats2half2_rn(
                    c2 - __half2float(h2), c3 - __half2float(h3));
            } else if (z == 1) {  /* K: f16 hi only */
                *(__half2*)(g_Kh + a0) = __halves2half2(h0, h1);
                *(__half2*)(g_Kh + a1) = __halves2half2(h2, h3);
            } else {              /* V: f16 hi only */
                *(__half2*)(g_Vh + a0) = __halves2half2(h0, h1);
                *(__half2*)(g_Vh + a1) = __halves2half2(h2, h3);
            }
        }
    }
}

/* ---- output projection GEMM ---- */
__global__ void __launch_bounds__(256, 2)
gemm_out(const float* __restrict__ bo, float* __restrict__ dst)
{
    extern __shared__ __align__(16) char gsm[];

    const int tid = threadIdx.x;
    const int wid = tid >> 5, l = tid & 31;
    const int warp_m = wid >> 1, warp_n = wid & 1;
    const int m0 = blockIdx.y * 128;
    const int n0 = blockIdx.x * 128;

    float acc[2][8][4];
#pragma unroll
    for (int i = 0; i < 2; i++)
#pragma unroll
        for (int j = 0; j < 8; j++)
#pragma unroll
            for (int p = 0; p < 4; p++) acc[i][j][p] = 0.f;

    gemm_core(s_at, s_wo, gsm, tid, warp_m, warp_n, l, m0, n0, acc);

    const int g = l >> 2, q = l & 3;
#pragma unroll
    for (int mt = 0; mt < 2; mt++) {
        int mrow0 = m0 + warp_m*32 + mt*16 + g;
#pragma unroll
        for (int nt2 = 0; nt2 < 8; nt2++) {
            int ncol = n0 + warp_n*64 + nt2*8 + q*2;
            float b0 = bo[ncol], b1 = bo[ncol+1];
            *(float2*)(dst + (size_t)mrow0    *HID + ncol) =
                make_float2(acc[mt][nt2][0] + b0, acc[mt][nt2][1] + b1);
            *(float2*)(dst + (size_t)(mrow0+8)*HID + ncol) =
                make_float2(acc[mt][nt2][2] + b0, acc[mt][nt2][3] + b1);
        }
    }
}

/* ================= two-pass attention, causal-paired, f16 =========
   QK: 2-term f16 (qh + ql) x kh. PV: w exact-f16 x vh.
   smem: Qh/Ql resident 36864; 2 K/V stages of 18432 (Kh @0, Vh @9216). */
#define QSZ   36864
#define ASTG  18432
#define ASMEM (QSZ + 2*ASTG)

__global__ void __launch_bounds__(256, 2)
attn_mma(float* __restrict__ wout, int write_w)
{
    extern __shared__ __align__(16) char dsm[];
    const int tid = threadIdx.x;
    const int w = tid >> 5, l = tid & 31;
    const int g = l >> 2, q = l & 3;
    const int h = blockIdx.y, b = blockIdx.z;
    const size_t basebh = (size_t)(b*NH + h) * SEQ;
    const uint32_t sb = smem_u32(dsm);
    const float CE = 0.125f * LOG2E;

    uint32_t bk_off[4];
    {
        int krow = (l & 7) + ((l >> 4) & 1) * 8;
        int kcb  = ((l >> 3) & 1) * 16;
#pragma unroll
        for (int nt = 0; nt < 4; nt++)
            bk_off[nt] = (nt*16 + krow)*144 + kcb;
    }
    const uint32_t aQh = sb + (w*16 + (l & 15))*144 + (l >> 4)*16;
    const uint32_t aQl = aQh + 18432;
    const uint32_t av_off = 9216 + (l & 15)*144 + (l >> 4)*16;

    auto loadK = [&](int stg, int kb) {
        uint32_t base = sb + QSZ + stg*ASTG;
        const uint4* gkh = (const uint4*)(g_Kh + (basebh + kb*64) * HD);
#pragma unroll
        for (int u = 0; u < 2; u++) {
            int f = u*256 + tid;
            int r = f >> 3, c = f & 7;
            cp16(base + r*144 + c*16, gkh + r*8 + c);
        }
    };
    auto loadKV = [&](int stg, int kb) {
        uint32_t base = sb + QSZ + stg*ASTG;
        const uint4* gkh = (const uint4*)(g_Kh + (basebh + kb*64) * HD);
        const uint4* gvh = (const uint4*)(g_Vh + (basebh + kb*64) * HD);
#pragma unroll
        for (int u = 0; u < 2; u++) {
            int f = u*256 + tid;
            int r = f >> 3, c = f & 7;
            cp16(base + r*144 + c*16,        gkh + r*8 + c);
            cp16(base + 9216 + r*144 + c*16, gvh + r*8 + c);
        }
    };

    /* QK: 2-term f16 (qh + ql) x kh */
    auto qk_tile = [&](uint32_t kbase, float acc[8][4]) {
#pragma unroll
        for (int nt = 0; nt < 8; nt++)
#pragma unroll
            for (int p = 0; p < 4; p++) acc[nt][p] = 0.f;
#pragma unroll
        for (int ks = 0; ks < 4; ks++) {
            uint32_t ah[4], al[4];
            ldsm4(ah[0], ah[1], ah[2], ah[3], aQh + ks*32);
            ldsm4(al[0], al[1], al[2], al[3], aQl + ks*32);
#pragma unroll
            for (int np = 0; np < 4; np++) {
                uint32_t kh[4];
                ldsm4(kh[0], kh[1], kh[2], kh[3], kbase + bk_off[np] + ks*32);
                mma_f16(acc[np*2],   ah, kh[0], kh[1]);
                mma_f16(acc[np*2+1], ah, kh[2], kh[3]);
                mma_f16(acc[np*2],   al, kh[0], kh[1]);
                mma_f16(acc[np*2+1], al, kh[2], kh[3]);
            }
        }
    };

    for (int half = 0; half < 2; half++) {
        const int qt = half ? blockIdx.x : (15 - blockIdx.x);
        const int q0 = qt * 128;
        const int nkt = 2*qt + 2;
        const int rw0 = q0 + w*16;
        const int r0 = rw0 + g, r1 = r0 + 8;

        /* Q loads */
        {
            const uint4* gh = (const uint4*)(g_Qh + (basebh + q0) * HD);
            const uint4* gl = (const uint4*)(g_Ql + (basebh + q0) * HD);
#pragma unroll
            for (int u = 0; u < 4; u++) {
                int f = u*256 + tid;
                int r = f >> 3, c = f & 7;
                cp16(sb + r*144 + c*16,         gh + r*8 + c);
                cp16(sb + 18432 + r*144 + c*16, gl + r*8 + c);
            }
            CP_COMMIT();
        }

        float m2[2] = {-1e30f, -1e30f};
        float l2[2] = {0.f, 0.f};

        /* ---------------- PASS 1: row max & sum ---------------- */
        loadK(0, 0);
        CP_COMMIT();

        for (int kb = 0; kb < nkt; kb++) {
            int cur = kb & 1;
            if (kb + 1 < nkt) {
                loadK(cur ^ 1, kb + 1);
                CP_COMMIT();
                CP_WAIT(1);
            } else {
                CP_WAIT(0);
            }
            __syncthreads();

            float acc[8][4];
            qk_tile(sb + QSZ + cur*ASTG, acc);
            __syncthreads();

            const bool needmask = (kb*64 + 63) > rw0;
#pragma unroll
            for (int nt = 0; nt < 8; nt++) {
                int k0c = kb*64 + nt*8 + q*2;
                acc[nt][0] = (!needmask || k0c   <= r0) ? acc[nt][0]*CE : -1e30f;
                acc[nt][1] = (!needmask || k0c+1 <= r0) ? acc[nt][1]*CE : -1e30f;
                acc[nt][2] = (!needmask || k0c   <= r1) ? acc[nt][2]*CE : -1e30f;
                acc[nt][3] = (!needmask || k0c+1 <= r1) ? acc[nt][3]*CE : -1e30f;
            }
            float tm0 = -1e30f, tm1 = -1e30f;
#pragma unroll
            for (int nt = 0; nt < 8; nt++) {
                tm0 = fmaxf(tm0, fmaxf(acc[nt][0], acc[nt][1]));
                tm1 = fmaxf(tm1, fmaxf(acc[nt][2], acc[nt][3]));
            }
            tm0 = fmaxf(tm0, __shfl_xor_sync(0xffffffffu, tm0, 1));
            tm0 = fmaxf(tm0, __shfl_xor_sync(0xffffffffu, tm0, 2));
            tm1 = fmaxf(tm1, __shfl_xor_sync(0xffffffffu, tm1, 1));
            tm1 = fmaxf(tm1, __shfl_xor_sync(0xffffffffu, tm1, 2));
            float mn0 = fmaxf(m2[0], tm0), mn1 = fmaxf(m2[1], tm1);
            float s0 = 0.f, s1 = 0.f;
#pragma unroll
            for (int nt = 0; nt < 8; nt++) {
                s0 += ex2(acc[nt][0] - mn0) + ex2(acc[nt][1] - mn0);
                s1 += ex2(acc[nt][2] - mn1) + ex2(acc[nt][3] - mn1);
            }
            s0 += __shfl_xor_sync(0xffffffffu, s0, 1);
            s0 += __shfl_xor_sync(0xffffffffu, s0, 2);
            s1 += __shfl_xor_sync(0xffffffffu, s1, 1);
            s1 += __shfl_xor_sync(0xffffffffu, s1, 2);
            l2[0] = l2[0] * ex2(m2[0] - mn0) + s0;  m2[0] = mn0;
            l2[1] = l2[1] * ex2(m2[1] - mn1) + s1;  m2[1] = mn1;
        }

        const float invl0 = 1.f / l2[0];
        const float invl1 = 1.f / l2[1];

        float o[8][4];
#pragma unroll
        for (int nd = 0; nd < 8; nd++)
#pragma unroll
            for (int p = 0; p < 4; p++) o[nd][p] = 0.f;

        /* ---------------- PASS 2: weights + O ---------------- */
        loadKV(0, 0);
        CP_COMMIT();

        for (int kb = 0; kb < nkt; kb++) {
            int cur = kb & 1;
            if (kb + 1 < nkt) {
                loadKV(cur ^ 1, kb + 1);
                CP_COMMIT();
                CP_WAIT(1);
            } else {
                CP_WAIT(0);
            }
            __syncthreads();

            uint32_t kbase = sb + QSZ + cur*ASTG;
            float acc[8][4];
            qk_tile(kbase, acc);

            const bool needmask = (kb*64 + 63) > rw0;
            uint32_t ew0[8], ew1[8];
#pragma unroll
            for (int nt = 0; nt < 8; nt++) {
                int k0c = kb*64 + nt*8 + q*2;
                float w0 = (!needmask || k0c   <= r0)
                           ? ex2(acc[nt][0]*CE - m2[0]) * invl0 : 0.f;
                float w1 = (!needmask || k0c+1 <= r0)
                           ? ex2(acc[nt][1]*CE - m2[0]) * invl0 : 0.f;
                float w2 = (!needmask || k0c   <= r1)
                           ? ex2(acc[nt][2]*CE - m2[1]) * invl1 : 0.f;
                float w3 = (!needmask || k0c+1 <= r1)
                           ? ex2(acc[nt][3]*CE - m2[1]) * invl1 : 0.f;
                ew0[nt] = pack_h2(w0, w1);
                ew1[nt] = pack_h2(w2, w3);
                if (write_w) {
                    __stcs((float2*)(wout + (basebh + r0)*SEQ + k0c),
                           make_float2(w0, w1));
                    __stcs((float2*)(wout + (basebh + r1)*SEQ + k0c),
                           make_float2(w2, w3));
                }
            }

            /* PV: w exact-f16 x vh */
#pragma unroll
            for (int t = 0; t < 4; t++) {
                uint32_t aw[4] = {ew0[2*t], ew1[2*t], ew0[2*t+1], ew1[2*t+1]};
#pragma unroll
                for (int nd = 0; nd < 4; nd++) {
                    uint32_t vh[4];
                    ldsm4t(vh[0], vh[1], vh[2], vh[3],
                           kbase + av_off + t*2304 + nd*32);
                    mma_f16(o[nd*2],   aw, vh[0], vh[1]);
                    mma_f16(o[nd*2+1], aw, vh[2], vh[3]);
                }
            }
            __syncthreads();
        }

        /* zero-fill masked (upper-triangle) region */
        if (write_w) {
            int kend = q0 + 128;
            int rem = SEQ - kend;
            if (rem > 0) {
                float4 z4 = make_float4(0.f, 0.f, 0.f, 0.f);
                for (int r = tid >> 5; r < 128; r += 8) {
                    float* rowp = wout + (basebh + q0 + r)*SEQ + kend;
                    for (int cc = (tid & 31)*4; cc < rem; cc += 128)
                        __stcs((float4*)(rowp + cc), z4);
                }
            }
        }

        /* write O in f16 split-A format for the out-projection */
        {
            size_t mg0 = (size_t)b*SEQ + q0 + w*16 + g;
            size_t mg1 = mg0 + 8;
#pragma unroll
            for (int nd = 0; nd < 8; nd++) {
                int col = h*64 + nd*8 + q*2;
                int blk = col >> 5, j = col & 31;
                size_t b0 = mg0*KS2 + blk*64 + j;
                size_t b1 = mg1*KS2 + blk*64 + j;
                float c0 = o[nd][0], c1 = o[nd][1];
                float c2 = o[nd][2], c3 = o[nd][3];
                __half h0 = __float2half_rn(c0);
                __half h1 = __float2half_rn(c1);
                __half h2 = __float2half_rn(c2);
                __half h3 = __float2half_rn(c3);
                *(__half2*)(s_at + b0)      = __halves2half2(h0, h1);
                *(__half2*)(s_at + b0 + 32) = __floats2half2_rn(
                    c0 - __half2float(h0), c1 - __half2float(h1));
                *(__half2*)(s_at + b1)      = __halves2half2(h2, h3);
                *(__half2*)(s_at + b1 + 32) = __floats2half2_rn(
                    c2 - __half2float(h2), c3 - __half2float(h3));
            }
        }
        __syncthreads();
    }
}

/* ---------------- launcher ---------------- */
extern "C" void kernel_launch(void* const* d_in, const int* in_sizes, int n_in,
                              void* d_out, int out_size)
{
    const float* q  = (const float*)d_in[0];
    const float* k  = (const float*)d_in[1];
    const float* v  = (const float*)d_in[2];
    const float* Wq = (const float*)d_in[3];
    const float* bq = (const float*)d_in[4];
    const float* Wk = (const float*)d_in[5];
    const float* bk = (const float*)d_in[6];
    const float* Wv = (const float*)d_in[7];
    const float* bv = (const float*)d_in[8];
    const float* Wo = (const float*)d_in[9];
    const float* bo = (const float*)d_in[10];

    float* out  = (float*)d_out;
    int write_w = (out_size >= OUT_ELEMS + W_ELEMS) ? 1 : 0;
    float* wout = out + OUT_ELEMS;

    rope_table_kernel<<<(SEQ*32 + 255)/256, 256>>>();

    split_all<<<65536, 256>>>(q, k, v, Wq, Wk, Wv, Wo);

    cudaFuncSetAttribute(gemm_qkv,
                         cudaFuncAttributeMaxDynamicSharedMemorySize, 2*GSTG);
    cudaFuncSetAttribute(gemm_out,
                         cudaFuncAttributeMaxDynamicSharedMemorySize, 2*GSTG);
    cudaFuncSetAttribute(attn_mma,
                         cudaFuncAttributeMaxDynamicSharedMemorySize, ASMEM);

    gemm_qkv<<<dim3(HID/128, MTOT/128, 3), 256, 2*GSTG>>>(bq, bk, bv);

    attn_mma<<<dim3(8, NH, BATCH), 256, ASMEM>>>(wout, write_w);

    gemm_out<<<dim3(HID/128, MTOT/128), 256, 2*GSTG>>>(bo, out);
}

// round 12
// speedup vs baseline: 1.9436x; 1.0446x over previous
#include <cuda_runtime.h>
#include <cuda_bf16.h>
#include <cuda_fp16.h>
#include <math.h>
#include <stdint.h>

#define BATCH 2
#define SEQ   2048
#define HID   1024
#define NH    16
#define HD    64
#define MTOT  (BATCH*SEQ)
#define OUT_ELEMS   (MTOT*HID)
#define W_ELEMS     (BATCH*NH*SEQ*SEQ)
#define KS2   2048               /* f16 split-K: [hi(32) | lo(32)] x 1024 */
#define LOG2E 1.44269504088896340736f

/* ---------------- scratch (no allocations allowed) ---------------- */
__device__ float g_cos[SEQ*(HD/2)];
__device__ float g_sin[SEQ*(HD/2)];

__device__ __half g_Qh[BATCH*NH*SEQ*HD];
__device__ __half g_Ql[BATCH*NH*SEQ*HD];
__device__ __half g_Kh[BATCH*NH*SEQ*HD];
__device__ __half g_Vh[BATCH*NH*SEQ*HD];

__device__ __half s_q [MTOT*KS2];
__device__ __half s_k [MTOT*KS2];
__device__ __half s_v [MTOT*KS2];
__device__ __half s_at[MTOT*KS2];
__device__ __half s_wq[HID*KS2];
__device__ __half s_wk[HID*KS2];
__device__ __half s_wv[HID*KS2];
__device__ __half s_wo[HID*KS2];

/* ---------------- helpers ---------------- */
__device__ __forceinline__ uint32_t smem_u32(const void* p) {
    uint32_t a;
    asm("{ .reg .u64 t; cvta.to.shared.u64 t, %1; cvt.u32.u64 %0, t; }"
        : "=r"(a) : "l"(p));
    return a;
}
__device__ __forceinline__ void cp16(uint32_t s, const void* g) {
    asm volatile("cp.async.cg.shared.global [%0], [%1], 16;"
                 :: "r"(s), "l"(g));
}
#define CP_COMMIT() asm volatile("cp.async.commit_group;" ::: "memory")
#define CP_WAIT(N)  asm volatile("cp.async.wait_group %0;" :: "n"(N) : "memory")

__device__ __forceinline__ void ldsm4(uint32_t& r0, uint32_t& r1,
                                      uint32_t& r2, uint32_t& r3, uint32_t addr)
{
    asm volatile("ldmatrix.sync.aligned.m8n8.x4.shared.b16 {%0,%1,%2,%3}, [%4];"
                 : "=r"(r0), "=r"(r1), "=r"(r2), "=r"(r3) : "r"(addr));
}
__device__ __forceinline__ void ldsm4t(uint32_t& r0, uint32_t& r1,
                                       uint32_t& r2, uint32_t& r3, uint32_t addr)
{
    asm volatile("ldmatrix.sync.aligned.m8n8.x4.trans.shared.b16 {%0,%1,%2,%3}, [%4];"
                 : "=r"(r0), "=r"(r1), "=r"(r2), "=r"(r3) : "r"(addr));
}
__device__ __forceinline__ void mma_f16(float* d, const uint32_t* a,
                                        uint32_t b0, uint32_t b1)
{
    asm volatile(
        "mma.sync.aligned.m16n8k16.row.col.f32.f16.f16.f32 "
        "{%0,%1,%2,%3}, {%4,%5,%6,%7}, {%8,%9}, {%0,%1,%2,%3};"
        : "+f"(d[0]), "+f"(d[1]), "+f"(d[2]), "+f"(d[3])
        : "r"(a[0]), "r"(a[1]), "r"(a[2]), "r"(a[3]), "r"(b0), "r"(b1));
}
__device__ __forceinline__ float ex2(float x) {
    float y;
    asm("ex2.approx.ftz.f32 %0, %1;" : "=f"(y) : "f"(x));
    return y;
}
__device__ __forceinline__ uint32_t pack_h2(float x, float y) {
    __half2 t = __floats2half2_rn(x, y);
    return *(uint32_t*)&t;
}

/* ---------------- RoPE tables ---------------- */
__global__ void rope_table_kernel() {
    int idx = blockIdx.x * blockDim.x + threadIdx.x;
    if (idx >= SEQ * (HD/2)) return;
    int s = idx >> 5;
    int j = idx & 31;
    double inv = exp(-((double)(2*j) / (double)HD) * log(10000.0));
    double ang = (double)s * inv;
    g_cos[idx] = (float)cos(ang);
    g_sin[idx] = (float)sin(ang);
}

/* -------- merged fp32 -> f16 split, vectorized (2 elems/thread) ---- */
__global__ void __launch_bounds__(256)
split_all(const float* __restrict__ q, const float* __restrict__ k,
          const float* __restrict__ v, const float* __restrict__ Wq,
          const float* __restrict__ Wk, const float* __restrict__ Wv,
          const float* __restrict__ Wo)
{
    int bid = blockIdx.x;
    const float* src;
    __half* dst;
    int idx2, isA;
    if (bid < 24576) {                 /* inputs: 3 x 8192 blocks */
        int t = bid >> 13;
        src = (t == 0) ? q : (t == 1) ? k : v;
        dst = (t == 0) ? s_q : (t == 1) ? s_k : s_v;
        idx2 = ((bid & 8191) << 8) + threadIdx.x;
        isA = 1;
    } else {                           /* weights: 4 x 2048 blocks */
        int r = bid - 24576;
        int t = r >> 11;
        src = (t == 0) ? Wq : (t == 1) ? Wk : (t == 2) ? Wv : Wo;
        dst = (t == 0) ? s_wq : (t == 1) ? s_wk : (t == 2) ? s_wv : s_wo;
        idx2 = ((r & 2047) << 8) + threadIdx.x;
        isA = 0;
    }
    float2 x = ((const float2*)src)[idx2];
    int row = idx2 >> 9, kk = (idx2 & 511) * 2;
    int blk = kk >> 5,  j  = kk & 31;
    __half2 hi = __floats2half2_rn(x.x, x.y);
    size_t base = (size_t)row * KS2 + blk*64 + j;
    *(__half2*)(dst + base) = hi;
    if (isA) {
        *(__half2*)(dst + base + 32) = __floats2half2_rn(
            x.x - __half2float(hi.x), x.y - __half2float(hi.y));
    } else {
        *(__half2*)(dst + base + 32) = hi;
    }
}

/* ================= GEMM mainloop core (f16, K=2048) ================= */
#define GSTG 36864

__device__ __forceinline__ void gemm_core(
    const __half* __restrict__ A, const __half* __restrict__ B,
    char* gsm, int tid, int warp_m, int warp_n, int l,
    int m0, int n0, float acc[2][8][4])
{
    const uint32_t sb = smem_u32(gsm);
    const uint4* gA = (const uint4*)(A + (size_t)m0 * KS2);
    const uint4* gB = (const uint4*)(B + (size_t)n0 * KS2);

    uint32_t a_off[2], b_off[4];
#pragma unroll
    for (int mt = 0; mt < 2; mt++)
        a_off[mt] = (warp_m*32 + mt*16 + (l & 15))*144 + (l >> 4)*16;
#pragma unroll
    for (int nt = 0; nt < 4; nt++) {
        int row = warp_n*64 + nt*16 + (l & 7) + ((l >> 4) & 1) * 8;
        b_off[nt] = 18432 + row*144 + ((l >> 3) & 1)*16;
    }

    auto load_stage = [&](int stg, int it) {
        uint32_t base = sb + stg*GSTG;
#pragma unroll
        for (int u = 0; u < 4; u++) {
            int f = u*256 + tid;
            int r = f >> 3, c = f & 7;
            cp16(base + r*144 + c*16,         gA + (size_t)r*(KS2/8) + it*8 + c);
            cp16(base + 18432 + r*144 + c*16, gB + (size_t)r*(KS2/8) + it*8 + c);
        }
    };

    load_stage(0, 0);
    CP_COMMIT();

    for (int it = 0; it < KS2/64; it++) {
        int cur = it & 1;
        if (it + 1 < KS2/64) {
            load_stage(cur ^ 1, it + 1);
            CP_COMMIT();
            CP_WAIT(1);
        } else {
            CP_WAIT(0);
        }
        __syncthreads();

        uint32_t stgb = sb + cur*GSTG;
#pragma unroll
        for (int ks = 0; ks < 4; ks++) {
            uint32_t a[2][4], b[4][4];
#pragma unroll
            for (int mt = 0; mt < 2; mt++)
                ldsm4(a[mt][0], a[mt][1], a[mt][2], a[mt][3],
                      stgb + a_off[mt] + ks*32);
#pragma unroll
            for (int nt = 0; nt < 4; nt++)
                ldsm4(b[nt][0], b[nt][1], b[nt][2], b[nt][3],
                      stgb + b_off[nt] + ks*32);
#pragma unroll
            for (int mt = 0; mt < 2; mt++)
#pragma unroll
                for (int nt = 0; nt < 4; nt++) {
                    mma_f16(acc[mt][nt*2],   a[mt], b[nt][0], b[nt][1]);
                    mma_f16(acc[mt][nt*2+1], a[mt], b[nt][2], b[nt][3]);
                }
        }
        __syncthreads();
    }
}

/* ---- merged QKV projection GEMM: z = 0 (Q), 1 (K), 2 (V) ---- */
__global__ void __launch_bounds__(256, 2)
gemm_qkv(const float* __restrict__ bq, const float* __restrict__ bk,
         const float* __restrict__ bv)
{
    extern __shared__ __align__(16) char gsm[];

    const int tid = threadIdx.x;
    const int wid = tid >> 5, l = tid & 31;
    const int warp_m = wid >> 1, warp_n = wid & 1;
    const int m0 = blockIdx.y * 128;
    const int n0 = blockIdx.x * 128;
    const int z = blockIdx.z;

    const __half* A = (z == 0) ? s_q  : (z == 1) ? s_k  : s_v;
    const __half* B = (z == 0) ? s_wq : (z == 1) ? s_wk : s_wv;
    const float* bias = (z == 0) ? bq : (z == 1) ? bk : bv;

    float acc[2][8][4];
#pragma unroll
    for (int i = 0; i < 2; i++)
#pragma unroll
        for (int j = 0; j < 8; j++)
#pragma unroll
            for (int p = 0; p < 4; p++) acc[i][j][p] = 0.f;

    gemm_core(A, B, gsm, tid, warp_m, warp_n, l, m0, n0, acc);

    const int g = l >> 2, q = l & 3;
#pragma unroll
    for (int mt = 0; mt < 2; mt++) {
        int mrow0 = m0 + warp_m*32 + mt*16 + g;
#pragma unroll
        for (int nt2 = 0; nt2 < 8; nt2++) {
            int ncol = n0 + warp_n*64 + nt2*8 + q*2;
            float b0 = bias[ncol], b1 = bias[ncol+1];
            float c0 = acc[mt][nt2][0] + b0;
            float c1 = acc[mt][nt2][1] + b1;
            float c2 = acc[mt][nt2][2] + b0;
            float c3 = acc[mt][nt2][3] + b1;

            int h = ncol >> 6, d = ncol & 63;
            int bb0 = mrow0 >> 11, ss0 = mrow0 & 2047;
            int mrow1 = mrow0 + 8;
            int bb1 = mrow1 >> 11, ss1 = mrow1 & 2047;
            if (z < 2) {
                float cs0 = g_cos[ss0*32 + (d>>1)], sn0 = g_sin[ss0*32 + (d>>1)];
                float cs1 = g_cos[ss1*32 + (d>>1)], sn1 = g_sin[ss1*32 + (d>>1)];
                float t0 = c0*cs0 - c1*sn0, t1 = c0*sn0 + c1*cs0;
                float t2 = c2*cs1 - c3*sn1, t3 = c2*sn1 + c3*cs1;
                c0 = t0; c1 = t1; c2 = t2; c3 = t3;
            }
            size_t a0 = (((size_t)(bb0*NH + h)*SEQ + ss0) << 6) + d;
            size_t a1 = (((size_t)(bb1*NH + h)*SEQ + ss1) << 6) + d;
            __half h0 = __float2half_rn(c0);
            __half h1 = __float2half_rn(c1);
            __half h2 = __float2half_rn(c2);
            __half h3 = __float2half_rn(c3);
            if (z == 0) {
                *(__half2*)(g_Qh + a0) = __halves2half2(h0, h1);
                *(__half2*)(g_Qh + a1) = __halves2half2(h2, h3);
                *(__half2*)(g_Ql + a0) = __floats2half2_rn(
                    c0 - __half2float(h0), c1 - __half2float(h1));
                *(__half2*)(g_Ql + a1) = __floats2half2_rn(
                    c2 - __half2float(h2), c3 - __half2float(h3));
            } else if (z == 1) {
                *(__half2*)(g_Kh + a0) = __halves2half2(h0, h1);
                *(__half2*)(g_Kh + a1) = __halves2half2(h2, h3);
            } else {
                *(__half2*)(g_Vh + a0) = __halves2half2(h0, h1);
                *(__half2*)(g_Vh + a1) = __halves2half2(h2, h3);
            }
        }
    }
}

/* ---- output projection GEMM ---- */
__global__ void __launch_bounds__(256, 2)
gemm_out(const float* __restrict__ bo, float* __restrict__ dst)
{
    extern __shared__ __align__(16) char gsm[];

    const int tid = threadIdx.x;
    const int wid = tid >> 5, l = tid & 31;
    const int warp_m = wid >> 1, warp_n = wid & 1;
    const int m0 = blockIdx.y * 128;
    const int n0 = blockIdx.x * 128;

    float acc[2][8][4];
#pragma unroll
    for (int i = 0; i < 2; i++)
#pragma unroll
        for (int j = 0; j < 8; j++)
#pragma unroll
            for (int p = 0; p < 4; p++) acc[i][j][p] = 0.f;

    gemm_core(s_at, s_wo, gsm, tid, warp_m, warp_n, l, m0, n0, acc);

    const int g = l >> 2, q = l & 3;
#pragma unroll
    for (int mt = 0; mt < 2; mt++) {
        int mrow0 = m0 + warp_m*32 + mt*16 + g;
#pragma unroll
        for (int nt2 = 0; nt2 < 8; nt2++) {
            int ncol = n0 + warp_n*64 + nt2*8 + q*2;
            float b0 = bo[ncol], b1 = bo[ncol+1];
            *(float2*)(dst + (size_t)mrow0    *HID + ncol) =
                make_float2(acc[mt][nt2][0] + b0, acc[mt][nt2][1] + b1);
            *(float2*)(dst + (size_t)(mrow0+8)*HID + ncol) =
                make_float2(acc[mt][nt2][2] + b0, acc[mt][nt2][3] + b1);
        }
    }
}

/* ================= two-pass attention, causal-paired, f16 =========
   3-stage cp.async pipeline, ONE __syncthreads per k-tile:
   per tile: CP_WAIT -> barrier -> issue load(tile+2) -> compute.     */
#define QSZ   36864
#define ASTG  18432
#define ASMEM (QSZ + 3*ASTG)

__global__ void __launch_bounds__(256, 2)
attn_mma(float* __restrict__ wout, int write_w)
{
    extern __shared__ __align__(16) char dsm[];
    const int tid = threadIdx.x;
    const int w = tid >> 5, l = tid & 31;
    const int g = l >> 2, q = l & 3;
    const int h = blockIdx.y, b = blockIdx.z;
    const size_t basebh = (size_t)(b*NH + h) * SEQ;
    const uint32_t sb = smem_u32(dsm);
    const float CE = 0.125f * LOG2E;

    uint32_t bk_off[4];
    {
        int krow = (l & 7) + ((l >> 4) & 1) * 8;
        int kcb  = ((l >> 3) & 1) * 16;
#pragma unroll
        for (int nt = 0; nt < 4; nt++)
            bk_off[nt] = (nt*16 + krow)*144 + kcb;
    }
    const uint32_t aQh = sb + (w*16 + (l & 15))*144 + (l >> 4)*16;
    const uint32_t aQl = aQh + 18432;
    const uint32_t av_off = 9216 + (l & 15)*144 + (l >> 4)*16;

    auto loadK = [&](int stg, int kb) {
        uint32_t base = sb + QSZ + stg*ASTG;
        const uint4* gkh = (const uint4*)(g_Kh + (basebh + kb*64) * HD);
#pragma unroll
        for (int u = 0; u < 2; u++) {
            int f = u*256 + tid;
            int r = f >> 3, c = f & 7;
            cp16(base + r*144 + c*16, gkh + r*8 + c);
        }
    };
    auto loadKV = [&](int stg, int kb) {
        uint32_t base = sb + QSZ + stg*ASTG;
        const uint4* gkh = (const uint4*)(g_Kh + (basebh + kb*64) * HD);
        const uint4* gvh = (const uint4*)(g_Vh + (basebh + kb*64) * HD);
#pragma unroll
        for (int u = 0; u < 2; u++) {
            int f = u*256 + tid;
            int r = f >> 3, c = f & 7;
            cp16(base + r*144 + c*16,        gkh + r*8 + c);
            cp16(base + 9216 + r*144 + c*16, gvh + r*8 + c);
        }
    };

    auto qk_tile = [&](uint32_t kbase, float acc[8][4]) {
#pragma unroll
        for (int nt = 0; nt < 8; nt++)
#pragma unroll
            for (int p = 0; p < 4; p++) acc[nt][p] = 0.f;
#pragma unroll
        for (int ks = 0; ks < 4; ks++) {
            uint32_t ah[4], al[4];
            ldsm4(ah[0], ah[1], ah[2], ah[3], aQh + ks*32);
            ldsm4(al[0], al[1], al[2], al[3], aQl + ks*32);
#pragma unroll
            for (int np = 0; np < 4; np++) {
                uint32_t kh[4];
                ldsm4(kh[0], kh[1], kh[2], kh[3], kbase + bk_off[np] + ks*32);
                mma_f16(acc[np*2],   ah, kh[0], kh[1]);
                mma_f16(acc[np*2+1], ah, kh[2], kh[3]);
                mma_f16(acc[np*2],   al, kh[0], kh[1]);
                mma_f16(acc[np*2+1], al, kh[2], kh[3]);
            }
        }
    };

    for (int half = 0; half < 2; half++) {
        const int qt = half ? blockIdx.x : (15 - blockIdx.x);
        const int q0 = qt * 128;
        const int nkt = 2*qt + 2;
        const int rw0 = q0 + w*16;
        const int r0 = rw0 + g, r1 = r0 + 8;

        /* Q loads */
        {
            const uint4* gh = (const uint4*)(g_Qh + (basebh + q0) * HD);
            const uint4* gl = (const uint4*)(g_Ql + (basebh + q0) * HD);
#pragma unroll
            for (int u = 0; u < 4; u++) {
                int f = u*256 + tid;
                int r = f >> 3, c = f & 7;
                cp16(sb + r*144 + c*16,         gh + r*8 + c);
                cp16(sb + 18432 + r*144 + c*16, gl + r*8 + c);
            }
            CP_COMMIT();
        }

        float m2[2] = {-1e30f, -1e30f};
        float l2[2] = {0.f, 0.f};

        /* ---------------- PASS 1: row max & sum ---------------- */
        loadK(0, 0);
        CP_COMMIT();
        if (nkt > 1) { loadK(1, 1); CP_COMMIT(); }

        for (int kb = 0; kb < nkt; kb++) {
            if (kb + 1 < nkt) CP_WAIT(1); else CP_WAIT(0);
            __syncthreads();
            if (kb + 2 < nkt) {
                int s2 = kb + 2; s2 = s2 - (s2 >= 3 ? 3 : 0) - (s2 - (s2 >= 3 ? 3 : 0) >= 3 ? 3 : 0);
                loadK((kb + 2) % 3, kb + 2);
                CP_COMMIT();
            }

            float acc[8][4];
            qk_tile(sb + QSZ + (kb % 3)*ASTG, acc);

            const bool needmask = (kb*64 + 63) > rw0;
#pragma unroll
            for (int nt = 0; nt < 8; nt++) {
                int k0c = kb*64 + nt*8 + q*2;
                acc[nt][0] = (!needmask || k0c   <= r0) ? acc[nt][0]*CE : -1e30f;
                acc[nt][1] = (!needmask || k0c+1 <= r0) ? acc[nt][1]*CE : -1e30f;
                acc[nt][2] = (!needmask || k0c   <= r1) ? acc[nt][2]*CE : -1e30f;
                acc[nt][3] = (!needmask || k0c+1 <= r1) ? acc[nt][3]*CE : -1e30f;
            }
            float tm0 = -1e30f, tm1 = -1e30f;
#pragma unroll
            for (int nt = 0; nt < 8; nt++) {
                tm0 = fmaxf(tm0, fmaxf(acc[nt][0], acc[nt][1]));
                tm1 = fmaxf(tm1, fmaxf(acc[nt][2], acc[nt][3]));
            }
            tm0 = fmaxf(tm0, __shfl_xor_sync(0xffffffffu, tm0, 1));
            tm0 = fmaxf(tm0, __shfl_xor_sync(0xffffffffu, tm0, 2));
            tm1 = fmaxf(tm1, __shfl_xor_sync(0xffffffffu, tm1, 1));
            tm1 = fmaxf(tm1, __shfl_xor_sync(0xffffffffu, tm1, 2));
            float mn0 = fmaxf(m2[0], tm0), mn1 = fmaxf(m2[1], tm1);
            float s0 = 0.f, s1 = 0.f;
#pragma unroll
            for (int nt = 0; nt < 8; nt++) {
                s0 += ex2(acc[nt][0] - mn0) + ex2(acc[nt][1] - mn0);
                s1 += ex2(acc[nt][2] - mn1) + ex2(acc[nt][3] - mn1);
            }
            s0 += __shfl_xor_sync(0xffffffffu, s0, 1);
            s0 += __shfl_xor_sync(0xffffffffu, s0, 2);
            s1 += __shfl_xor_sync(0xffffffffu, s1, 1);
            s1 += __shfl_xor_sync(0xffffffffu, s1, 2);
            l2[0] = l2[0] * ex2(m2[0] - mn0) + s0;  m2[0] = mn0;
            l2[1] = l2[1] * ex2(m2[1] - mn1) + s1;  m2[1] = mn1;
        }

        const float invl0 = 1.f / l2[0];
        const float invl1 = 1.f / l2[1];

        float o[8][4];
#pragma unroll
        for (int nd = 0; nd < 8; nd++)
#pragma unroll
            for (int p = 0; p < 4; p++) o[nd][p] = 0.f;

        /* ---------------- PASS 2: weights + O ---------------- */
        __syncthreads();          /* pass-1 reads done before reuse */
        loadKV(0, 0);
        CP_COMMIT();
        if (nkt > 1) { loadKV(1, 1); CP_COMMIT(); }

        for (int kb = 0; kb < nkt; kb++) {
            if (kb + 1 < nkt) CP_WAIT(1); else CP_WAIT(0);
            __syncthreads();
            if (kb + 2 < nkt) {
                loadKV((kb + 2) % 3, kb + 2);
                CP_COMMIT();
            }

            uint32_t kbase = sb + QSZ + (kb % 3)*ASTG;
            float acc[8][4];
            qk_tile(kbase, acc);

            const bool needmask = (kb*64 + 63) > rw0;
            uint32_t ew0[8], ew1[8];
#pragma unroll
            for (int nt = 0; nt < 8; nt++) {
                int k0c = kb*64 + nt*8 + q*2;
                float w0 = (!needmask || k0c   <= r0)
                           ? ex2(acc[nt][0]*CE - m2[0]) * invl0 : 0.f;
                float w1 = (!needmask || k0c+1 <= r0)
                           ? ex2(acc[nt][1]*CE - m2[0]) * invl0 : 0.f;
                float w2 = (!needmask || k0c   <= r1)
                           ? ex2(acc[nt][2]*CE - m2[1]) * invl1 : 0.f;
                float w3 = (!needmask || k0c+1 <= r1)
                           ? ex2(acc[nt][3]*CE - m2[1]) * invl1 : 0.f;
                ew0[nt] = pack_h2(w0, w1);
                ew1[nt] = pack_h2(w2, w3);
                if (write_w) {
                    __stcs((float2*)(wout + (basebh + r0)*SEQ + k0c),
                           make_float2(w0, w1));
                    __stcs((float2*)(wout + (basebh + r1)*SEQ + k0c),
                           make_float2(w2, w3));
                }
            }

            /* PV: w exact-f16 x vh */
#pragma unroll
            for (int t = 0; t < 4; t++) {
                uint32_t aw[4] = {ew0[2*t], ew1[2*t], ew0[2*t+1], ew1[2*t+1]};
#pragma unroll
                for (int nd = 0; nd < 4; nd++) {
                    uint32_t vh[4];
                    ldsm4t(vh[0], vh[1], vh[2], vh[3],
                           kbase + av_off + t*2304 + nd*32);
                    mma_f16(o[nd*2],   aw, vh[0], vh[1]);
                    mma_f16(o[nd*2+1], aw, vh[2], vh[3]);
                }
            }
        }

        /* zero-fill masked (upper-triangle) region */
        if (write_w) {
            int kend = q0 + 128;
            int rem = SEQ - kend;
            if (rem > 0) {
                float4 z4 = make_float4(0.f, 0.f, 0.f, 0.f);
                for (int r = tid >> 5; r < 128; r += 8) {
                    float* rowp = wout + (basebh + q0 + r)*SEQ + kend;
                    for (int cc = (tid & 31)*4; cc < rem; cc += 128)
                        __stcs((float4*)(rowp + cc), z4);
                }
            }
        }

        /* write O in f16 split-A format for the out-projection */
        {
            size_t mg0 = (size_t)b*SEQ + q0 + w*16 + g;
            size_t mg1 = mg0 + 8;
#pragma unroll
            for (int nd = 0; nd < 8; nd++) {
                int col = h*64 + nd*8 + q*2;
                int blk = col >> 5, j = col & 31;
                size_t b0 = mg0*KS2 + blk*64 + j;
                size_t b1 = mg1*KS2 + blk*64 + j;
                float c0 = o[nd][0], c1 = o[nd][1];
                float c2 = o[nd][2], c3 = o[nd][3];
                __half h0 = __float2half_rn(c0);
                __half h1 = __float2half_rn(c1);
                __half h2 = __float2half_rn(c2);
                __half h3 = __float2half_rn(c3);
                *(__half2*)(s_at + b0)      = __halves2half2(h0, h1);
                *(__half2*)(s_at + b0 + 32) = __floats2half2_rn(
                    c0 - __half2float(h0), c1 - __half2float(h1));
                *(__half2*)(s_at + b1)      = __halves2half2(h2, h3);
                *(__half2*)(s_at + b1 + 32) = __floats2half2_rn(
                    c2 - __half2float(h2), c3 - __half2float(h3));
            }
        }
        __syncthreads();
    }
}

/* ---------------- launcher ---------------- */
extern "C" void kernel_launch(void* const* d_in, const int* in_sizes, int n_in,
                              void* d_out, int out_size)
{
    const float* q  = (const float*)d_in[0];
    const float* k  = (const float*)d_in[1];
    const float* v  = (const float*)d_in[2];
    const float* Wq = (const float*)d_in[3];
    const float* bq = (const float*)d_in[4];
    const float* Wk = (const float*)d_in[5];
    const float* bk = (const float*)d_in[6];
    const float* Wv = (const float*)d_in[7];
    const float* bv = (const float*)d_in[8];
    const float* Wo = (const float*)d_in[9];
    const float* bo = (const float*)d_in[10];

    float* out  = (float*)d_out;
    int write_w = (out_size >= OUT_ELEMS + W_ELEMS) ? 1 : 0;
    float* wout = out + OUT_ELEMS;

    rope_table_kernel<<<(SEQ*32 + 255)/256, 256>>>();

    split_all<<<32768, 256>>>(q, k, v, Wq, Wk, Wv, Wo);

    cudaFuncSetAttribute(gemm_qkv,
                         cudaFuncAttributeMaxDynamicSharedMemorySize, 2*GSTG);
    cudaFuncSetAttribute(gemm_out,
                         cudaFuncAttributeMaxDynamicSharedMemorySize, 2*GSTG);
    cudaFuncSetAttribute(attn_mma,
                         cudaFuncAttributeMaxDynamicSharedMemorySize, ASMEM);

    gemm_qkv<<<dim3(HID/128, MTOT/128, 3), 256, 2*GSTG>>>(bq, bk, bv);

    attn_mma<<<dim3(8, NH, BATCH), 256, ASMEM>>>(wout, write_w);

    gemm_out<<<dim3(HID/128, MTOT/128), 256, 2*GSTG>>>(bo, out);
}

// round 13
// speedup vs baseline: 1.9617x; 1.0093x over previous
#include <cuda_runtime.h>
#include <cuda_bf16.h>
#include <cuda_fp16.h>
#include <math.h>
#include <stdint.h>

#define BATCH 2
#define SEQ   2048
#define HID   1024
#define NH    16
#define HD    64
#define MTOT  (BATCH*SEQ)
#define OUT_ELEMS   (MTOT*HID)
#define W_ELEMS     (BATCH*NH*SEQ*SEQ)
#define KS2   2048               /* f16 split-K: [hi(32) | lo(32)] x 1024 */
#define LOG2E 1.44269504088896340736f

/* ---------------- scratch (no allocations allowed) ---------------- */
__device__ float g_cos[SEQ*(HD/2)];
__device__ float g_sin[SEQ*(HD/2)];

__device__ __half g_Qh[BATCH*NH*SEQ*HD];
__device__ __half g_Ql[BATCH*NH*SEQ*HD];
__device__ __half g_Kh[BATCH*NH*SEQ*HD];
__device__ __half g_Vh[BATCH*NH*SEQ*HD];

__device__ __half s_q [MTOT*KS2];
__device__ __half s_k [MTOT*KS2];
__device__ __half s_v [MTOT*1024];        /* V input: flat f16 */
__device__ __half s_at[MTOT*KS2];
__device__ __half s_wq[HID*KS2];
__device__ __half s_wk[HID*KS2];
__device__ __half s_wv[HID*1024];         /* Wv: flat f16 */
__device__ __half s_wo[HID*KS2];

/* ---------------- helpers ---------------- */
__device__ __forceinline__ uint32_t smem_u32(const void* p) {
    uint32_t a;
    asm("{ .reg .u64 t; cvta.to.shared.u64 t, %1; cvt.u32.u64 %0, t; }"
        : "=r"(a) : "l"(p));
    return a;
}
__device__ __forceinline__ void cp16(uint32_t s, const void* g) {
    asm volatile("cp.async.cg.shared.global [%0], [%1], 16;"
                 :: "r"(s), "l"(g));
}
#define CP_COMMIT() asm volatile("cp.async.commit_group;" ::: "memory")
#define CP_WAIT(N)  asm volatile("cp.async.wait_group %0;" :: "n"(N) : "memory")

__device__ __forceinline__ void ldsm4(uint32_t& r0, uint32_t& r1,
                                      uint32_t& r2, uint32_t& r3, uint32_t addr)
{
    asm volatile("ldmatrix.sync.aligned.m8n8.x4.shared.b16 {%0,%1,%2,%3}, [%4];"
                 : "=r"(r0), "=r"(r1), "=r"(r2), "=r"(r3) : "r"(addr));
}
__device__ __forceinline__ void ldsm4t(uint32_t& r0, uint32_t& r1,
                                       uint32_t& r2, uint32_t& r3, uint32_t addr)
{
    asm volatile("ldmatrix.sync.aligned.m8n8.x4.trans.shared.b16 {%0,%1,%2,%3}, [%4];"
                 : "=r"(r0), "=r"(r1), "=r"(r2), "=r"(r3) : "r"(addr));
}
__device__ __forceinline__ void mma_f16(float* d, const uint32_t* a,
                                        uint32_t b0, uint32_t b1)
{
    asm volatile(
        "mma.sync.aligned.m16n8k16.row.col.f32.f16.f16.f32 "
        "{%0,%1,%2,%3}, {%4,%5,%6,%7}, {%8,%9}, {%0,%1,%2,%3};"
        : "+f"(d[0]), "+f"(d[1]), "+f"(d[2]), "+f"(d[3])
        : "r"(a[0]), "r"(a[1]), "r"(a[2]), "r"(a[3]), "r"(b0), "r"(b1));
}
__device__ __forceinline__ float ex2(float x) {
    float y;
    asm("ex2.approx.ftz.f32 %0, %1;" : "=f"(y) : "f"(x));
    return y;
}
__device__ __forceinline__ uint32_t pack_h2(float x, float y) {
    __half2 t = __floats2half2_rn(x, y);
    return *(uint32_t*)&t;
}

/* ------ merged fp32 -> f16 split + RoPE tables, one launch --------
   [0,8192)      q  -> s_q  A-format [hi|lo]
   [8192,16384)  k  -> s_k  A-format
   [16384,24576) v  -> s_v  flat f16
   [24576,26624) Wq -> s_wq B-format [hi|hi]
   [26624,28672) Wk -> s_wk B-format
   [28672,30720) Wo -> s_wo B-format
   [30720,32768) Wv -> s_wv flat f16
   [32768,33024) rope tables                                          */
__global__ void __launch_bounds__(256)
split_all(const float* __restrict__ q, const float* __restrict__ k,
          const float* __restrict__ v, const float* __restrict__ Wq,
          const float* __restrict__ Wk, const float* __restrict__ Wv,
          const float* __restrict__ Wo)
{
    int bid = blockIdx.x;
    int tid = threadIdx.x;

    if (bid >= 32768) {                    /* rope tables */
        int idx = ((bid - 32768) << 8) + tid;
        int s = idx >> 5, j = idx & 31;
        double inv = exp(-((double)(2*j) / (double)HD) * log(10000.0));
        double ang = (double)s * inv;
        g_cos[idx] = (float)cos(ang);
        g_sin[idx] = (float)sin(ang);
        return;
    }

    if (bid < 16384) {                     /* q, k: A-format split */
        int t = bid >> 13;
        const float* src = t ? k : q;
        __half* dst = t ? s_k : s_q;
        int idx2 = ((bid & 8191) << 8) + tid;
        float2 x = ((const float2*)src)[idx2];
        int row = idx2 >> 9, kk = (idx2 & 511) * 2;
        int blk = kk >> 5,  j  = kk & 31;
        __half2 hi = __floats2half2_rn(x.x, x.y);
        size_t base = (size_t)row * KS2 + blk*64 + j;
        *(__half2*)(dst + base) = hi;
        *(__half2*)(dst + base + 32) = __floats2half2_rn(
            x.x - __half2float(hi.x), x.y - __half2float(hi.y));
        return;
    }
    if (bid < 24576) {                     /* v: flat f16 */
        int idx2 = ((bid - 16384) << 8) + tid;
        float2 x = ((const float2*)v)[idx2];
        *(__half2*)(s_v + (size_t)idx2*2) = __floats2half2_rn(x.x, x.y);
        return;
    }
    if (bid < 30720) {                     /* Wq, Wk, Wo: B-format */
        int r = bid - 24576;
        int t = r >> 11;
        const float* src = (t == 0) ? Wq : (t == 1) ? Wk : Wo;
        __half* dst = (t == 0) ? s_wq : (t == 1) ? s_wk : s_wo;
        int idx2 = ((r & 2047) << 8) + tid;
        float2 x = ((const float2*)src)[idx2];
        int row = idx2 >> 9, kk = (idx2 & 511) * 2;
        int blk = kk >> 5,  j  = kk & 31;
        __half2 hi = __floats2half2_rn(x.x, x.y);
        size_t base = (size_t)row * KS2 + blk*64 + j;
        *(__half2*)(dst + base)      = hi;
        *(__half2*)(dst + base + 32) = hi;
        return;
    }
    {                                      /* Wv: flat f16 */
        int idx2 = ((bid - 30720) << 8) + tid;
        float2 x = ((const float2*)Wv)[idx2];
        *(__half2*)(s_wv + (size_t)idx2*2) = __floats2half2_rn(x.x, x.y);
    }
}

/* ================= GEMM mainloop core (f16) ================= */
#define GSTG 36864

template<int KSZ>
__device__ __forceinline__ void gemm_core(
    const __half* __restrict__ A, const __half* __restrict__ B,
    char* gsm, int tid, int warp_m, int warp_n, int l,
    int m0, int n0, float acc[2][8][4])
{
    const uint32_t sb = smem_u32(gsm);
    const uint4* gA = (const uint4*)(A + (size_t)m0 * KSZ);
    const uint4* gB = (const uint4*)(B + (size_t)n0 * KSZ);

    uint32_t a_off[2], b_off[4];
#pragma unroll
    for (int mt = 0; mt < 2; mt++)
        a_off[mt] = (warp_m*32 + mt*16 + (l & 15))*144 + (l >> 4)*16;
#pragma unroll
    for (int nt = 0; nt < 4; nt++) {
        int row = warp_n*64 + nt*16 + (l & 7) + ((l >> 4) & 1) * 8;
        b_off[nt] = 18432 + row*144 + ((l >> 3) & 1)*16;
    }

    auto load_stage = [&](int stg, int it) {
        uint32_t base = sb + stg*GSTG;
#pragma unroll
        for (int u = 0; u < 4; u++) {
            int f = u*256 + tid;
            int r = f >> 3, c = f & 7;
            cp16(base + r*144 + c*16,         gA + (size_t)r*(KSZ/8) + it*8 + c);
            cp16(base + 18432 + r*144 + c*16, gB + (size_t)r*(KSZ/8) + it*8 + c);
        }
    };

    load_stage(0, 0);
    CP_COMMIT();

    for (int it = 0; it < KSZ/64; it++) {
        int cur = it & 1;
        if (it + 1 < KSZ/64) {
            load_stage(cur ^ 1, it + 1);
            CP_COMMIT();
            CP_WAIT(1);
        } else {
            CP_WAIT(0);
        }
        __syncthreads();

        uint32_t stgb = sb + cur*GSTG;
#pragma unroll
        for (int ks = 0; ks < 4; ks++) {
            uint32_t a[2][4], b[4][4];
#pragma unroll
            for (int mt = 0; mt < 2; mt++)
                ldsm4(a[mt][0], a[mt][1], a[mt][2], a[mt][3],
                      stgb + a_off[mt] + ks*32);
#pragma unroll
            for (int nt = 0; nt < 4; nt++)
                ldsm4(b[nt][0], b[nt][1], b[nt][2], b[nt][3],
                      stgb + b_off[nt] + ks*32);
#pragma unroll
            for (int mt = 0; mt < 2; mt++)
#pragma unroll
                for (int nt = 0; nt < 4; nt++) {
                    mma_f16(acc[mt][nt*2],   a[mt], b[nt][0], b[nt][1]);
                    mma_f16(acc[mt][nt*2+1], a[mt], b[nt][2], b[nt][3]);
                }
        }
        __syncthreads();
    }
}

/* ---- merged QKV projection GEMM: z = 0 (Q), 1 (K), 2 (V) ---- */
__global__ void __launch_bounds__(256, 2)
gemm_qkv(const float* __restrict__ bq, const float* __restrict__ bk,
         const float* __restrict__ bv)
{
    extern __shared__ __align__(16) char gsm[];

    const int tid = threadIdx.x;
    const int wid = tid >> 5, l = tid & 31;
    const int warp_m = wid >> 1, warp_n = wid & 1;
    const int m0 = blockIdx.y * 128;
    const int n0 = blockIdx.x * 128;
    const int z = blockIdx.z;

    const float* bias = (z == 0) ? bq : (z == 1) ? bk : bv;

    float acc[2][8][4];
#pragma unroll
    for (int i = 0; i < 2; i++)
#pragma unroll
        for (int j = 0; j < 8; j++)
#pragma unroll
            for (int p = 0; p < 4; p++) acc[i][j][p] = 0.f;

    if (z == 2)
        gemm_core<1024>(s_v, s_wv, gsm, tid, warp_m, warp_n, l, m0, n0, acc);
    else
        gemm_core<2048>((z == 0) ? s_q : s_k, (z == 0) ? s_wq : s_wk,
                        gsm, tid, warp_m, warp_n, l, m0, n0, acc);

    const int g = l >> 2, q = l & 3;
#pragma unroll
    for (int mt = 0; mt < 2; mt++) {
        int mrow0 = m0 + warp_m*32 + mt*16 + g;
#pragma unroll
        for (int nt2 = 0; nt2 < 8; nt2++) {
            int ncol = n0 + warp_n*64 + nt2*8 + q*2;
            float b0 = bias[ncol], b1 = bias[ncol+1];
            float c0 = acc[mt][nt2][0] + b0;
            float c1 = acc[mt][nt2][1] + b1;
            float c2 = acc[mt][nt2][2] + b0;
            float c3 = acc[mt][nt2][3] + b1;

            int h = ncol >> 6, d = ncol & 63;
            int bb0 = mrow0 >> 11, ss0 = mrow0 & 2047;
            int mrow1 = mrow0 + 8;
            int bb1 = mrow1 >> 11, ss1 = mrow1 & 2047;
            if (z < 2) {
                float cs0 = g_cos[ss0*32 + (d>>1)], sn0 = g_sin[ss0*32 + (d>>1)];
                float cs1 = g_cos[ss1*32 + (d>>1)], sn1 = g_sin[ss1*32 + (d>>1)];
                float t0 = c0*cs0 - c1*sn0, t1 = c0*sn0 + c1*cs0;
                float t2 = c2*cs1 - c3*sn1, t3 = c2*sn1 + c3*cs1;
                c0 = t0; c1 = t1; c2 = t2; c3 = t3;
            }
            size_t a0 = (((size_t)(bb0*NH + h)*SEQ + ss0) << 6) + d;
            size_t a1 = (((size_t)(bb1*NH + h)*SEQ + ss1) << 6) + d;
            __half h0 = __float2half_rn(c0);
            __half h1 = __float2half_rn(c1);
            __half h2 = __float2half_rn(c2);
            __half h3 = __float2half_rn(c3);
            if (z == 0) {
                *(__half2*)(g_Qh + a0) = __halves2half2(h0, h1);
                *(__half2*)(g_Qh + a1) = __halves2half2(h2, h3);
                *(__half2*)(g_Ql + a0) = __floats2half2_rn(
                    c0 - __half2float(h0), c1 - __half2float(h1));
                *(__half2*)(g_Ql + a1) = __floats2half2_rn(
                    c2 - __half2float(h2), c3 - __half2float(h3));
            } else if (z == 1) {
                *(__half2*)(g_Kh + a0) = __halves2half2(h0, h1);
                *(__half2*)(g_Kh + a1) = __halves2half2(h2, h3);
            } else {
                *(__half2*)(g_Vh + a0) = __halves2half2(h0, h1);
                *(__half2*)(g_Vh + a1) = __halves2half2(h2, h3);
            }
        }
    }
}

/* ---- output projection GEMM + zero-fill of masked weight region ---- */
__global__ void __launch_bounds__(256, 2)
gemm_out(const float* __restrict__ bo, float* __restrict__ dst,
         float* __restrict__ wout, int write_w)
{
    extern __shared__ __align__(16) char gsm[];

    const int tid = threadIdx.x;
    const int wid = tid >> 5, l = tid & 31;
    const int warp_m = wid >> 1, warp_n = wid & 1;
    const int m0 = blockIdx.y * 128;
    const int n0 = blockIdx.x * 128;

    /* zero-fill prologue: CTA c handles (bh,qt) pairs c and 511-c.
       work per pair = (15-qt1)+(15-qt2) = 15, perfectly balanced.     */
    if (write_w) {
        int c = blockIdx.y * 8 + blockIdx.x;     /* 0..255 */
        float4 z4 = make_float4(0.f, 0.f, 0.f, 0.f);
#pragma unroll
        for (int u = 0; u < 2; u++) {
            int p = u ? (511 - c) : c;
            int bh = p >> 4, qt = p & 15;
            int nfl = 128 * (15 - qt);           /* masked floats per row */
            if (nfl > 0) {
                int q0 = qt * 128;
                float* basep = wout + ((size_t)bh*SEQ + q0)*SEQ + q0 + 128;
                for (int r = tid >> 5; r < 128; r += 8) {
                    float* rowp = basep + (size_t)r * SEQ;
                    for (int cc = (tid & 31)*4; cc < nfl; cc += 128)
                        __stcs((float4*)(rowp + cc), z4);
                }
            }
        }
    }

    float acc[2][8][4];
#pragma unroll
    for (int i = 0; i < 2; i++)
#pragma unroll
        for (int j = 0; j < 8; j++)
#pragma unroll
            for (int p = 0; p < 4; p++) acc[i][j][p] = 0.f;

    gemm_core<2048>(s_at, s_wo, gsm, tid, warp_m, warp_n, l, m0, n0, acc);

    const int g = l >> 2, q = l & 3;
#pragma unroll
    for (int mt = 0; mt < 2; mt++) {
        int mrow0 = m0 + warp_m*32 + mt*16 + g;
#pragma unroll
        for (int nt2 = 0; nt2 < 8; nt2++) {
            int ncol = n0 + warp_n*64 + nt2*8 + q*2;
            float b0 = bo[ncol], b1 = bo[ncol+1];
            *(float2*)(dst + (size_t)mrow0    *HID + ncol) =
                make_float2(acc[mt][nt2][0] + b0, acc[mt][nt2][1] + b1);
            *(float2*)(dst + (size_t)(mrow0+8)*HID + ncol) =
                make_float2(acc[mt][nt2][2] + b0, acc[mt][nt2][3] + b1);
        }
    }
}

/* ================= two-pass attention, causal-paired, f16 ========= */
#define QSZ   36864
#define ASTG  18432
#define ASMEM (QSZ + 3*ASTG)

__global__ void __launch_bounds__(256, 2)
attn_mma(float* __restrict__ wout, int write_w)
{
    extern __shared__ __align__(16) char dsm[];
    const int tid = threadIdx.x;
    const int w = tid >> 5, l = tid & 31;
    const int g = l >> 2, q = l & 3;
    const int h = blockIdx.y, b = blockIdx.z;
    const size_t basebh = (size_t)(b*NH + h) * SEQ;
    const uint32_t sb = smem_u32(dsm);
    const float CE = 0.125f * LOG2E;

    uint32_t bk_off[4];
    {
        int krow = (l & 7) + ((l >> 4) & 1) * 8;
        int kcb  = ((l >> 3) & 1) * 16;
#pragma unroll
        for (int nt = 0; nt < 4; nt++)
            bk_off[nt] = (nt*16 + krow)*144 + kcb;
    }
    const uint32_t aQh = sb + (w*16 + (l & 15))*144 + (l >> 4)*16;
    const uint32_t aQl = aQh + 18432;
    const uint32_t av_off = 9216 + (l & 15)*144 + (l >> 4)*16;

    auto loadK = [&](int stg, int kb) {
        uint32_t base = sb + QSZ + stg*ASTG;
        const uint4* gkh = (const uint4*)(g_Kh + (basebh + kb*64) * HD);
#pragma unroll
        for (int u = 0; u < 2; u++) {
            int f = u*256 + tid;
            int r = f >> 3, c = f & 7;
            cp16(base + r*144 + c*16, gkh + r*8 + c);
        }
    };
    auto loadKV = [&](int stg, int kb) {
        uint32_t base = sb + QSZ + stg*ASTG;
        const uint4* gkh = (const uint4*)(g_Kh + (basebh + kb*64) * HD);
        const uint4* gvh = (const uint4*)(g_Vh + (basebh + kb*64) * HD);
#pragma unroll
        for (int u = 0; u < 2; u++) {
            int f = u*256 + tid;
            int r = f >> 3, c = f & 7;
            cp16(base + r*144 + c*16,        gkh + r*8 + c);
            cp16(base + 9216 + r*144 + c*16, gvh + r*8 + c);
        }
    };

    auto qk_tile = [&](uint32_t kbase, float acc[8][4]) {
#pragma unroll
        for (int nt = 0; nt < 8; nt++)
#pragma unroll
            for (int p = 0; p < 4; p++) acc[nt][p] = 0.f;
#pragma unroll
        for (int ks = 0; ks < 4; ks++) {
            uint32_t ah[4], al[4];
            ldsm4(ah[0], ah[1], ah[2], ah[3], aQh + ks*32);
            ldsm4(al[0], al[1], al[2], al[3], aQl + ks*32);
#pragma unroll
            for (int np = 0; np < 4; np++) {
                uint32_t kh[4];
                ldsm4(kh[0], kh[1], kh[2], kh[3], kbase + bk_off[np] + ks*32);
                mma_f16(acc[np*2],   ah, kh[0], kh[1]);
                mma_f16(acc[np*2+1], ah, kh[2], kh[3]);
                mma_f16(acc[np*2],   al, kh[0], kh[1]);
                mma_f16(acc[np*2+1], al, kh[2], kh[3]);
            }
        }
    };

    for (int half = 0; half < 2; half++) {
        const int qt = half ? blockIdx.x : (15 - blockIdx.x);
        const int q0 = qt * 128;
        const int nkt = 2*qt + 2;
        const int rw0 = q0 + w*16;
        const int r0 = rw0 + g, r1 = r0 + 8;

        /* Q loads */
        {
            const uint4* gh = (const uint4*)(g_Qh + (basebh + q0) * HD);
            const uint4* gl = (const uint4*)(g_Ql + (basebh + q0) * HD);
#pragma unroll
            for (int u = 0; u < 4; u++) {
                int f = u*256 + tid;
                int r = f >> 3, c = f & 7;
                cp16(sb + r*144 + c*16,         gh + r*8 + c);
                cp16(sb + 18432 + r*144 + c*16, gl + r*8 + c);
            }
            CP_COMMIT();
        }

        float m2[2] = {-1e30f, -1e30f};
        float l2[2] = {0.f, 0.f};

        /* ---------------- PASS 1: row max & sum ---------------- */
        loadK(0, 0);
        CP_COMMIT();
        if (nkt > 1) { loadK(1, 1); CP_COMMIT(); }

        for (int kb = 0; kb < nkt; kb++) {
            if (kb + 1 < nkt) CP_WAIT(1); else CP_WAIT(0);
            __syncthreads();
            if (kb + 2 < nkt) {
                loadK((kb + 2) % 3, kb + 2);
                CP_COMMIT();
            }

            float acc[8][4];
            qk_tile(sb + QSZ + (kb % 3)*ASTG, acc);

            const bool needmask = (kb*64 + 63) > rw0;
#pragma unroll
            for (int nt = 0; nt < 8; nt++) {
                int k0c = kb*64 + nt*8 + q*2;
                acc[nt][0] = (!needmask || k0c   <= r0) ? acc[nt][0]*CE : -1e30f;
                acc[nt][1] = (!needmask || k0c+1 <= r0) ? acc[nt][1]*CE : -1e30f;
                acc[nt][2] = (!needmask || k0c   <= r1) ? acc[nt][2]*CE : -1e30f;
                acc[nt][3] = (!needmask || k0c+1 <= r1) ? acc[nt][3]*CE : -1e30f;
            }
            float tm0 = -1e30f, tm1 = -1e30f;
#pragma unroll
            for (int nt = 0; nt < 8; nt++) {
                tm0 = fmaxf(tm0, fmaxf(acc[nt][0], acc[nt][1]));
                tm1 = fmaxf(tm1, fmaxf(acc[nt][2], acc[nt][3]));
            }
            tm0 = fmaxf(tm0, __shfl_xor_sync(0xffffffffu, tm0, 1));
            tm0 = fmaxf(tm0, __shfl_xor_sync(0xffffffffu, tm0, 2));
            tm1 = fmaxf(tm1, __shfl_xor_sync(0xffffffffu, tm1, 1));
            tm1 = fmaxf(tm1, __shfl_xor_sync(0xffffffffu, tm1, 2));
            float mn0 = fmaxf(m2[0], tm0), mn1 = fmaxf(m2[1], tm1);
            float s0 = 0.f, s1 = 0.f;
#pragma unroll
            for (int nt = 0; nt < 8; nt++) {
                s0 += ex2(acc[nt][0] - mn0) + ex2(acc[nt][1] - mn0);
                s1 += ex2(acc[nt][2] - mn1) + ex2(acc[nt][3] - mn1);
            }
            s0 += __shfl_xor_sync(0xffffffffu, s0, 1);
            s0 += __shfl_xor_sync(0xffffffffu, s0, 2);
            s1 += __shfl_xor_sync(0xffffffffu, s1, 1);
            s1 += __shfl_xor_sync(0xffffffffu, s1, 2);
            l2[0] = l2[0] * ex2(m2[0] - mn0) + s0;  m2[0] = mn0;
            l2[1] = l2[1] * ex2(m2[1] - mn1) + s1;  m2[1] = mn1;
        }

        const float invl0 = 1.f / l2[0];
        const float invl1 = 1.f / l2[1];

        float o[8][4];
#pragma unroll
        for (int nd = 0; nd < 8; nd++)
#pragma unroll
            for (int p = 0; p < 4; p++) o[nd][p] = 0.f;

        /* ---------------- PASS 2: weights + O ---------------- */
        __syncthreads();
        loadKV(0, 0);
        CP_COMMIT();
        if (nkt > 1) { loadKV(1, 1); CP_COMMIT(); }

        for (int kb = 0; kb < nkt; kb++) {
            if (kb + 1 < nkt) CP_WAIT(1); else CP_WAIT(0);
            __syncthreads();
            if (kb + 2 < nkt) {
                loadKV((kb + 2) % 3, kb + 2);
                CP_COMMIT();
            }

            uint32_t kbase = sb + QSZ + (kb % 3)*ASTG;
            float acc[8][4];
            qk_tile(kbase, acc);

            const bool needmask = (kb*64 + 63) > rw0;
            uint32_t ew0[8], ew1[8];
#pragma unroll
            for (int nt = 0; nt < 8; nt++) {
                int k0c = kb*64 + nt*8 + q*2;
                float w0 = (!needmask || k0c   <= r0)
                           ? ex2(acc[nt][0]*CE - m2[0]) * invl0 : 0.f;
                float w1 = (!needmask || k0c+1 <= r0)
                           ? ex2(acc[nt][1]*CE - m2[0]) * invl0 : 0.f;
                float w2 = (!needmask || k0c   <= r1)
                           ? ex2(acc[nt][2]*CE - m2[1]) * invl1 : 0.f;
                float w3 = (!needmask || k0c+1 <= r1)
                           ? ex2(acc[nt][3]*CE - m2[1]) * invl1 : 0.f;
                ew0[nt] = pack_h2(w0, w1);
                ew1[nt] = pack_h2(w2, w3);
                if (write_w) {
                    __stcs((float2*)(wout + (basebh + r0)*SEQ + k0c),
                           make_float2(w0, w1));
                    __stcs((float2*)(wout + (basebh + r1)*SEQ + k0c),
                           make_float2(w2, w3));
                }
            }

            /* PV: w exact-f16 x vh */
#pragma unroll
            for (int t = 0; t < 4; t++) {
                uint32_t aw[4] = {ew0[2*t], ew1[2*t], ew0[2*t+1], ew1[2*t+1]};
#pragma unroll
                for (int nd = 0; nd < 4; nd++) {
                    uint32_t vh[4];
                    ldsm4t(vh[0], vh[1], vh[2], vh[3],
                           kbase + av_off + t*2304 + nd*32);
                    mma_f16(o[nd*2],   aw, vh[0], vh[1]);
                    mma_f16(o[nd*2+1], aw, vh[2], vh[3]);
                }
            }
        }

        /* write O in f16 split-A format for the out-projection */
        {
            size_t mg0 = (size_t)b*SEQ + q0 + w*16 + g;
            size_t mg1 = mg0 + 8;
#pragma unroll
            for (int nd = 0; nd < 8; nd++) {
                int col = h*64 + nd*8 + q*2;
                int blk = col >> 5, j = col & 31;
                size_t b0 = mg0*KS2 + blk*64 + j;
                size_t b1 = mg1*KS2 + blk*64 + j;
                float c0 = o[nd][0], c1 = o[nd][1];
                float c2 = o[nd][2], c3 = o[nd][3];
                __half h0 = __float2half_rn(c0);
                __half h1 = __float2half_rn(c1);
                __half h2 = __float2half_rn(c2);
                __half h3 = __float2half_rn(c3);
                *(__half2*)(s_at + b0)      = __halves2half2(h0, h1);
                *(__half2*)(s_at + b0 + 32) = __floats2half2_rn(
                    c0 - __half2float(h0), c1 - __half2float(h1));
                *(__half2*)(s_at + b1)      = __halves2half2(h2, h3);
                *(__half2*)(s_at + b1 + 32) = __floats2half2_rn(
                    c2 - __half2float(h2), c3 - __half2float(h3));
            }
        }
        __syncthreads();
    }
}

/* ---------------- launcher ---------------- */
extern "C" void kernel_launch(void* const* d_in, const int* in_sizes, int n_in,
                              void* d_out, int out_size)
{
    const float* q  = (const float*)d_in[0];
    const float* k  = (const float*)d_in[1];
    const float* v  = (const float*)d_in[2];
    const float* Wq = (const float*)d_in[3];
    const float* bq = (const float*)d_in[4];
    const float* Wk = (const float*)d_in[5];
    const float* bk = (const float*)d_in[6];
    const float* Wv = (const float*)d_in[7];
    const float* bv = (const float*)d_in[8];
    const float* Wo = (const float*)d_in[9];
    const float* bo = (const float*)d_in[10];

    float* out  = (float*)d_out;
    int write_w = (out_size >= OUT_ELEMS + W_ELEMS) ? 1 : 0;
    float* wout = out + OUT_ELEMS;

    split_all<<<33024, 256>>>(q, k, v, Wq, Wk, Wv, Wo);

    cudaFuncSetAttribute(gemm_qkv,
                         cudaFuncAttributeMaxDynamicSharedMemorySize, 2*GSTG);
    cudaFuncSetAttribute(gemm_out,
                         cudaFuncAttributeMaxDynamicSharedMemorySize, 2*GSTG);
    cudaFuncSetAttribute(attn_mma,
                         cudaFuncAttributeMaxDynamicSharedMemorySize, ASMEM);

    gemm_qkv<<<dim3(HID/128, MTOT/128, 3), 256, 2*GSTG>>>(bq, bk, bv);

    attn_mma<<<dim3(8, NH, BATCH), 256, ASMEM>>>(wout, write_w);

    gemm_out<<<dim3(HID/128, MTOT/128), 256, 2*GSTG>>>(bo, out, wout, write_w);
}